// round 6
// baseline (speedup 1.0000x reference)
#include <cuda_runtime.h>
#include <cuda_bf16.h>
#include <math.h>

#define N_NODES 50000
#define N_EDGES 400000
#define SLOPE   0.2f

#define ETILE   64
#define NTILES  (N_EDGES / ETILE)   // 6250, exact
#define NSCANB  196                 // ceil(50000/256)
#define MAXNT   1566                // max node tiles (ceil(N/32)+3)

// ---------------- scratch ----------------
__device__ __align__(16) float g_P[(size_t)N_NODES * 128];
__device__ __align__(16) float g_star[N_NODES * 8];
__device__ __align__(16) float g_ssrc[N_NODES * 8];
__device__ __align__(16) float g_attrpart[(size_t)N_EDGES * 128];
__device__ __align__(16) float g_ex[N_EDGES * 8];
__device__ __align__(16) float g_denom[N_NODES * 8];
__device__ int g_src[N_EDGES], g_tar[N_EDGES];
__device__ int g_deg[N_NODES], g_off[N_NODES + 1], g_cursor[N_NODES], g_perm[N_EDGES];
__device__ int g_ntype[N_NODES];
__device__ int g_bpart[NSCANB], g_bpre[NSCANB];
__device__ int g_tcount[3], g_tcursor3[3], g_toff3[3], g_tilestart[4];
__device__ int g_perm3[N_NODES + 96];

// prepped split-bf16 transposed weights  [n][k]
__device__ __align__(16) __nv_bfloat16 gWeaHiT[128 * 64],  gWeaLoT[128 * 64];
__device__ __align__(16) __nv_bfloat16 gWetHiT[128 * 64],  gWetLoT[128 * 64];
__device__ __align__(16) __nv_bfloat16 gWupHiT[128 * 128], gWupLoT[128 * 128];
__device__ __align__(16) __nv_bfloat16 gWaHiT[8 * 256],    gWaLoT[8 * 256];
__device__ __align__(16) __nv_bfloat16 gWnHiT[3 * 128 * 256], gWnLoT[3 * 128 * 256];
__device__ __align__(16) __nv_bfloat16 gWuTopHiT[128 * 128],  gWuTopLoT[128 * 128];
__device__ __align__(16) __nv_bfloat16 gWsHiT[16 * 128],      gWsLoT[16 * 128];

__device__ __forceinline__ float lrelu(float x) { return x >= 0.f ? x : SLOPE * x; }

__device__ __forceinline__ void splitpack(float x, float y, unsigned& hi, unsigned& lo) {
    __nv_bfloat16 hx = __float2bfloat16(x);
    __nv_bfloat16 hy = __float2bfloat16(y);
    float lx = x - __bfloat162float(hx);
    float ly = y - __bfloat162float(hy);
    __nv_bfloat162 h2 = __halves2bfloat162(hx, hy);
    __nv_bfloat162 l2 = __halves2bfloat162(__float2bfloat16(lx), __float2bfloat16(ly));
    hi = *reinterpret_cast<unsigned*>(&h2);
    lo = *reinterpret_cast<unsigned*>(&l2);
}

__device__ __forceinline__ void mma16816(float* c, unsigned a0, unsigned a1, unsigned a2,
                                         unsigned a3, unsigned b0, unsigned b1) {
    asm volatile(
        "mma.sync.aligned.m16n8k16.row.col.f32.bf16.bf16.f32 "
        "{%0,%1,%2,%3}, {%4,%5,%6,%7}, {%8,%9}, {%0,%1,%2,%3};"
        : "+f"(c[0]), "+f"(c[1]), "+f"(c[2]), "+f"(c[3])
        : "r"(a0), "r"(a1), "r"(a2), "r"(a3), "r"(b0), "r"(b1));
}

__device__ __forceinline__ void splitw(float x, __nv_bfloat16* hi, __nv_bfloat16* lo, int idx) {
    __nv_bfloat16 h = __float2bfloat16(x);
    hi[idx] = h;
    lo[idx] = __float2bfloat16(x - __bfloat162float(h));
}

// ---------------- weight prep: split + transpose ----------------
__global__ void k_wprep(const float* __restrict__ Wea, const float* __restrict__ Wet,
                        const float* __restrict__ Wupd, const float* __restrict__ Wattn,
                        const float* __restrict__ Wn) {
    int i = blockIdx.x * blockDim.x + threadIdx.x;
    if (i < 8192) {                                   // [n=128][k=64]
        int n = i >> 6, k = i & 63;
        splitw(Wea[k * 128 + n], gWeaHiT, gWeaLoT, i);
        splitw(Wet[k * 128 + n], gWetHiT, gWetLoT, i);
    }
    if (i < 16384) {                                  // W_upd rows 128..255 -> [n=128][k=128]
        int n = i >> 7, k = i & 127;
        splitw(Wupd[(128 + k) * 128 + n], gWupHiT, gWupLoT, i);
        // W_upd rows 0..127 -> [n=128][k=128]
        splitw(Wupd[k * 128 + n], gWuTopHiT, gWuTopLoT, i);
    }
    if (i < 2048) {                                   // W_attn rows 128..383 -> [h=8][k=256]
        int hh = i >> 8, k = i & 255;
        splitw(Wattn[(128 + k) * 8 + hh], gWaHiT, gWaLoT, i);
        // W_s: [n=16][k=128] : n<8 -> attn rows 0..127 head n; n>=8 -> rows 384..511 head n-8
        int n = i >> 7, k2 = i & 127;
        float v = (n < 8) ? Wattn[k2 * 8 + n] : Wattn[(384 + k2) * 8 + (n - 8)];
        splitw(v, gWsHiT, gWsLoT, i);
    }
    if (i < 98304) {                                  // W_node: [t][n=128][k=256]
        int tp = i >> 15, r = i & 32767;
        int n = r >> 8, k = r & 255;
        splitw(Wn[tp * 32768 + k * 128 + n], gWnHiT, gWnLoT, i);
    }
}

// ---------------- init (indices are INT32) ----------------
__global__ void k_init(const int* __restrict__ eidx, const int* __restrict__ ntl) {
    int i = blockIdx.x * blockDim.x + threadIdx.x;
    if (i < N_EDGES) {
        g_src[i] = eidx[i];
        g_tar[i] = eidx[N_EDGES + i];
    }
    if (i < N_NODES * 8) g_denom[i] = 0.f;
    if (i < N_NODES) { g_deg[i] = 0; g_ntype[i] = ntl[i]; }
    if (i < N_NODES + 96) g_perm3[i] = -1;
    if (i < 3) g_tcount[i] = 0;
}

__global__ void k_hist() {
    int i = blockIdx.x * blockDim.x + threadIdx.x;
    if (i < N_EDGES) atomicAdd(&g_deg[g_src[i]], 1);
    if (i < N_NODES) atomicAdd(&g_tcount[g_ntype[i]], 1);
}

// ---------------- parallel scan (3 phases) ----------------
__global__ void k_scanA() {
    __shared__ int sh[8];
    int b = blockIdx.x, t = threadIdx.x, i = b * 256 + t;
    int v = (i < N_NODES) ? g_deg[i] : 0;
#pragma unroll
    for (int d = 16; d; d >>= 1) v += __shfl_down_sync(~0u, v, d);
    if ((t & 31) == 0) sh[t >> 5] = v;
    __syncthreads();
    if (t < 8) {
        int s = sh[t];
#pragma unroll
        for (int d = 4; d; d >>= 1) s += __shfl_down_sync(0xff, s, d);
        if (t == 0) g_bpart[b] = s;
    }
}

__global__ void k_scanB() {
    int t = threadIdx.x, lane = t & 31, wp = t >> 5;
    int v = (t < NSCANB) ? g_bpart[t] : 0;
    int inc = v;
#pragma unroll
    for (int d = 1; d < 32; d <<= 1) {
        int n = __shfl_up_sync(~0u, inc, d);
        if (lane >= d) inc += n;
    }
    __shared__ int wsum[8];
    if (lane == 31) wsum[wp] = inc;
    __syncthreads();
    if (t == 0) {
        int r = 0;
        for (int q = 0; q < 8; q++) { int x = wsum[q]; wsum[q] = r; r += x; }
    }
    __syncthreads();
    if (t < NSCANB) g_bpre[t] = inc - v + wsum[wp];
    if (t == 0) {
        g_off[N_NODES] = N_EDGES;
        int c0 = g_tcount[0], c1 = g_tcount[1], c2 = g_tcount[2];
        g_toff3[0] = 0;
        g_toff3[1] = (c0 + 31) & ~31;
        g_toff3[2] = g_toff3[1] + ((c1 + 31) & ~31);
        int t0 = (c0 + 31) >> 5, t1 = (c1 + 31) >> 5, t2 = (c2 + 31) >> 5;
        g_tilestart[0] = 0; g_tilestart[1] = t0;
        g_tilestart[2] = t0 + t1; g_tilestart[3] = t0 + t1 + t2;
        g_tcursor3[0] = 0; g_tcursor3[1] = 0; g_tcursor3[2] = 0;
    }
}

__global__ void k_scanC() {
    int b = blockIdx.x, t = threadIdx.x, lane = t & 31, wp = t >> 5;
    int i = b * 256 + t;
    int v = (i < N_NODES) ? g_deg[i] : 0;
    int inc = v;
#pragma unroll
    for (int d = 1; d < 32; d <<= 1) {
        int n = __shfl_up_sync(~0u, inc, d);
        if (lane >= d) inc += n;
    }
    __shared__ int wsum[8];
    if (lane == 31) wsum[wp] = inc;
    __syncthreads();
    if (t == 0) {
        int r = 0;
        for (int q = 0; q < 8; q++) { int x = wsum[q]; wsum[q] = r; r += x; }
    }
    __syncthreads();
    int off = g_bpre[b] + inc - v + wsum[wp];
    if (i < N_NODES) { g_off[i] = off; g_cursor[i] = off; }
}

__global__ void k_scatter() {
    int i = blockIdx.x * blockDim.x + threadIdx.x;
    if (i < N_EDGES) {
        int p = atomicAdd(&g_cursor[g_src[i]], 1);
        g_perm[p] = i;
    }
    if (i < N_NODES) {
        int tp = g_ntype[i];
        int p = atomicAdd(&g_tcursor3[tp], 1);
        g_perm3[g_toff3[tp] + p] = i;
    }
}

// ---------------- bucketed tensor-core node kernel (M=32 tiles) ----------------
// smem u32: Xhi[32*132] Xlo[32*132] Ehi[32*68] Elo[32*68]
#define N2_XHI 0
#define N2_XLO 4224
#define N2_EHI 8448
#define N2_ELO 10624
#define NODE2_SMEM_U32 12800
#define NODE2_SMEM_BYTES (NODE2_SMEM_U32 * 4)

__global__ void __launch_bounds__(256)
k_node2(const float* __restrict__ x) {
    extern __shared__ unsigned su[];
    __shared__ int sNid[32];
    unsigned* Xhi = su + N2_XHI;
    unsigned* Xlo = su + N2_XLO;
    unsigned* Ehi = su + N2_EHI;
    unsigned* Elo = su + N2_ELO;

    int t = threadIdx.x, lane = t & 31, w = t >> 5;
    int tl = blockIdx.x;
    if (tl >= g_tilestart[3]) return;
    int tp = (tl >= g_tilestart[2]) ? 2 : (tl >= g_tilestart[1]) ? 1 : 0;
    int row0 = g_toff3[tp] + (tl - g_tilestart[tp]) * 32;

    if (t < 32) sNid[t] = g_perm3[row0 + t];
    __syncthreads();

    // stage X: 32 rows x 256 floats -> bf16 hi/lo
    {
        int row = t >> 3, seg = t & 7;
        int nid = sNid[row];
        const float4* src = (const float4*)(x + (size_t)(nid < 0 ? 0 : nid) * 256 + seg * 32);
        unsigned* xh = Xhi + row * 132 + seg * 16;
        unsigned* xl = Xlo + row * 132 + seg * 16;
#pragma unroll
        for (int p = 0; p < 8; p++) {
            float4 v = (nid >= 0) ? src[p] : make_float4(0.f, 0.f, 0.f, 0.f);
            unsigned h0, l0, h1, l1;
            splitpack(v.x, v.y, h0, l0);
            splitpack(v.z, v.w, h1, l1);
            xh[p * 2] = h0; xh[p * 2 + 1] = h1;
            xl[p * 2] = l0; xl[p * 2 + 1] = l1;
        }
    }
    __syncthreads();

    int rt = w >> 2, nh = w & 3;
    int rb = rt * 16;
    int fr = lane >> 2, fc = lane & 3;

    const unsigned* WnH = (const unsigned*)gWnHiT + tp * 16384;
    const unsigned* WnL = (const unsigned*)gWnLoT + tp * 16384;

    float acc[4][4];
#pragma unroll
    for (int j = 0; j < 4; j++)
#pragma unroll
        for (int c = 0; c < 4; c++) acc[j][c] = 0.f;

    // emb = X @ Wn[type]   (K=256 -> 16 ksteps; each warp 16 rows x 32 cols)
#pragma unroll
    for (int kk = 0; kk < 16; kk++) {
        int o0 = (rb + fr) * 132 + kk * 8 + fc;
        int o1 = o0 + 8 * 132;
        unsigned ah0 = Xhi[o0], ah1 = Xhi[o1], ah2 = Xhi[o0 + 4], ah3 = Xhi[o1 + 4];
        unsigned al0 = Xlo[o0], al1 = Xlo[o1], al2 = Xlo[o0 + 4], al3 = Xlo[o1 + 4];
#pragma unroll
        for (int j = 0; j < 4; j++) {
            int n = nh * 32 + j * 8 + fr;
            const unsigned* wh = WnH + n * 128 + kk * 8 + fc;
            const unsigned* wl = WnL + n * 128 + kk * 8 + fc;
            unsigned bh0 = wh[0], bh1 = wh[4];
            unsigned bl0 = wl[0], bl1 = wl[4];
            mma16816(acc[j], ah0, ah1, ah2, ah3, bh0, bh1);
            mma16816(acc[j], ah0, ah1, ah2, ah3, bl0, bl1);
            mma16816(acc[j], al0, al1, al2, al3, bh0, bh1);
        }
    }
    // epilogue: emb -> smem hi/lo (stride 68)
#pragma unroll
    for (int j = 0; j < 4; j++) {
        int colu = nh * 16 + j * 4 + fc;
        unsigned h, l;
        splitpack(acc[j][0], acc[j][1], h, l);
        Ehi[(rb + fr) * 68 + colu] = h;
        Elo[(rb + fr) * 68 + colu] = l;
        splitpack(acc[j][2], acc[j][3], h, l);
        Ehi[(rb + fr + 8) * 68 + colu] = h;
        Elo[(rb + fr + 8) * 68 + colu] = l;
    }
    __syncthreads();

    // P = emb @ W_upd[0:128]   (K=128 -> 8 ksteps)
#pragma unroll
    for (int j = 0; j < 4; j++)
#pragma unroll
        for (int c = 0; c < 4; c++) acc[j][c] = 0.f;
    const unsigned* WuH = (const unsigned*)gWuTopHiT;
    const unsigned* WuL = (const unsigned*)gWuTopLoT;
#pragma unroll
    for (int kk = 0; kk < 8; kk++) {
        int o0 = (rb + fr) * 68 + kk * 8 + fc;
        int o1 = o0 + 8 * 68;
        unsigned ah0 = Ehi[o0], ah1 = Ehi[o1], ah2 = Ehi[o0 + 4], ah3 = Ehi[o1 + 4];
        unsigned al0 = Elo[o0], al1 = Elo[o1], al2 = Elo[o0 + 4], al3 = Elo[o1 + 4];
#pragma unroll
        for (int j = 0; j < 4; j++) {
            int n = nh * 32 + j * 8 + fr;
            const unsigned* wh = WuH + n * 64 + kk * 8 + fc;
            const unsigned* wl = WuL + n * 64 + kk * 8 + fc;
            unsigned bh0 = wh[0], bh1 = wh[4];
            unsigned bl0 = wl[0], bl1 = wl[4];
            mma16816(acc[j], ah0, ah1, ah2, ah3, bh0, bh1);
            mma16816(acc[j], ah0, ah1, ah2, ah3, bl0, bl1);
            mma16816(acc[j], al0, al1, al2, al3, bh0, bh1);
        }
    }
    {
        int n1 = sNid[rb + fr], n2 = sNid[rb + fr + 8];
#pragma unroll
        for (int j = 0; j < 4; j++) {
            int c0 = nh * 32 + j * 8 + fc * 2;
            if (n1 >= 0)
                *(float2*)(g_P + (size_t)n1 * 128 + c0) = make_float2(acc[j][0], acc[j][1]);
            if (n2 >= 0)
                *(float2*)(g_P + (size_t)n2 * 128 + c0) = make_float2(acc[j][2], acc[j][3]);
        }
    }

    // s_tar/s_src = emb @ Ws  (N=16: cols 0..7 star, 8..15 ssrc) on warps nh==0
    if (nh == 0) {
        float sa[2][4];
#pragma unroll
        for (int j = 0; j < 2; j++)
#pragma unroll
            for (int c = 0; c < 4; c++) sa[j][c] = 0.f;
        const unsigned* WsH = (const unsigned*)gWsHiT;
        const unsigned* WsL = (const unsigned*)gWsLoT;
#pragma unroll
        for (int kk = 0; kk < 8; kk++) {
            int o0 = (rb + fr) * 68 + kk * 8 + fc;
            int o1 = o0 + 8 * 68;
            unsigned ah0 = Ehi[o0], ah1 = Ehi[o1], ah2 = Ehi[o0 + 4], ah3 = Ehi[o1 + 4];
            unsigned al0 = Elo[o0], al1 = Elo[o1], al2 = Elo[o0 + 4], al3 = Elo[o1 + 4];
#pragma unroll
            for (int j = 0; j < 2; j++) {
                int n = j * 8 + fr;
                const unsigned* wh = WsH + n * 64 + kk * 8 + fc;
                const unsigned* wl = WsL + n * 64 + kk * 8 + fc;
                unsigned bh0 = wh[0], bh1 = wh[4];
                unsigned bl0 = wl[0], bl1 = wl[4];
                mma16816(sa[j], ah0, ah1, ah2, ah3, bh0, bh1);
                mma16816(sa[j], ah0, ah1, ah2, ah3, bl0, bl1);
                mma16816(sa[j], al0, al1, al2, al3, bh0, bh1);
            }
        }
        int n1 = sNid[rb + fr], n2 = sNid[rb + fr + 8];
        int h0 = fc * 2;
        if (n1 >= 0) {
            g_star[n1 * 8 + h0] = sa[0][0];  g_star[n1 * 8 + h0 + 1] = sa[0][1];
            g_ssrc[n1 * 8 + h0] = sa[1][0];  g_ssrc[n1 * 8 + h0 + 1] = sa[1][1];
        }
        if (n2 >= 0) {
            g_star[n2 * 8 + h0] = sa[0][2];  g_star[n2 * 8 + h0 + 1] = sa[0][3];
            g_ssrc[n2 * 8 + h0] = sa[1][2];  g_ssrc[n2 * 8 + h0 + 1] = sa[1][3];
        }
    }
}

// ---------------- tensor-core edge kernel (round-5, unchanged) ----------------
#define XHI 0
#define XLO 2304
#define AHI 4608
#define ALO 8960
#define THI 13312
#define TLO 17664
#define EDGE_SMEM_U32 22016
#define EDGE_SMEM_BYTES (EDGE_SMEM_U32 * 4)

template <int KSTEPS, int STRIDE>
__device__ __forceinline__ void gemm_frag(const unsigned* xh, const unsigned* xl,
                                          const unsigned* WhT, const unsigned* WlT,
                                          int wk, int rb, int nh, int lane,
                                          float acc[8][4]) {
    int fr = lane >> 2, fc = lane & 3;
#pragma unroll
    for (int kk = 0; kk < KSTEPS; kk++) {
        int o0 = (rb + fr) * STRIDE + kk * 8 + fc;
        int o1 = (rb + fr + 8) * STRIDE + kk * 8 + fc;
        unsigned ah0 = xh[o0], ah1 = xh[o1], ah2 = xh[o0 + 4], ah3 = xh[o1 + 4];
        unsigned al0 = xl[o0], al1 = xl[o1], al2 = xl[o0 + 4], al3 = xl[o1 + 4];
#pragma unroll
        for (int j = 0; j < 8; j++) {
            int n = nh * 64 + j * 8 + fr;
            const unsigned* wh = WhT + n * wk + kk * 8 + fc;
            const unsigned* wl = WlT + n * wk + kk * 8 + fc;
            unsigned bh0 = wh[0], bh1 = wh[4];
            unsigned bl0 = wl[0], bl1 = wl[4];
            mma16816(acc[j], ah0, ah1, ah2, ah3, bh0, bh1);
            mma16816(acc[j], ah0, ah1, ah2, ah3, bl0, bl1);
            mma16816(acc[j], al0, al1, al2, al3, bh0, bh1);
        }
    }
}

__global__ void __launch_bounds__(256)
k_edge(const float* __restrict__ eattr, const float* __restrict__ etype) {
    extern __shared__ unsigned su[];
    __shared__ int sSrc[ETILE], sTar[ETILE];

    int t = threadIdx.x, lane = t & 31, w = t >> 5;
    int rt = w >> 1, nh = w & 1;
    int rb = rt * 16;
    int fr = lane >> 2, fc = lane & 3;
    int e0 = blockIdx.x * ETILE;

    const unsigned* WeaH = (const unsigned*)gWeaHiT;
    const unsigned* WeaL = (const unsigned*)gWeaLoT;
    const unsigned* WetH = (const unsigned*)gWetHiT;
    const unsigned* WetL = (const unsigned*)gWetLoT;
    const unsigned* WupH = (const unsigned*)gWupHiT;
    const unsigned* WupL = (const unsigned*)gWupLoT;
    const unsigned* WaH  = (const unsigned*)gWaHiT;
    const unsigned* WaL  = (const unsigned*)gWaLoT;

    {
        int row = t >> 2, cg = (t & 3) * 16;
        const float4* src = (const float4*)(eattr + (size_t)(e0 + row) * 64 + cg);
        unsigned* xh = su + XHI + row * 36 + cg / 2;
        unsigned* xl = su + XLO + row * 36 + cg / 2;
#pragma unroll
        for (int p = 0; p < 4; p++) {
            float4 v = src[p];
            unsigned h0, l0, h1, l1;
            splitpack(v.x, v.y, h0, l0);
            splitpack(v.z, v.w, h1, l1);
            xh[p * 2] = h0; xh[p * 2 + 1] = h1;
            xl[p * 2] = l0; xl[p * 2 + 1] = l1;
        }
    }
    if (t < ETILE) sSrc[t] = g_src[e0 + t];
    else if (t < 2 * ETILE) sTar[t - ETILE] = g_tar[e0 + t - ETILE];
    __syncthreads();

    float acc[8][4];

#pragma unroll
    for (int j = 0; j < 8; j++)
#pragma unroll
        for (int c = 0; c < 4; c++) acc[j][c] = 0.f;
    gemm_frag<4, 36>(su + XHI, su + XLO, WeaH, WeaL, 32, rb, nh, lane, acc);
#pragma unroll
    for (int j = 0; j < 8; j++) {
        int colu = nh * 32 + j * 4 + fc;
        unsigned h, l;
        splitpack(lrelu(acc[j][0]), lrelu(acc[j][1]), h, l);
        su[AHI + (rb + fr) * 68 + colu] = h;
        su[ALO + (rb + fr) * 68 + colu] = l;
        splitpack(lrelu(acc[j][2]), lrelu(acc[j][3]), h, l);
        su[AHI + (rb + fr + 8) * 68 + colu] = h;
        su[ALO + (rb + fr + 8) * 68 + colu] = l;
    }
    __syncthreads();

    {
        int row = t >> 2, cg = (t & 3) * 16;
        const float4* src = (const float4*)(etype + (size_t)(e0 + row) * 64 + cg);
        unsigned* xh = su + XHI + row * 36 + cg / 2;
        unsigned* xl = su + XLO + row * 36 + cg / 2;
#pragma unroll
        for (int p = 0; p < 4; p++) {
            float4 v = src[p];
            unsigned h0, l0, h1, l1;
            splitpack(v.x, v.y, h0, l0);
            splitpack(v.z, v.w, h1, l1);
            xh[p * 2] = h0; xh[p * 2 + 1] = h1;
            xl[p * 2] = l0; xl[p * 2 + 1] = l1;
        }
    }
    __syncthreads();

#pragma unroll
    for (int j = 0; j < 8; j++)
#pragma unroll
        for (int c = 0; c < 4; c++) acc[j][c] = 0.f;
    gemm_frag<4, 36>(su + XHI, su + XLO, WetH, WetL, 32, rb, nh, lane, acc);
#pragma unroll
    for (int j = 0; j < 8; j++) {
        int colu = nh * 32 + j * 4 + fc;
        unsigned h, l;
        splitpack(lrelu(acc[j][0]), lrelu(acc[j][1]), h, l);
        su[THI + (rb + fr) * 68 + colu] = h;
        su[TLO + (rb + fr) * 68 + colu] = l;
        splitpack(lrelu(acc[j][2]), lrelu(acc[j][3]), h, l);
        su[THI + (rb + fr + 8) * 68 + colu] = h;
        su[TLO + (rb + fr + 8) * 68 + colu] = l;
    }
    __syncthreads();

    if (w < 4) {
        int srb = w * 16;
        float sacc[4] = {0.f, 0.f, 0.f, 0.f};
#pragma unroll
        for (int kk = 0; kk < 8; kk++) {
            int o0 = (srb + fr) * 68 + kk * 8 + fc;
            int o1 = (srb + fr + 8) * 68 + kk * 8 + fc;
            unsigned ah0 = su[AHI + o0], ah1 = su[AHI + o1];
            unsigned ah2 = su[AHI + o0 + 4], ah3 = su[AHI + o1 + 4];
            unsigned al0 = su[ALO + o0], al1 = su[ALO + o1];
            unsigned al2 = su[ALO + o0 + 4], al3 = su[ALO + o1 + 4];
            const unsigned* wh = WaH + fr * 128 + kk * 8 + fc;
            const unsigned* wl = WaL + fr * 128 + kk * 8 + fc;
            unsigned bh0 = wh[0], bh1 = wh[4], bl0 = wl[0], bl1 = wl[4];
            mma16816(sacc, ah0, ah1, ah2, ah3, bh0, bh1);
            mma16816(sacc, ah0, ah1, ah2, ah3, bl0, bl1);
            mma16816(sacc, al0, al1, al2, al3, bh0, bh1);
        }
#pragma unroll
        for (int kk = 0; kk < 8; kk++) {
            int o0 = (srb + fr) * 68 + kk * 8 + fc;
            int o1 = (srb + fr + 8) * 68 + kk * 8 + fc;
            unsigned ah0 = su[THI + o0], ah1 = su[THI + o1];
            unsigned ah2 = su[THI + o0 + 4], ah3 = su[THI + o1 + 4];
            unsigned al0 = su[TLO + o0], al1 = su[TLO + o1];
            unsigned al2 = su[TLO + o0 + 4], al3 = su[TLO + o1 + 4];
            const unsigned* wh = WaH + fr * 128 + 64 + kk * 8 + fc;
            const unsigned* wl = WaL + fr * 128 + 64 + kk * 8 + fc;
            unsigned bh0 = wh[0], bh1 = wh[4], bl0 = wl[0], bl1 = wl[4];
            mma16816(sacc, ah0, ah1, ah2, ah3, bh0, bh1);
            mma16816(sacc, ah0, ah1, ah2, ah3, bl0, bl1);
            mma16816(sacc, al0, al1, al2, al3, bh0, bh1);
        }
        int h0 = fc * 2;
#pragma unroll
        for (int q = 0; q < 4; q++) {
            int row = srb + fr + (q >> 1) * 8;
            int h = h0 + (q & 1);
            int sr = sSrc[row], tg = sTar[row];
            float sc = sacc[q] + g_star[tg * 8 + h] + g_ssrc[sr * 8 + h];
            sc = lrelu(sc);
            float ex = expf(sc);
            g_ex[(e0 + row) * 8 + h] = ex;
            atomicAdd(&g_denom[sr * 8 + h], ex);
        }
    }

#pragma unroll
    for (int j = 0; j < 8; j++)
#pragma unroll
        for (int c = 0; c < 4; c++) acc[j][c] = 0.f;
    gemm_frag<8, 68>(su + AHI, su + ALO, WupH, WupL, 64, rb, nh, lane, acc);
#pragma unroll
    for (int j = 0; j < 8; j++) {
        int n0 = nh * 64 + j * 8 + fc * 2;
        *(float2*)(g_attrpart + (size_t)(e0 + rb + fr) * 128 + n0) =
            make_float2(acc[j][0], acc[j][1]);
        *(float2*)(g_attrpart + (size_t)(e0 + rb + fr + 8) * 128 + n0) =
            make_float2(acc[j][2], acc[j][3]);
    }
}

// ---------------- aggregation ----------------
__global__ void k_aggr(float* __restrict__ out) {
    int n = blockIdx.x;
    int t = threadIdx.x;
    int s = g_off[n], e_end = g_off[n + 1];
    float p = g_P[(size_t)n * 128 + t];
    float acc[8];
#pragma unroll
    for (int h = 0; h < 8; h++) acc[h] = 0.f;
    if (e_end > s) {
        for (int j = s; j < e_end; j++) {
            int e = g_perm[j];
            float m = lrelu(p + g_attrpart[(size_t)e * 128 + t]);
            const float4* xp = (const float4*)(g_ex + e * 8);
            float4 ea = xp[0], eb = xp[1];
            acc[0] += ea.x * m; acc[1] += ea.y * m; acc[2] += ea.z * m; acc[3] += ea.w * m;
            acc[4] += eb.x * m; acc[5] += eb.y * m; acc[6] += eb.z * m; acc[7] += eb.w * m;
        }
        const float4* dp = (const float4*)(g_denom + n * 8);
        float4 da = dp[0], db = dp[1];
        acc[0] /= da.x; acc[1] /= da.y; acc[2] /= da.z; acc[3] /= da.w;
        acc[4] /= db.x; acc[5] /= db.y; acc[6] /= db.z; acc[7] /= db.w;
    }
#pragma unroll
    for (int h = 0; h < 8; h++) out[(size_t)n * 1024 + h * 128 + t] = acc[h];
}

// ---------------- launch ----------------
extern "C" void kernel_launch(void* const* d_in, const int* in_sizes, int n_in,
                              void* d_out, int out_size) {
    const float* node_feats = (const float*)d_in[0];
    const int*   edge_index = (const int*)d_in[1];
    const float* edge_attr  = (const float*)d_in[2];
    const float* edge_type  = (const float*)d_in[3];
    const int*   ntl        = (const int*)d_in[4];
    const float* W_node  = (const float*)d_in[6];
    const float* W_eattr = (const float*)d_in[7];
    const float* W_etype = (const float*)d_in[8];
    const float* W_upd   = (const float*)d_in[9];
    const float* W_attn  = (const float*)d_in[10];
    float* out = (float*)d_out;

    cudaFuncSetAttribute(k_edge, cudaFuncAttributeMaxDynamicSharedMemorySize, EDGE_SMEM_BYTES);
    cudaFuncSetAttribute(k_node2, cudaFuncAttributeMaxDynamicSharedMemorySize, NODE2_SMEM_BYTES);

    const int TB = 256;
    const int GB_E = (N_EDGES + TB - 1) / TB;

    k_wprep<<<384, TB>>>(W_eattr, W_etype, W_upd, W_attn, W_node);
    k_init<<<GB_E, TB>>>(edge_index, ntl);
    k_hist<<<GB_E, TB>>>();
    k_scanA<<<NSCANB, TB>>>();
    k_scanB<<<1, TB>>>();
    k_scanC<<<NSCANB, TB>>>();
    k_scatter<<<GB_E, TB>>>();
    k_node2<<<MAXNT, TB, NODE2_SMEM_BYTES>>>(node_feats);
    k_edge<<<NTILES, TB, EDGE_SMEM_BYTES>>>(edge_attr, edge_type);
    k_aggr<<<N_NODES, 128>>>(out);
}

// round 7
// speedup vs baseline: 1.3559x; 1.3559x over previous
#include <cuda_runtime.h>
#include <cuda_bf16.h>
#include <math.h>

#define N_NODES 50000
#define N_EDGES 400000
#define SLOPE   0.2f

#define ETILE   64
#define NTILES  (N_EDGES / ETILE)   // 6250, exact
#define NSCANB  196                 // ceil(50000/256)

// ---------------- scratch ----------------
__device__ __align__(16) float g_P[(size_t)N_NODES * 128];
__device__ __align__(16) float g_star[N_NODES * 8];
__device__ __align__(16) float g_ssrc[N_NODES * 8];
__device__ __align__(16) float g_attrpart[(size_t)N_EDGES * 128];
__device__ __align__(16) float g_ex[N_EDGES * 8];
__device__ __align__(16) float g_denom[N_NODES * 8];
__device__ int g_src[N_EDGES], g_tar[N_EDGES];
__device__ int g_deg[N_NODES], g_off[N_NODES + 1], g_cursor[N_NODES], g_perm[N_EDGES];
__device__ int g_bpart[NSCANB], g_bpre[NSCANB];

// prepped split-bf16 transposed weights  [n][k]
__device__ __align__(16) __nv_bfloat16 gWeaHiT[128 * 64],  gWeaLoT[128 * 64];
__device__ __align__(16) __nv_bfloat16 gWetHiT[128 * 64],  gWetLoT[128 * 64];
__device__ __align__(16) __nv_bfloat16 gWupHiT[128 * 128], gWupLoT[128 * 128];
__device__ __align__(16) __nv_bfloat16 gWaHiT[8 * 256],    gWaLoT[8 * 256];

__device__ __forceinline__ float lrelu(float x) { return x >= 0.f ? x : SLOPE * x; }

__device__ __forceinline__ void splitpack(float x, float y, unsigned& hi, unsigned& lo) {
    __nv_bfloat16 hx = __float2bfloat16(x);
    __nv_bfloat16 hy = __float2bfloat16(y);
    float lx = x - __bfloat162float(hx);
    float ly = y - __bfloat162float(hy);
    __nv_bfloat162 h2 = __halves2bfloat162(hx, hy);
    __nv_bfloat162 l2 = __halves2bfloat162(__float2bfloat16(lx), __float2bfloat16(ly));
    hi = *reinterpret_cast<unsigned*>(&h2);
    lo = *reinterpret_cast<unsigned*>(&l2);
}

__device__ __forceinline__ void mma16816(float* c, unsigned a0, unsigned a1, unsigned a2,
                                         unsigned a3, unsigned b0, unsigned b1) {
    asm volatile(
        "mma.sync.aligned.m16n8k16.row.col.f32.bf16.bf16.f32 "
        "{%0,%1,%2,%3}, {%4,%5,%6,%7}, {%8,%9}, {%0,%1,%2,%3};"
        : "+f"(c[0]), "+f"(c[1]), "+f"(c[2]), "+f"(c[3])
        : "r"(a0), "r"(a1), "r"(a2), "r"(a3), "r"(b0), "r"(b1));
}

__device__ __forceinline__ void splitw(float x, __nv_bfloat16* hi, __nv_bfloat16* lo, int idx) {
    __nv_bfloat16 h = __float2bfloat16(x);
    hi[idx] = h;
    lo[idx] = __float2bfloat16(x - __bfloat162float(h));
}

// ---------------- weight prep: split + transpose ----------------
__global__ void k_wprep(const float* __restrict__ Wea, const float* __restrict__ Wet,
                        const float* __restrict__ Wupd, const float* __restrict__ Wattn) {
    int i = blockIdx.x * blockDim.x + threadIdx.x;
    if (i < 8192) {                                   // [n=128][k=64]
        int n = i >> 6, k = i & 63;
        splitw(Wea[k * 128 + n], gWeaHiT, gWeaLoT, i);
        splitw(Wet[k * 128 + n], gWetHiT, gWetLoT, i);
    }
    if (i < 16384) {                                  // W_upd rows 128..255 -> [n=128][k=128]
        int n = i >> 7, k = i & 127;
        splitw(Wupd[(128 + k) * 128 + n], gWupHiT, gWupLoT, i);
    }
    if (i < 2048) {                                   // W_attn rows 128..383 -> [h=8][k=256]
        int hh = i >> 8, k = i & 255;
        splitw(Wattn[(128 + k) * 8 + hh], gWaHiT, gWaLoT, i);
    }
}

// ---------------- init (indices are INT32) ----------------
__global__ void k_init(const int* __restrict__ eidx) {
    int i = blockIdx.x * blockDim.x + threadIdx.x;
    if (i < N_EDGES) {
        g_src[i] = eidx[i];
        g_tar[i] = eidx[N_EDGES + i];
    }
    if (i < N_NODES * 8) g_denom[i] = 0.f;
    if (i < N_NODES) g_deg[i] = 0;
}

__global__ void k_hist() {
    int i = blockIdx.x * blockDim.x + threadIdx.x;
    if (i < N_EDGES) atomicAdd(&g_deg[g_src[i]], 1);
}

// ---------------- parallel scan (3 phases) ----------------
__global__ void k_scanA() {
    __shared__ int sh[8];
    int b = blockIdx.x, t = threadIdx.x, i = b * 256 + t;
    int v = (i < N_NODES) ? g_deg[i] : 0;
#pragma unroll
    for (int d = 16; d; d >>= 1) v += __shfl_down_sync(~0u, v, d);
    if ((t & 31) == 0) sh[t >> 5] = v;
    __syncthreads();
    if (t < 8) {
        int s = sh[t];
#pragma unroll
        for (int d = 4; d; d >>= 1) s += __shfl_down_sync(0xff, s, d);
        if (t == 0) g_bpart[b] = s;
    }
}

__global__ void k_scanB() {
    int t = threadIdx.x, lane = t & 31, wp = t >> 5;
    int v = (t < NSCANB) ? g_bpart[t] : 0;
    int inc = v;
#pragma unroll
    for (int d = 1; d < 32; d <<= 1) {
        int n = __shfl_up_sync(~0u, inc, d);
        if (lane >= d) inc += n;
    }
    __shared__ int wsum[8];
    if (lane == 31) wsum[wp] = inc;
    __syncthreads();
    if (t == 0) {
        int r = 0;
        for (int q = 0; q < 8; q++) { int x = wsum[q]; wsum[q] = r; r += x; }
    }
    __syncthreads();
    if (t < NSCANB) g_bpre[t] = inc - v + wsum[wp];
    if (t == 0) g_off[N_NODES] = N_EDGES;
}

__global__ void k_scanC() {
    int b = blockIdx.x, t = threadIdx.x, lane = t & 31, wp = t >> 5;
    int i = b * 256 + t;
    int v = (i < N_NODES) ? g_deg[i] : 0;
    int inc = v;
#pragma unroll
    for (int d = 1; d < 32; d <<= 1) {
        int n = __shfl_up_sync(~0u, inc, d);
        if (lane >= d) inc += n;
    }
    __shared__ int wsum[8];
    if (lane == 31) wsum[wp] = inc;
    __syncthreads();
    if (t == 0) {
        int r = 0;
        for (int q = 0; q < 8; q++) { int x = wsum[q]; wsum[q] = r; r += x; }
    }
    __syncthreads();
    int off = g_bpre[b] + inc - v + wsum[wp];
    if (i < N_NODES) { g_off[i] = off; g_cursor[i] = off; }
}

__global__ void k_scatter() {
    int i = blockIdx.x * blockDim.x + threadIdx.x;
    if (i < N_EDGES) {
        int p = atomicAdd(&g_cursor[g_src[i]], 1);
        g_perm[p] = i;
    }
}

// ---------------- merged node kernel (fp32, round-2/5 proven) ----------------
#define NODE_SMEM_BYTES ((8192 + 4224) * 4)

__global__ void k_node(const float* __restrict__ x, const int* __restrict__ ntl,
                       const float* __restrict__ Wn, const float* __restrict__ Wupd,
                       const float* __restrict__ Wattn) {
    extern __shared__ float smn[];
    float* sx = smn;          // 32 x 256
    float* se = smn + 8192;   // 32 x 132
    int n0 = blockIdx.x * 32;
    int t = threadIdx.x;

    for (int i = t; i < 2048; i += 256) {
        int row = i >> 6, c4 = i & 63;
        int node = n0 + row;
        float4 v = make_float4(0.f, 0.f, 0.f, 0.f);
        if (node < N_NODES) v = ((const float4*)(x + (size_t)node * 256))[c4];
        ((float4*)sx)[row * 64 + c4] = v;
    }
    __syncthreads();

    int tx = t & 31, ty = t >> 5;
    int r0 = ty * 4;

    {   // emb = x @ W_node[type]
        const float* wp[4];
#pragma unroll
        for (int j = 0; j < 4; j++) {
            int node = n0 + r0 + j;
            int tp = (node < N_NODES) ? ntl[node] : 0;
            wp[j] = Wn + (size_t)tp * (256 * 128) + tx * 4;
        }
        float acc[4][4];
#pragma unroll
        for (int j = 0; j < 4; j++)
#pragma unroll
            for (int c = 0; c < 4; c++) acc[j][c] = 0.f;
#pragma unroll 4
        for (int k = 0; k < 256; k++) {
#pragma unroll
            for (int j = 0; j < 4; j++) {
                float4 w = *(const float4*)(wp[j] + (size_t)k * 128);
                float xv = sx[(r0 + j) * 256 + k];
                acc[j][0] += xv * w.x; acc[j][1] += xv * w.y;
                acc[j][2] += xv * w.z; acc[j][3] += xv * w.w;
            }
        }
#pragma unroll
        for (int j = 0; j < 4; j++)
            *(float4*)(se + (r0 + j) * 132 + tx * 4) =
                make_float4(acc[j][0], acc[j][1], acc[j][2], acc[j][3]);
    }
    __syncthreads();

    {   // P = emb @ W_upd[0:128]
        float acc[4][4];
#pragma unroll
        for (int j = 0; j < 4; j++)
#pragma unroll
            for (int c = 0; c < 4; c++) acc[j][c] = 0.f;
#pragma unroll 4
        for (int k = 0; k < 128; k++) {
            float4 w = *(const float4*)(Wupd + (size_t)k * 128 + tx * 4);
#pragma unroll
            for (int j = 0; j < 4; j++) {
                float xv = se[(r0 + j) * 132 + k];
                acc[j][0] += xv * w.x; acc[j][1] += xv * w.y;
                acc[j][2] += xv * w.z; acc[j][3] += xv * w.w;
            }
        }
#pragma unroll
        for (int j = 0; j < 4; j++) {
            int node = n0 + r0 + j;
            if (node < N_NODES)
                *(float4*)(g_P + (size_t)node * 128 + tx * 4) =
                    make_float4(acc[j][0], acc[j][1], acc[j][2], acc[j][3]);
        }
    }

    {   // s_tar / s_src
        int e = t >> 3, h = t & 7;
        int node = n0 + e;
        float at = 0.f, as = 0.f;
        for (int k = 0; k < 128; k++) {
            float v = se[e * 132 + k];
            at += v * Wattn[k * 8 + h];
            as += v * Wattn[(384 + k) * 8 + h];
        }
        if (node < N_NODES) {
            g_star[node * 8 + h] = at;
            g_ssrc[node * 8 + h] = as;
        }
    }
}

// ---------------- tensor-core edge kernel (round-5, unchanged) ----------------
#define XHI 0
#define XLO 2304
#define AHI 4608
#define ALO 8960
#define THI 13312
#define TLO 17664
#define EDGE_SMEM_U32 22016
#define EDGE_SMEM_BYTES (EDGE_SMEM_U32 * 4)

template <int KSTEPS, int STRIDE>
__device__ __forceinline__ void gemm_frag(const unsigned* xh, const unsigned* xl,
                                          const unsigned* WhT, const unsigned* WlT,
                                          int wk, int rb, int nh, int lane,
                                          float acc[8][4]) {
    int fr = lane >> 2, fc = lane & 3;
#pragma unroll
    for (int kk = 0; kk < KSTEPS; kk++) {
        int o0 = (rb + fr) * STRIDE + kk * 8 + fc;
        int o1 = (rb + fr + 8) * STRIDE + kk * 8 + fc;
        unsigned ah0 = xh[o0], ah1 = xh[o1], ah2 = xh[o0 + 4], ah3 = xh[o1 + 4];
        unsigned al0 = xl[o0], al1 = xl[o1], al2 = xl[o0 + 4], al3 = xl[o1 + 4];
#pragma unroll
        for (int j = 0; j < 8; j++) {
            int n = nh * 64 + j * 8 + fr;
            const unsigned* wh = WhT + n * wk + kk * 8 + fc;
            const unsigned* wl = WlT + n * wk + kk * 8 + fc;
            unsigned bh0 = wh[0], bh1 = wh[4];
            unsigned bl0 = wl[0], bl1 = wl[4];
            mma16816(acc[j], ah0, ah1, ah2, ah3, bh0, bh1);
            mma16816(acc[j], ah0, ah1, ah2, ah3, bl0, bl1);
            mma16816(acc[j], al0, al1, al2, al3, bh0, bh1);
        }
    }
}

__global__ void __launch_bounds__(256)
k_edge(const float* __restrict__ eattr, const float* __restrict__ etype) {
    extern __shared__ unsigned su[];
    __shared__ int sSrc[ETILE], sTar[ETILE];

    int t = threadIdx.x, lane = t & 31, w = t >> 5;
    int rt = w >> 1, nh = w & 1;
    int rb = rt * 16;
    int fr = lane >> 2, fc = lane & 3;
    int e0 = blockIdx.x * ETILE;

    const unsigned* WeaH = (const unsigned*)gWeaHiT;
    const unsigned* WeaL = (const unsigned*)gWeaLoT;
    const unsigned* WetH = (const unsigned*)gWetHiT;
    const unsigned* WetL = (const unsigned*)gWetLoT;
    const unsigned* WupH = (const unsigned*)gWupHiT;
    const unsigned* WupL = (const unsigned*)gWupLoT;
    const unsigned* WaH  = (const unsigned*)gWaHiT;
    const unsigned* WaL  = (const unsigned*)gWaLoT;

    {
        int row = t >> 2, cg = (t & 3) * 16;
        const float4* src = (const float4*)(eattr + (size_t)(e0 + row) * 64 + cg);
        unsigned* xh = su + XHI + row * 36 + cg / 2;
        unsigned* xl = su + XLO + row * 36 + cg / 2;
#pragma unroll
        for (int p = 0; p < 4; p++) {
            float4 v = src[p];
            unsigned h0, l0, h1, l1;
            splitpack(v.x, v.y, h0, l0);
            splitpack(v.z, v.w, h1, l1);
            xh[p * 2] = h0; xh[p * 2 + 1] = h1;
            xl[p * 2] = l0; xl[p * 2 + 1] = l1;
        }
    }
    if (t < ETILE) sSrc[t] = g_src[e0 + t];
    else if (t < 2 * ETILE) sTar[t - ETILE] = g_tar[e0 + t - ETILE];
    __syncthreads();

    float acc[8][4];

#pragma unroll
    for (int j = 0; j < 8; j++)
#pragma unroll
        for (int c = 0; c < 4; c++) acc[j][c] = 0.f;
    gemm_frag<4, 36>(su + XHI, su + XLO, WeaH, WeaL, 32, rb, nh, lane, acc);
#pragma unroll
    for (int j = 0; j < 8; j++) {
        int colu = nh * 32 + j * 4 + fc;
        unsigned h, l;
        splitpack(lrelu(acc[j][0]), lrelu(acc[j][1]), h, l);
        su[AHI + (rb + fr) * 68 + colu] = h;
        su[ALO + (rb + fr) * 68 + colu] = l;
        splitpack(lrelu(acc[j][2]), lrelu(acc[j][3]), h, l);
        su[AHI + (rb + fr + 8) * 68 + colu] = h;
        su[ALO + (rb + fr + 8) * 68 + colu] = l;
    }
    __syncthreads();

    {
        int row = t >> 2, cg = (t & 3) * 16;
        const float4* src = (const float4*)(etype + (size_t)(e0 + row) * 64 + cg);
        unsigned* xh = su + XHI + row * 36 + cg / 2;
        unsigned* xl = su + XLO + row * 36 + cg / 2;
#pragma unroll
        for (int p = 0; p < 4; p++) {
            float4 v = src[p];
            unsigned h0, l0, h1, l1;
            splitpack(v.x, v.y, h0, l0);
            splitpack(v.z, v.w, h1, l1);
            xh[p * 2] = h0; xh[p * 2 + 1] = h1;
            xl[p * 2] = l0; xl[p * 2 + 1] = l1;
        }
    }
    __syncthreads();

#pragma unroll
    for (int j = 0; j < 8; j++)
#pragma unroll
        for (int c = 0; c < 4; c++) acc[j][c] = 0.f;
    gemm_frag<4, 36>(su + XHI, su + XLO, WetH, WetL, 32, rb, nh, lane, acc);
#pragma unroll
    for (int j = 0; j < 8; j++) {
        int colu = nh * 32 + j * 4 + fc;
        unsigned h, l;
        splitpack(lrelu(acc[j][0]), lrelu(acc[j][1]), h, l);
        su[THI + (rb + fr) * 68 + colu] = h;
        su[TLO + (rb + fr) * 68 + colu] = l;
        splitpack(lrelu(acc[j][2]), lrelu(acc[j][3]), h, l);
        su[THI + (rb + fr + 8) * 68 + colu] = h;
        su[TLO + (rb + fr + 8) * 68 + colu] = l;
    }
    __syncthreads();

    if (w < 4) {
        int srb = w * 16;
        float sacc[4] = {0.f, 0.f, 0.f, 0.f};
#pragma unroll
        for (int kk = 0; kk < 8; kk++) {
            int o0 = (srb + fr) * 68 + kk * 8 + fc;
            int o1 = (srb + fr + 8) * 68 + kk * 8 + fc;
            unsigned ah0 = su[AHI + o0], ah1 = su[AHI + o1];
            unsigned ah2 = su[AHI + o0 + 4], ah3 = su[AHI + o1 + 4];
            unsigned al0 = su[ALO + o0], al1 = su[ALO + o1];
            unsigned al2 = su[ALO + o0 + 4], al3 = su[ALO + o1 + 4];
            const unsigned* wh = WaH + fr * 128 + kk * 8 + fc;
            const unsigned* wl = WaL + fr * 128 + kk * 8 + fc;
            unsigned bh0 = wh[0], bh1 = wh[4], bl0 = wl[0], bl1 = wl[4];
            mma16816(sacc, ah0, ah1, ah2, ah3, bh0, bh1);
            mma16816(sacc, ah0, ah1, ah2, ah3, bl0, bl1);
            mma16816(sacc, al0, al1, al2, al3, bh0, bh1);
        }
#pragma unroll
        for (int kk = 0; kk < 8; kk++) {
            int o0 = (srb + fr) * 68 + kk * 8 + fc;
            int o1 = (srb + fr + 8) * 68 + kk * 8 + fc;
            unsigned ah0 = su[THI + o0], ah1 = su[THI + o1];
            unsigned ah2 = su[THI + o0 + 4], ah3 = su[THI + o1 + 4];
            unsigned al0 = su[TLO + o0], al1 = su[TLO + o1];
            unsigned al2 = su[TLO + o0 + 4], al3 = su[TLO + o1 + 4];
            const unsigned* wh = WaH + fr * 128 + 64 + kk * 8 + fc;
            const unsigned* wl = WaL + fr * 128 + 64 + kk * 8 + fc;
            unsigned bh0 = wh[0], bh1 = wh[4], bl0 = wl[0], bl1 = wl[4];
            mma16816(sacc, ah0, ah1, ah2, ah3, bh0, bh1);
            mma16816(sacc, ah0, ah1, ah2, ah3, bl0, bl1);
            mma16816(sacc, al0, al1, al2, al3, bh0, bh1);
        }
        int h0 = fc * 2;
#pragma unroll
        for (int q = 0; q < 4; q++) {
            int row = srb + fr + (q >> 1) * 8;
            int h = h0 + (q & 1);
            int sr = sSrc[row], tg = sTar[row];
            float sc = sacc[q] + g_star[tg * 8 + h] + g_ssrc[sr * 8 + h];
            sc = lrelu(sc);
            float ex = expf(sc);
            g_ex[(e0 + row) * 8 + h] = ex;
            atomicAdd(&g_denom[sr * 8 + h], ex);
        }
    }

#pragma unroll
    for (int j = 0; j < 8; j++)
#pragma unroll
        for (int c = 0; c < 4; c++) acc[j][c] = 0.f;
    gemm_frag<8, 68>(su + AHI, su + ALO, WupH, WupL, 64, rb, nh, lane, acc);
#pragma unroll
    for (int j = 0; j < 8; j++) {
        int n0 = nh * 64 + j * 8 + fc * 2;
        *(float2*)(g_attrpart + (size_t)(e0 + rb + fr) * 128 + n0) =
            make_float2(acc[j][0], acc[j][1]);
        *(float2*)(g_attrpart + (size_t)(e0 + rb + fr + 8) * 128 + n0) =
            make_float2(acc[j][2], acc[j][3]);
    }
}

// ---------------- aggregation ----------------
__global__ void k_aggr(float* __restrict__ out) {
    int n = blockIdx.x;
    int t = threadIdx.x;
    int s = g_off[n], e_end = g_off[n + 1];
    float p = g_P[(size_t)n * 128 + t];
    float acc[8];
#pragma unroll
    for (int h = 0; h < 8; h++) acc[h] = 0.f;
    if (e_end > s) {
        for (int j = s; j < e_end; j++) {
            int e = g_perm[j];
            float m = lrelu(p + g_attrpart[(size_t)e * 128 + t]);
            const float4* xp = (const float4*)(g_ex + e * 8);
            float4 ea = xp[0], eb = xp[1];
            acc[0] += ea.x * m; acc[1] += ea.y * m; acc[2] += ea.z * m; acc[3] += ea.w * m;
            acc[4] += eb.x * m; acc[5] += eb.y * m; acc[6] += eb.z * m; acc[7] += eb.w * m;
        }
        const float4* dp = (const float4*)(g_denom + n * 8);
        float4 da = dp[0], db = dp[1];
        acc[0] /= da.x; acc[1] /= da.y; acc[2] /= da.z; acc[3] /= da.w;
        acc[4] /= db.x; acc[5] /= db.y; acc[6] /= db.z; acc[7] /= db.w;
    }
#pragma unroll
    for (int h = 0; h < 8; h++) out[(size_t)n * 1024 + h * 128 + t] = acc[h];
}

// ---------------- launch ----------------
// NOTE: launch order chosen so k_edge is launch #4 (the one ncu profiles).
// hist/scan/scatter only feed k_aggr, so they can run after k_edge.
extern "C" void kernel_launch(void* const* d_in, const int* in_sizes, int n_in,
                              void* d_out, int out_size) {
    const float* node_feats = (const float*)d_in[0];
    const int*   edge_index = (const int*)d_in[1];
    const float* edge_attr  = (const float*)d_in[2];
    const float* edge_type  = (const float*)d_in[3];
    const int*   ntl        = (const int*)d_in[4];
    const float* W_node  = (const float*)d_in[6];
    const float* W_eattr = (const float*)d_in[7];
    const float* W_etype = (const float*)d_in[8];
    const float* W_upd   = (const float*)d_in[9];
    const float* W_attn  = (const float*)d_in[10];
    float* out = (float*)d_out;

    cudaFuncSetAttribute(k_edge, cudaFuncAttributeMaxDynamicSharedMemorySize, EDGE_SMEM_BYTES);
    cudaFuncSetAttribute(k_node, cudaFuncAttributeMaxDynamicSharedMemorySize, NODE_SMEM_BYTES);

    const int TB = 256;
    const int GB_E = (N_EDGES + TB - 1) / TB;

    k_wprep<<<64, TB>>>(W_eattr, W_etype, W_upd, W_attn);                                  // 1
    k_init<<<GB_E, TB>>>(edge_index);                                                       // 2
    k_node<<<(N_NODES + 31) / 32, TB, NODE_SMEM_BYTES>>>(node_feats, ntl, W_node, W_upd, W_attn); // 3
    k_edge<<<NTILES, TB, EDGE_SMEM_BYTES>>>(edge_attr, edge_type);                          // 4 <- profiled
    k_hist<<<GB_E, TB>>>();                                                                 // 5
    k_scanA<<<NSCANB, TB>>>();                                                              // 6
    k_scanB<<<1, TB>>>();                                                                   // 7
    k_scanC<<<NSCANB, TB>>>();                                                              // 8
    k_scatter<<<GB_E, TB>>>();                                                              // 9
    k_aggr<<<N_NODES, 128>>>(out);                                                          // 10
}

// round 8
// speedup vs baseline: 2.0885x; 1.5403x over previous
#include <cuda_runtime.h>
#include <cuda_bf16.h>
#include <math.h>

#define N_NODES 50000
#define N_EDGES 400000
#define SLOPE   0.2f

#define ETILE   64
#define NTILES  (N_EDGES / ETILE)   // 6250, exact
#define NSCANB  196                 // ceil(50000/256)

// ---------------- scratch ----------------
__device__ __align__(16) float g_P[(size_t)N_NODES * 128];
__device__ __align__(16) float g_star[N_NODES * 8];
__device__ __align__(16) float g_ssrc[N_NODES * 8];
__device__ __align__(16) float g_attrpart[(size_t)N_EDGES * 128];
__device__ __align__(16) float g_ex[N_EDGES * 8];
__device__ __align__(16) float g_denom[N_NODES * 8];
__device__ int g_src[N_EDGES], g_tar[N_EDGES];
__device__ int g_deg[N_NODES], g_off[N_NODES + 1], g_cursor[N_NODES], g_perm[N_EDGES];
__device__ int g_bpart[NSCANB], g_bpre[NSCANB];

// mma-ready packed B fragments: uint4 {bh0, bh1, bl0, bl1} per (n, kstep, fc)
__device__ __align__(16) uint4 gBea[128 * 4 * 4];   // Wea:  [n=128][kk=4][fc=4]
__device__ __align__(16) uint4 gBet[128 * 4 * 4];   // Wet
__device__ __align__(16) uint4 gBup[128 * 8 * 4];   // Wupd rows 128:256, [n=128][kk=8][fc=4]
__device__ __align__(16) uint4 gBa [8 * 16 * 4];    // Wattn rows 128:384, [h=8][kk=16][fc=4]

__device__ __forceinline__ float lrelu(float x) { return x >= 0.f ? x : SLOPE * x; }

__device__ __forceinline__ void splitpack(float x, float y, unsigned& hi, unsigned& lo) {
    __nv_bfloat16 hx = __float2bfloat16(x);
    __nv_bfloat16 hy = __float2bfloat16(y);
    float lx = x - __bfloat162float(hx);
    float ly = y - __bfloat162float(hy);
    __nv_bfloat162 h2 = __halves2bfloat162(hx, hy);
    __nv_bfloat162 l2 = __halves2bfloat162(__float2bfloat16(lx), __float2bfloat16(ly));
    hi = *reinterpret_cast<unsigned*>(&h2);
    lo = *reinterpret_cast<unsigned*>(&l2);
}

__device__ __forceinline__ uint4 pack4(float w0, float w1, float w2, float w3) {
    unsigned h0, l0, h1, l1;
    splitpack(w0, w1, h0, l0);
    splitpack(w2, w3, h1, l1);
    return make_uint4(h0, h1, l0, l1);
}

__device__ __forceinline__ void mma16816(float* c, unsigned a0, unsigned a1, unsigned a2,
                                         unsigned a3, unsigned b0, unsigned b1) {
    asm volatile(
        "mma.sync.aligned.m16n8k16.row.col.f32.bf16.bf16.f32 "
        "{%0,%1,%2,%3}, {%4,%5,%6,%7}, {%8,%9}, {%0,%1,%2,%3};"
        : "+f"(c[0]), "+f"(c[1]), "+f"(c[2]), "+f"(c[3])
        : "r"(a0), "r"(a1), "r"(a2), "r"(a3), "r"(b0), "r"(b1));
}

// ---------------- weight prep: pack into mma-ready uint4 fragments ----------------
__global__ void k_wprep(const float* __restrict__ Wea, const float* __restrict__ Wet,
                        const float* __restrict__ Wupd, const float* __restrict__ Wattn) {
    int i = blockIdx.x * blockDim.x + threadIdx.x;
    if (i < 2048) {            // Bea / Bet: n = i>>4, kk = (i>>2)&3, fc = i&3
        int n = i >> 4, kk = (i >> 2) & 3, fc = i & 3;
        int k0 = 2 * (kk * 8 + fc);          // k index of first bf16 pair
        gBea[i] = pack4(Wea[k0 * 128 + n],       Wea[(k0 + 1) * 128 + n],
                        Wea[(k0 + 8) * 128 + n], Wea[(k0 + 9) * 128 + n]);
        gBet[i] = pack4(Wet[k0 * 128 + n],       Wet[(k0 + 1) * 128 + n],
                        Wet[(k0 + 8) * 128 + n], Wet[(k0 + 9) * 128 + n]);
    }
    if (i < 4096) {            // Bup: n = i>>5, kk = (i>>2)&7, fc = i&3 (Wupd rows 128..255)
        int n = i >> 5, kk = (i >> 2) & 7, fc = i & 3;
        int k0 = 2 * (kk * 8 + fc);
        gBup[i] = pack4(Wupd[(128 + k0) * 128 + n],     Wupd[(129 + k0) * 128 + n],
                        Wupd[(136 + k0) * 128 + n],     Wupd[(137 + k0) * 128 + n]);
    }
    if (i < 512) {             // Ba: h = i>>6, kk = (i>>2)&15, fc = i&3 (Wattn rows 128..383)
        int h = i >> 6, kk = (i >> 2) & 15, fc = i & 3;
        int k0 = 2 * (kk * 8 + fc);
        gBa[i] = pack4(Wattn[(128 + k0) * 8 + h],     Wattn[(129 + k0) * 8 + h],
                       Wattn[(136 + k0) * 8 + h],     Wattn[(137 + k0) * 8 + h]);
    }
}

// ---------------- init (indices are INT32) ----------------
__global__ void k_init(const int* __restrict__ eidx) {
    int i = blockIdx.x * blockDim.x + threadIdx.x;
    if (i < N_EDGES) {
        g_src[i] = eidx[i];
        g_tar[i] = eidx[N_EDGES + i];
    }
    if (i < N_NODES * 8) g_denom[i] = 0.f;
    if (i < N_NODES) g_deg[i] = 0;
}

__global__ void k_hist() {
    int i = blockIdx.x * blockDim.x + threadIdx.x;
    if (i < N_EDGES) atomicAdd(&g_deg[g_src[i]], 1);
}

// ---------------- parallel scan (3 phases) ----------------
__global__ void k_scanA() {
    __shared__ int sh[8];
    int b = blockIdx.x, t = threadIdx.x, i = b * 256 + t;
    int v = (i < N_NODES) ? g_deg[i] : 0;
#pragma unroll
    for (int d = 16; d; d >>= 1) v += __shfl_down_sync(~0u, v, d);
    if ((t & 31) == 0) sh[t >> 5] = v;
    __syncthreads();
    if (t < 8) {
        int s = sh[t];
#pragma unroll
        for (int d = 4; d; d >>= 1) s += __shfl_down_sync(0xff, s, d);
        if (t == 0) g_bpart[b] = s;
    }
}

__global__ void k_scanB() {
    int t = threadIdx.x, lane = t & 31, wp = t >> 5;
    int v = (t < NSCANB) ? g_bpart[t] : 0;
    int inc = v;
#pragma unroll
    for (int d = 1; d < 32; d <<= 1) {
        int n = __shfl_up_sync(~0u, inc, d);
        if (lane >= d) inc += n;
    }
    __shared__ int wsum[8];
    if (lane == 31) wsum[wp] = inc;
    __syncthreads();
    if (t == 0) {
        int r = 0;
        for (int q = 0; q < 8; q++) { int x = wsum[q]; wsum[q] = r; r += x; }
    }
    __syncthreads();
    if (t < NSCANB) g_bpre[t] = inc - v + wsum[wp];
    if (t == 0) g_off[N_NODES] = N_EDGES;
}

__global__ void k_scanC() {
    int b = blockIdx.x, t = threadIdx.x, lane = t & 31, wp = t >> 5;
    int i = b * 256 + t;
    int v = (i < N_NODES) ? g_deg[i] : 0;
    int inc = v;
#pragma unroll
    for (int d = 1; d < 32; d <<= 1) {
        int n = __shfl_up_sync(~0u, inc, d);
        if (lane >= d) inc += n;
    }
    __shared__ int wsum[8];
    if (lane == 31) wsum[wp] = inc;
    __syncthreads();
    if (t == 0) {
        int r = 0;
        for (int q = 0; q < 8; q++) { int x = wsum[q]; wsum[q] = r; r += x; }
    }
    __syncthreads();
    int off = g_bpre[b] + inc - v + wsum[wp];
    if (i < N_NODES) { g_off[i] = off; g_cursor[i] = off; }
}

__global__ void k_scatter() {
    int i = blockIdx.x * blockDim.x + threadIdx.x;
    if (i < N_EDGES) {
        int p = atomicAdd(&g_cursor[g_src[i]], 1);
        g_perm[p] = i;
    }
}

// ---------------- merged node kernel (fp32, proven) ----------------
#define NODE_SMEM_BYTES ((8192 + 4224) * 4)

__global__ void k_node(const float* __restrict__ x, const int* __restrict__ ntl,
                       const float* __restrict__ Wn, const float* __restrict__ Wupd,
                       const float* __restrict__ Wattn) {
    extern __shared__ float smn[];
    float* sx = smn;          // 32 x 256
    float* se = smn + 8192;   // 32 x 132
    int n0 = blockIdx.x * 32;
    int t = threadIdx.x;

    for (int i = t; i < 2048; i += 256) {
        int row = i >> 6, c4 = i & 63;
        int node = n0 + row;
        float4 v = make_float4(0.f, 0.f, 0.f, 0.f);
        if (node < N_NODES) v = ((const float4*)(x + (size_t)node * 256))[c4];
        ((float4*)sx)[row * 64 + c4] = v;
    }
    __syncthreads();

    int tx = t & 31, ty = t >> 5;
    int r0 = ty * 4;

    {   // emb = x @ W_node[type]
        const float* wp[4];
#pragma unroll
        for (int j = 0; j < 4; j++) {
            int node = n0 + r0 + j;
            int tp = (node < N_NODES) ? ntl[node] : 0;
            wp[j] = Wn + (size_t)tp * (256 * 128) + tx * 4;
        }
        float acc[4][4];
#pragma unroll
        for (int j = 0; j < 4; j++)
#pragma unroll
            for (int c = 0; c < 4; c++) acc[j][c] = 0.f;
#pragma unroll 4
        for (int k = 0; k < 256; k++) {
#pragma unroll
            for (int j = 0; j < 4; j++) {
                float4 w = *(const float4*)(wp[j] + (size_t)k * 128);
                float xv = sx[(r0 + j) * 256 + k];
                acc[j][0] += xv * w.x; acc[j][1] += xv * w.y;
                acc[j][2] += xv * w.z; acc[j][3] += xv * w.w;
            }
        }
#pragma unroll
        for (int j = 0; j < 4; j++)
            *(float4*)(se + (r0 + j) * 132 + tx * 4) =
                make_float4(acc[j][0], acc[j][1], acc[j][2], acc[j][3]);
    }
    __syncthreads();

    {   // P = emb @ W_upd[0:128]
        float acc[4][4];
#pragma unroll
        for (int j = 0; j < 4; j++)
#pragma unroll
            for (int c = 0; c < 4; c++) acc[j][c] = 0.f;
#pragma unroll 4
        for (int k = 0; k < 128; k++) {
            float4 w = *(const float4*)(Wupd + (size_t)k * 128 + tx * 4);
#pragma unroll
            for (int j = 0; j < 4; j++) {
                float xv = se[(r0 + j) * 132 + k];
                acc[j][0] += xv * w.x; acc[j][1] += xv * w.y;
                acc[j][2] += xv * w.z; acc[j][3] += xv * w.w;
            }
        }
#pragma unroll
        for (int j = 0; j < 4; j++) {
            int node = n0 + r0 + j;
            if (node < N_NODES)
                *(float4*)(g_P + (size_t)node * 128 + tx * 4) =
                    make_float4(acc[j][0], acc[j][1], acc[j][2], acc[j][3]);
        }
    }

    {   // s_tar / s_src
        int e = t >> 3, h = t & 7;
        int node = n0 + e;
        float at = 0.f, as = 0.f;
        for (int k = 0; k < 128; k++) {
            float v = se[e * 132 + k];
            at += v * Wattn[k * 8 + h];
            as += v * Wattn[(384 + k) * 8 + h];
        }
        if (node < N_NODES) {
            g_star[node * 8 + h] = at;
            g_ssrc[node * 8 + h] = as;
        }
    }
}

// ---------------- tensor-core edge kernel (packed-B) ----------------
#define XHI 0
#define XLO 2304
#define AHI 4608
#define ALO 8960
#define THI 13312
#define TLO 17664
#define EDGE_SMEM_U32 22016
#define EDGE_SMEM_BYTES (EDGE_SMEM_U32 * 4)

template <int KSTEPS, int STRIDE>
__device__ __forceinline__ void gemm_frag(const unsigned* xh, const unsigned* xl,
                                          const uint4* __restrict__ B,
                                          int rb, int nh, int lane, float acc[8][4]) {
    int fr = lane >> 2, fc = lane & 3;
#pragma unroll
    for (int kk = 0; kk < KSTEPS; kk++) {
        int o0 = (rb + fr) * STRIDE + kk * 8 + fc;
        int o1 = (rb + fr + 8) * STRIDE + kk * 8 + fc;
        unsigned ah0 = xh[o0], ah1 = xh[o1], ah2 = xh[o0 + 4], ah3 = xh[o1 + 4];
        unsigned al0 = xl[o0], al1 = xl[o1], al2 = xl[o0 + 4], al3 = xl[o1 + 4];
#pragma unroll
        for (int j = 0; j < 8; j++) {
            int n = nh * 64 + j * 8 + fr;
            uint4 b = B[(n * KSTEPS + kk) * 4 + fc];   // one LDG.128
            mma16816(acc[j], ah0, ah1, ah2, ah3, b.x, b.y);
            mma16816(acc[j], ah0, ah1, ah2, ah3, b.z, b.w);
            mma16816(acc[j], al0, al1, al2, al3, b.x, b.y);
        }
    }
}

__global__ void __launch_bounds__(256)
k_edge(const float* __restrict__ eattr, const float* __restrict__ etype) {
    extern __shared__ unsigned su[];
    __shared__ int sSrc[ETILE], sTar[ETILE];

    int t = threadIdx.x, lane = t & 31, w = t >> 5;
    int rt = w >> 1, nh = w & 1;
    int rb = rt * 16;
    int fr = lane >> 2, fc = lane & 3;
    int e0 = blockIdx.x * ETILE;

    {
        int row = t >> 2, cg = (t & 3) * 16;
        const float4* src = (const float4*)(eattr + (size_t)(e0 + row) * 64 + cg);
        unsigned* xh = su + XHI + row * 36 + cg / 2;
        unsigned* xl = su + XLO + row * 36 + cg / 2;
#pragma unroll
        for (int p = 0; p < 4; p++) {
            float4 v = src[p];
            unsigned h0, l0, h1, l1;
            splitpack(v.x, v.y, h0, l0);
            splitpack(v.z, v.w, h1, l1);
            xh[p * 2] = h0; xh[p * 2 + 1] = h1;
            xl[p * 2] = l0; xl[p * 2 + 1] = l1;
        }
    }
    if (t < ETILE) sSrc[t] = g_src[e0 + t];
    else if (t < 2 * ETILE) sTar[t - ETILE] = g_tar[e0 + t - ETILE];
    __syncthreads();

    float acc[8][4];

    // ---- phase A: A = lrelu(Xa @ Wea) ----
#pragma unroll
    for (int j = 0; j < 8; j++)
#pragma unroll
        for (int c = 0; c < 4; c++) acc[j][c] = 0.f;
    gemm_frag<4, 36>(su + XHI, su + XLO, gBea, rb, nh, lane, acc);
#pragma unroll
    for (int j = 0; j < 8; j++) {
        int colu = nh * 32 + j * 4 + fc;
        unsigned h, l;
        splitpack(lrelu(acc[j][0]), lrelu(acc[j][1]), h, l);
        su[AHI + (rb + fr) * 68 + colu] = h;
        su[ALO + (rb + fr) * 68 + colu] = l;
        splitpack(lrelu(acc[j][2]), lrelu(acc[j][3]), h, l);
        su[AHI + (rb + fr + 8) * 68 + colu] = h;
        su[ALO + (rb + fr + 8) * 68 + colu] = l;
    }
    __syncthreads();

    {
        int row = t >> 2, cg = (t & 3) * 16;
        const float4* src = (const float4*)(etype + (size_t)(e0 + row) * 64 + cg);
        unsigned* xh = su + XHI + row * 36 + cg / 2;
        unsigned* xl = su + XLO + row * 36 + cg / 2;
#pragma unroll
        for (int p = 0; p < 4; p++) {
            float4 v = src[p];
            unsigned h0, l0, h1, l1;
            splitpack(v.x, v.y, h0, l0);
            splitpack(v.z, v.w, h1, l1);
            xh[p * 2] = h0; xh[p * 2 + 1] = h1;
            xl[p * 2] = l0; xl[p * 2 + 1] = l1;
        }
    }
    __syncthreads();

    // ---- phase T: T = lrelu(Xt @ Wet) ----
#pragma unroll
    for (int j = 0; j < 8; j++)
#pragma unroll
        for (int c = 0; c < 4; c++) acc[j][c] = 0.f;
    gemm_frag<4, 36>(su + XHI, su + XLO, gBet, rb, nh, lane, acc);
#pragma unroll
    for (int j = 0; j < 8; j++) {
        int colu = nh * 32 + j * 4 + fc;
        unsigned h, l;
        splitpack(lrelu(acc[j][0]), lrelu(acc[j][1]), h, l);
        su[THI + (rb + fr) * 68 + colu] = h;
        su[TLO + (rb + fr) * 68 + colu] = l;
        splitpack(lrelu(acc[j][2]), lrelu(acc[j][3]), h, l);
        su[THI + (rb + fr + 8) * 68 + colu] = h;
        su[TLO + (rb + fr + 8) * 68 + colu] = l;
    }
    __syncthreads();

    // ---- scores (warps 0-3): D[64x8] = A@Wa1 + T@Wa2, packed B ----
    if (w < 4) {
        int srb = w * 16;
        float sacc[4] = {0.f, 0.f, 0.f, 0.f};
#pragma unroll
        for (int kk = 0; kk < 16; kk++) {
            int base_h = (kk < 8) ? AHI : THI;
            int base_l = (kk < 8) ? ALO : TLO;
            int kx = kk & 7;
            int o0 = (srb + fr) * 68 + kx * 8 + fc;
            int o1 = (srb + fr + 8) * 68 + kx * 8 + fc;
            unsigned ah0 = su[base_h + o0], ah1 = su[base_h + o1];
            unsigned ah2 = su[base_h + o0 + 4], ah3 = su[base_h + o1 + 4];
            unsigned al0 = su[base_l + o0], al1 = su[base_l + o1];
            unsigned al2 = su[base_l + o0 + 4], al3 = su[base_l + o1 + 4];
            uint4 b = gBa[(fr * 16 + kk) * 4 + fc];
            mma16816(sacc, ah0, ah1, ah2, ah3, b.x, b.y);
            mma16816(sacc, ah0, ah1, ah2, ah3, b.z, b.w);
            mma16816(sacc, al0, al1, al2, al3, b.x, b.y);
        }
        int h0 = fc * 2;
#pragma unroll
        for (int q = 0; q < 4; q++) {
            int row = srb + fr + (q >> 1) * 8;
            int h = h0 + (q & 1);
            int sr = sSrc[row], tg = sTar[row];
            float sc = sacc[q] + g_star[tg * 8 + h] + g_ssrc[sr * 8 + h];
            sc = lrelu(sc);
            float ex = expf(sc);
            g_ex[(e0 + row) * 8 + h] = ex;
            atomicAdd(&g_denom[sr * 8 + h], ex);
        }
    }

    // ---- phase P: attrpart = A @ Wupd[128:256] ----
#pragma unroll
    for (int j = 0; j < 8; j++)
#pragma unroll
        for (int c = 0; c < 4; c++) acc[j][c] = 0.f;
    gemm_frag<8, 68>(su + AHI, su + ALO, gBup, rb, nh, lane, acc);
#pragma unroll
    for (int j = 0; j < 8; j++) {
        int n0 = nh * 64 + j * 8 + fc * 2;
        *(float2*)(g_attrpart + (size_t)(e0 + rb + fr) * 128 + n0) =
            make_float2(acc[j][0], acc[j][1]);
        *(float2*)(g_attrpart + (size_t)(e0 + rb + fr + 8) * 128 + n0) =
            make_float2(acc[j][2], acc[j][3]);
    }
}

// ---------------- aggregation ----------------
__global__ void k_aggr(float* __restrict__ out) {
    int n = blockIdx.x;
    int t = threadIdx.x;
    int s = g_off[n], e_end = g_off[n + 1];
    float p = g_P[(size_t)n * 128 + t];
    float acc[8];
#pragma unroll
    for (int h = 0; h < 8; h++) acc[h] = 0.f;
    if (e_end > s) {
        for (int j = s; j < e_end; j++) {
            int e = g_perm[j];
            float m = lrelu(p + g_attrpart[(size_t)e * 128 + t]);
            const float4* xp = (const float4*)(g_ex + e * 8);
            float4 ea = xp[0], eb = xp[1];
            acc[0] += ea.x * m; acc[1] += ea.y * m; acc[2] += ea.z * m; acc[3] += ea.w * m;
            acc[4] += eb.x * m; acc[5] += eb.y * m; acc[6] += eb.z * m; acc[7] += eb.w * m;
        }
        const float4* dp = (const float4*)(g_denom + n * 8);
        float4 da = dp[0], db = dp[1];
        acc[0] /= da.x; acc[1] /= da.y; acc[2] /= da.z; acc[3] /= da.w;
        acc[4] /= db.x; acc[5] /= db.y; acc[6] /= db.z; acc[7] /= db.w;
    }
#pragma unroll
    for (int h = 0; h < 8; h++) out[(size_t)n * 1024 + h * 128 + t] = acc[h];
}

// ---------------- launch (k_edge at slot 4 for ncu) ----------------
extern "C" void kernel_launch(void* const* d_in, const int* in_sizes, int n_in,
                              void* d_out, int out_size) {
    const float* node_feats = (const float*)d_in[0];
    const int*   edge_index = (const int*)d_in[1];
    const float* edge_attr  = (const float*)d_in[2];
    const float* edge_type  = (const float*)d_in[3];
    const int*   ntl        = (const int*)d_in[4];
    const float* W_node  = (const float*)d_in[6];
    const float* W_eattr = (const float*)d_in[7];
    const float* W_etype = (const float*)d_in[8];
    const float* W_upd   = (const float*)d_in[9];
    const float* W_attn  = (const float*)d_in[10];
    float* out = (float*)d_out;

    cudaFuncSetAttribute(k_edge, cudaFuncAttributeMaxDynamicSharedMemorySize, EDGE_SMEM_BYTES);
    cudaFuncSetAttribute(k_node, cudaFuncAttributeMaxDynamicSharedMemorySize, NODE_SMEM_BYTES);

    const int TB = 256;
    const int GB_E = (N_EDGES + TB - 1) / TB;

    k_wprep<<<16, TB>>>(W_eattr, W_etype, W_upd, W_attn);                                   // 1
    k_init<<<GB_E, TB>>>(edge_index);                                                       // 2
    k_node<<<(N_NODES + 31) / 32, TB, NODE_SMEM_BYTES>>>(node_feats, ntl, W_node, W_upd, W_attn); // 3
    k_edge<<<NTILES, TB, EDGE_SMEM_BYTES>>>(edge_attr, edge_type);                          // 4 <- profiled
    k_hist<<<GB_E, TB>>>();                                                                 // 5
    k_scanA<<<NSCANB, TB>>>();                                                              // 6
    k_scanB<<<1, TB>>>();                                                                   // 7
    k_scanC<<<NSCANB, TB>>>();                                                              // 8
    k_scatter<<<GB_E, TB>>>();                                                              // 9
    k_aggr<<<N_NODES, 128>>>(out);                                                          // 10
}

// round 9
// speedup vs baseline: 2.3427x; 1.1217x over previous
#include <cuda_runtime.h>
#include <cuda_bf16.h>
#include <math.h>

#define N_NODES 50000
#define N_EDGES 400000
#define SLOPE   0.2f

#define ETILE   64
#define NTILES  (N_EDGES / ETILE)   // 6250, exact
#define NSCANB  196                 // ceil(50000/256)
#define NBLK3   1563                // ceil(50000/32) tiles per type bucket
#define PERM3_CAP (NBLK3 * 32)      // 50016

// ---------------- scratch ----------------
__device__ __align__(16) float g_P[(size_t)N_NODES * 128];
__device__ __align__(16) float g_star[N_NODES * 8];
__device__ __align__(16) float g_ssrc[N_NODES * 8];
__device__ __align__(16) float g_attrpart[(size_t)N_EDGES * 128];
__device__ __align__(16) float g_ex[N_EDGES * 8];
__device__ __align__(16) float g_denom[N_NODES * 8];
__device__ int g_src[N_EDGES], g_tar[N_EDGES];
__device__ int g_deg[N_NODES], g_off[N_NODES + 1], g_cursor[N_NODES], g_perm[N_EDGES];
__device__ int g_bpart[NSCANB], g_bpre[NSCANB];
__device__ int g_perm3[3 * PERM3_CAP];
__device__ int g_tcursor3[3];

// mma-ready packed B fragments: uint4 {bh0, bh1, bl0, bl1} per (n, kstep, fc)
__device__ __align__(16) uint4 gBea[128 * 4 * 4];   // Wea:  [n=128][kk=4][fc=4]
__device__ __align__(16) uint4 gBet[128 * 4 * 4];   // Wet
__device__ __align__(16) uint4 gBup[128 * 8 * 4];   // Wupd rows 128:256, [n=128][kk=8][fc=4]
__device__ __align__(16) uint4 gBa [8 * 16 * 4];    // Wattn rows 128:384, [h=8][kk=16][fc=4]

__device__ __forceinline__ float lrelu(float x) { return x >= 0.f ? x : SLOPE * x; }

__device__ __forceinline__ void splitpack(float x, float y, unsigned& hi, unsigned& lo) {
    __nv_bfloat16 hx = __float2bfloat16(x);
    __nv_bfloat16 hy = __float2bfloat16(y);
    float lx = x - __bfloat162float(hx);
    float ly = y - __bfloat162float(hy);
    __nv_bfloat162 h2 = __halves2bfloat162(hx, hy);
    __nv_bfloat162 l2 = __halves2bfloat162(__float2bfloat16(lx), __float2bfloat16(ly));
    hi = *reinterpret_cast<unsigned*>(&h2);
    lo = *reinterpret_cast<unsigned*>(&l2);
}

__device__ __forceinline__ uint4 pack4(float w0, float w1, float w2, float w3) {
    unsigned h0, l0, h1, l1;
    splitpack(w0, w1, h0, l0);
    splitpack(w2, w3, h1, l1);
    return make_uint4(h0, h1, l0, l1);
}

__device__ __forceinline__ void mma16816(float* c, unsigned a0, unsigned a1, unsigned a2,
                                         unsigned a3, unsigned b0, unsigned b1) {
    asm volatile(
        "mma.sync.aligned.m16n8k16.row.col.f32.bf16.bf16.f32 "
        "{%0,%1,%2,%3}, {%4,%5,%6,%7}, {%8,%9}, {%0,%1,%2,%3};"
        : "+f"(c[0]), "+f"(c[1]), "+f"(c[2]), "+f"(c[3])
        : "r"(a0), "r"(a1), "r"(a2), "r"(a3), "r"(b0), "r"(b1));
}

// ---------------- weight prep: pack into mma-ready uint4 fragments ----------------
__global__ void k_wprep(const float* __restrict__ Wea, const float* __restrict__ Wet,
                        const float* __restrict__ Wupd, const float* __restrict__ Wattn) {
    int i = blockIdx.x * blockDim.x + threadIdx.x;
    if (i < 2048) {            // Bea / Bet: n = i>>4, kk = (i>>2)&3, fc = i&3
        int n = i >> 4, kk = (i >> 2) & 3, fc = i & 3;
        int k0 = 2 * (kk * 8 + fc);
        gBea[i] = pack4(Wea[k0 * 128 + n],       Wea[(k0 + 1) * 128 + n],
                        Wea[(k0 + 8) * 128 + n], Wea[(k0 + 9) * 128 + n]);
        gBet[i] = pack4(Wet[k0 * 128 + n],       Wet[(k0 + 1) * 128 + n],
                        Wet[(k0 + 8) * 128 + n], Wet[(k0 + 9) * 128 + n]);
    }
    if (i < 4096) {            // Bup: n = i>>5, kk = (i>>2)&7, fc = i&3 (Wupd rows 128..255)
        int n = i >> 5, kk = (i >> 2) & 7, fc = i & 3;
        int k0 = 2 * (kk * 8 + fc);
        gBup[i] = pack4(Wupd[(128 + k0) * 128 + n], Wupd[(129 + k0) * 128 + n],
                        Wupd[(136 + k0) * 128 + n], Wupd[(137 + k0) * 128 + n]);
    }
    if (i < 512) {             // Ba: h = i>>6, kk = (i>>2)&15, fc = i&3 (Wattn rows 128..383)
        int h = i >> 6, kk = (i >> 2) & 15, fc = i & 3;
        int k0 = 2 * (kk * 8 + fc);
        gBa[i] = pack4(Wattn[(128 + k0) * 8 + h], Wattn[(129 + k0) * 8 + h],
                       Wattn[(136 + k0) * 8 + h], Wattn[(137 + k0) * 8 + h]);
    }
}

// ---------------- init (indices are INT32) ----------------
__global__ void k_init(const int* __restrict__ eidx) {
    int i = blockIdx.x * blockDim.x + threadIdx.x;
    if (i < N_EDGES) {
        g_src[i] = eidx[i];
        g_tar[i] = eidx[N_EDGES + i];
    }
    if (i < N_NODES * 8) g_denom[i] = 0.f;
    if (i < N_NODES) g_deg[i] = 0;
    if (i < 3 * PERM3_CAP) g_perm3[i] = -1;
    if (i < 3) g_tcursor3[i] = 0;
}

// scatter nodes into type buckets
__global__ void k_tscatter(const int* __restrict__ ntl) {
    int i = blockIdx.x * blockDim.x + threadIdx.x;
    if (i < N_NODES) {
        int tp = ntl[i];
        int p = atomicAdd(&g_tcursor3[tp], 1);
        g_perm3[tp * PERM3_CAP + p] = i;
    }
}

__global__ void k_hist() {
    int i = blockIdx.x * blockDim.x + threadIdx.x;
    if (i < N_EDGES) atomicAdd(&g_deg[g_src[i]], 1);
}

// ---------------- parallel scan (3 phases) ----------------
__global__ void k_scanA() {
    __shared__ int sh[8];
    int b = blockIdx.x, t = threadIdx.x, i = b * 256 + t;
    int v = (i < N_NODES) ? g_deg[i] : 0;
#pragma unroll
    for (int d = 16; d; d >>= 1) v += __shfl_down_sync(~0u, v, d);
    if ((t & 31) == 0) sh[t >> 5] = v;
    __syncthreads();
    if (t < 8) {
        int s = sh[t];
#pragma unroll
        for (int d = 4; d; d >>= 1) s += __shfl_down_sync(0xff, s, d);
        if (t == 0) g_bpart[b] = s;
    }
}

__global__ void k_scanB() {
    int t = threadIdx.x, lane = t & 31, wp = t >> 5;
    int v = (t < NSCANB) ? g_bpart[t] : 0;
    int inc = v;
#pragma unroll
    for (int d = 1; d < 32; d <<= 1) {
        int n = __shfl_up_sync(~0u, inc, d);
        if (lane >= d) inc += n;
    }
    __shared__ int wsum[8];
    if (lane == 31) wsum[wp] = inc;
    __syncthreads();
    if (t == 0) {
        int r = 0;
        for (int q = 0; q < 8; q++) { int x = wsum[q]; wsum[q] = r; r += x; }
    }
    __syncthreads();
    if (t < NSCANB) g_bpre[t] = inc - v + wsum[wp];
    if (t == 0) g_off[N_NODES] = N_EDGES;
}

__global__ void k_scanC() {
    int b = blockIdx.x, t = threadIdx.x, lane = t & 31, wp = t >> 5;
    int i = b * 256 + t;
    int v = (i < N_NODES) ? g_deg[i] : 0;
    int inc = v;
#pragma unroll
    for (int d = 1; d < 32; d <<= 1) {
        int n = __shfl_up_sync(~0u, inc, d);
        if (lane >= d) inc += n;
    }
    __shared__ int wsum[8];
    if (lane == 31) wsum[wp] = inc;
    __syncthreads();
    if (t == 0) {
        int r = 0;
        for (int q = 0; q < 8; q++) { int x = wsum[q]; wsum[q] = r; r += x; }
    }
    __syncthreads();
    int off = g_bpre[b] + inc - v + wsum[wp];
    if (i < N_NODES) { g_off[i] = off; g_cursor[i] = off; }
}

__global__ void k_scatter() {
    int i = blockIdx.x * blockDim.x + threadIdx.x;
    if (i < N_EDGES) {
        int p = atomicAdd(&g_cursor[g_src[i]], 1);
        g_perm[p] = i;
    }
}

// ---------------- type-bucketed node kernel (fp32, uniform weights per block) ----------------
#define NODE_SMEM_BYTES ((8192 + 4224) * 4)

__global__ void k_node(const float* __restrict__ x, const float* __restrict__ Wn,
                       const float* __restrict__ Wupd, const float* __restrict__ Wattn) {
    extern __shared__ float smn[];
    float* sx = smn;          // 32 x 256
    float* se = smn + 8192;   // 32 x 132
    __shared__ int sNid[32];
    int b = blockIdx.x;
    int tp = b / NBLK3;
    int base = tp * PERM3_CAP + (b - tp * NBLK3) * 32;
    int t = threadIdx.x;

    if (g_perm3[base] < 0) return;   // empty tile (uniform across block)
    if (t < 32) sNid[t] = g_perm3[base + t];
    __syncthreads();

    for (int i = t; i < 2048; i += 256) {
        int row = i >> 6, c4 = i & 63;
        int nid = sNid[row];
        float4 v = make_float4(0.f, 0.f, 0.f, 0.f);
        if (nid >= 0) v = ((const float4*)(x + (size_t)nid * 256))[c4];
        ((float4*)sx)[row * 64 + c4] = v;
    }
    __syncthreads();

    int tx = t & 31, ty = t >> 5;
    int r0 = ty * 4;

    {   // emb = x @ W_node[tp] — uniform weight stream per block
        const float* wrow = Wn + (size_t)tp * (256 * 128) + tx * 4;
        float acc[4][4];
#pragma unroll
        for (int j = 0; j < 4; j++)
#pragma unroll
            for (int c = 0; c < 4; c++) acc[j][c] = 0.f;
#pragma unroll 4
        for (int k = 0; k < 256; k++) {
            float4 w = *(const float4*)(wrow + (size_t)k * 128);
#pragma unroll
            for (int j = 0; j < 4; j++) {
                float xv = sx[(r0 + j) * 256 + k];
                acc[j][0] += xv * w.x; acc[j][1] += xv * w.y;
                acc[j][2] += xv * w.z; acc[j][3] += xv * w.w;
            }
        }
#pragma unroll
        for (int j = 0; j < 4; j++)
            *(float4*)(se + (r0 + j) * 132 + tx * 4) =
                make_float4(acc[j][0], acc[j][1], acc[j][2], acc[j][3]);
    }
    __syncthreads();

    {   // P = emb @ W_upd[0:128]
        float acc[4][4];
#pragma unroll
        for (int j = 0; j < 4; j++)
#pragma unroll
            for (int c = 0; c < 4; c++) acc[j][c] = 0.f;
#pragma unroll 4
        for (int k = 0; k < 128; k++) {
            float4 w = *(const float4*)(Wupd + (size_t)k * 128 + tx * 4);
#pragma unroll
            for (int j = 0; j < 4; j++) {
                float xv = se[(r0 + j) * 132 + k];
                acc[j][0] += xv * w.x; acc[j][1] += xv * w.y;
                acc[j][2] += xv * w.z; acc[j][3] += xv * w.w;
            }
        }
#pragma unroll
        for (int j = 0; j < 4; j++) {
            int nid = sNid[r0 + j];
            if (nid >= 0)
                *(float4*)(g_P + (size_t)nid * 128 + tx * 4) =
                    make_float4(acc[j][0], acc[j][1], acc[j][2], acc[j][3]);
        }
    }

    {   // s_tar / s_src
        int e = t >> 3, h = t & 7;
        int nid = sNid[e];
        float at = 0.f, as = 0.f;
        for (int k = 0; k < 128; k++) {
            float v = se[e * 132 + k];
            at += v * Wattn[k * 8 + h];
            as += v * Wattn[(384 + k) * 8 + h];
        }
        if (nid >= 0) {
            g_star[nid * 8 + h] = at;
            g_ssrc[nid * 8 + h] = as;
        }
    }
}

// ---------------- tensor-core edge kernel (packed-B, 32-row warps for B reuse) ----------------
#define XHI 0
#define XLO 2304
#define AHI 4608
#define ALO 8960
#define THI 13312
#define TLO 17664
#define EDGE_SMEM_U32 22016
#define EDGE_SMEM_BYTES (EDGE_SMEM_U32 * 4)

// warp computes rows {rb..rb+15, rb+32..rb+47} x cols [nh*32, nh*32+32)
template <int KSTEPS, int STRIDE>
__device__ __forceinline__ void gemm_frag2(const unsigned* xh, const unsigned* xl,
                                           const uint4* __restrict__ B,
                                           int rb, int nh, int lane, float acc[2][4][4]) {
    int fr = lane >> 2, fc = lane & 3;
#pragma unroll
    for (int kk = 0; kk < KSTEPS; kk++) {
        int o0 = (rb + fr) * STRIDE + kk * 8 + fc;
        int o1 = o0 + 8 * STRIDE;
        int o2 = o0 + 32 * STRIDE;
        int o3 = o0 + 40 * STRIDE;
        unsigned ah0 = xh[o0], ah1 = xh[o1], ah2 = xh[o0 + 4], ah3 = xh[o1 + 4];
        unsigned al0 = xl[o0], al1 = xl[o1], al2 = xl[o0 + 4], al3 = xl[o1 + 4];
        unsigned ch0 = xh[o2], ch1 = xh[o3], ch2 = xh[o2 + 4], ch3 = xh[o3 + 4];
        unsigned cl0 = xl[o2], cl1 = xl[o3], cl2 = xl[o2 + 4], cl3 = xl[o3 + 4];
#pragma unroll
        for (int j = 0; j < 4; j++) {
            int n = nh * 32 + j * 8 + fr;
            uint4 b = B[(n * KSTEPS + kk) * 4 + fc];   // one LDG.128, feeds 6 mmas
            mma16816(acc[0][j], ah0, ah1, ah2, ah3, b.x, b.y);
            mma16816(acc[0][j], ah0, ah1, ah2, ah3, b.z, b.w);
            mma16816(acc[0][j], al0, al1, al2, al3, b.x, b.y);
            mma16816(acc[1][j], ch0, ch1, ch2, ch3, b.x, b.y);
            mma16816(acc[1][j], ch0, ch1, ch2, ch3, b.z, b.w);
            mma16816(acc[1][j], cl0, cl1, cl2, cl3, b.x, b.y);
        }
    }
}

__global__ void __launch_bounds__(256)
k_edge(const float* __restrict__ eattr, const float* __restrict__ etype) {
    extern __shared__ unsigned su[];
    __shared__ int sSrc[ETILE], sTar[ETILE];

    int t = threadIdx.x, lane = t & 31, w = t >> 5;
    int nh = w & 3, rt = w >> 2;     // nh: 32-col quarter, rt: row half
    int rb = rt * 16;
    int fr = lane >> 2, fc = lane & 3;
    int e0 = blockIdx.x * ETILE;

    {
        int row = t >> 2, cg = (t & 3) * 16;
        const float4* src = (const float4*)(eattr + (size_t)(e0 + row) * 64 + cg);
        unsigned* xh = su + XHI + row * 36 + cg / 2;
        unsigned* xl = su + XLO + row * 36 + cg / 2;
#pragma unroll
        for (int p = 0; p < 4; p++) {
            float4 v = src[p];
            unsigned h0, l0, h1, l1;
            splitpack(v.x, v.y, h0, l0);
            splitpack(v.z, v.w, h1, l1);
            xh[p * 2] = h0; xh[p * 2 + 1] = h1;
            xl[p * 2] = l0; xl[p * 2 + 1] = l1;
        }
    }
    if (t < ETILE) sSrc[t] = g_src[e0 + t];
    else if (t < 2 * ETILE) sTar[t - ETILE] = g_tar[e0 + t - ETILE];
    __syncthreads();

    float acc[2][4][4];

    // ---- phase A: A = lrelu(Xa @ Wea) ----
#pragma unroll
    for (int ti = 0; ti < 2; ti++)
#pragma unroll
        for (int j = 0; j < 4; j++)
#pragma unroll
            for (int c = 0; c < 4; c++) acc[ti][j][c] = 0.f;
    gemm_frag2<4, 36>(su + XHI, su + XLO, gBea, rb, nh, lane, acc);
#pragma unroll
    for (int ti = 0; ti < 2; ti++)
#pragma unroll
        for (int j = 0; j < 4; j++) {
            int colu = nh * 16 + j * 4 + fc;
            int r = rb + fr + ti * 32;
            unsigned h, l;
            splitpack(lrelu(acc[ti][j][0]), lrelu(acc[ti][j][1]), h, l);
            su[AHI + r * 68 + colu] = h;
            su[ALO + r * 68 + colu] = l;
            splitpack(lrelu(acc[ti][j][2]), lrelu(acc[ti][j][3]), h, l);
            su[AHI + (r + 8) * 68 + colu] = h;
            su[ALO + (r + 8) * 68 + colu] = l;
        }
    __syncthreads();

    {
        int row = t >> 2, cg = (t & 3) * 16;
        const float4* src = (const float4*)(etype + (size_t)(e0 + row) * 64 + cg);
        unsigned* xh = su + XHI + row * 36 + cg / 2;
        unsigned* xl = su + XLO + row * 36 + cg / 2;
#pragma unroll
        for (int p = 0; p < 4; p++) {
            float4 v = src[p];
            unsigned h0, l0, h1, l1;
            splitpack(v.x, v.y, h0, l0);
            splitpack(v.z, v.w, h1, l1);
            xh[p * 2] = h0; xh[p * 2 + 1] = h1;
            xl[p * 2] = l0; xl[p * 2 + 1] = l1;
        }
    }
    __syncthreads();

    // ---- phase T: T = lrelu(Xt @ Wet) ----
#pragma unroll
    for (int ti = 0; ti < 2; ti++)
#pragma unroll
        for (int j = 0; j < 4; j++)
#pragma unroll
            for (int c = 0; c < 4; c++) acc[ti][j][c] = 0.f;
    gemm_frag2<4, 36>(su + XHI, su + XLO, gBet, rb, nh, lane, acc);
#pragma unroll
    for (int ti = 0; ti < 2; ti++)
#pragma unroll
        for (int j = 0; j < 4; j++) {
            int colu = nh * 16 + j * 4 + fc;
            int r = rb + fr + ti * 32;
            unsigned h, l;
            splitpack(lrelu(acc[ti][j][0]), lrelu(acc[ti][j][1]), h, l);
            su[THI + r * 68 + colu] = h;
            su[TLO + r * 68 + colu] = l;
            splitpack(lrelu(acc[ti][j][2]), lrelu(acc[ti][j][3]), h, l);
            su[THI + (r + 8) * 68 + colu] = h;
            su[TLO + (r + 8) * 68 + colu] = l;
        }
    __syncthreads();

    // ---- scores (warps 0-3): D[64x8] = A@Wa1 + T@Wa2, packed B ----
    if (w < 4) {
        int srb = w * 16;
        float sacc[4] = {0.f, 0.f, 0.f, 0.f};
#pragma unroll
        for (int kk = 0; kk < 16; kk++) {
            int base_h = (kk < 8) ? AHI : THI;
            int base_l = (kk < 8) ? ALO : TLO;
            int kx = kk & 7;
            int o0 = (srb + fr) * 68 + kx * 8 + fc;
            int o1 = (srb + fr + 8) * 68 + kx * 8 + fc;
            unsigned ah0 = su[base_h + o0], ah1 = su[base_h + o1];
            unsigned ah2 = su[base_h + o0 + 4], ah3 = su[base_h + o1 + 4];
            unsigned al0 = su[base_l + o0], al1 = su[base_l + o1];
            unsigned al2 = su[base_l + o0 + 4], al3 = su[base_l + o1 + 4];
            uint4 b = gBa[(fr * 16 + kk) * 4 + fc];
            mma16816(sacc, ah0, ah1, ah2, ah3, b.x, b.y);
            mma16816(sacc, ah0, ah1, ah2, ah3, b.z, b.w);
            mma16816(sacc, al0, al1, al2, al3, b.x, b.y);
        }
        int h0 = fc * 2;
#pragma unroll
        for (int q = 0; q < 4; q++) {
            int row = srb + fr + (q >> 1) * 8;
            int h = h0 + (q & 1);
            int sr = sSrc[row], tg = sTar[row];
            float sc = sacc[q] + g_star[tg * 8 + h] + g_ssrc[sr * 8 + h];
            sc = lrelu(sc);
            float ex = expf(sc);
            g_ex[(e0 + row) * 8 + h] = ex;
            atomicAdd(&g_denom[sr * 8 + h], ex);
        }
    }

    // ---- phase P: attrpart = A @ Wupd[128:256] ----
#pragma unroll
    for (int ti = 0; ti < 2; ti++)
#pragma unroll
        for (int j = 0; j < 4; j++)
#pragma unroll
            for (int c = 0; c < 4; c++) acc[ti][j][c] = 0.f;
    gemm_frag2<8, 68>(su + AHI, su + ALO, gBup, rb, nh, lane, acc);
#pragma unroll
    for (int ti = 0; ti < 2; ti++)
#pragma unroll
        for (int j = 0; j < 4; j++) {
            int n0 = nh * 32 + j * 8 + fc * 2;
            int r = rb + fr + ti * 32;
            *(float2*)(g_attrpart + (size_t)(e0 + r) * 128 + n0) =
                make_float2(acc[ti][j][0], acc[ti][j][1]);
            *(float2*)(g_attrpart + (size_t)(e0 + r + 8) * 128 + n0) =
                make_float2(acc[ti][j][2], acc[ti][j][3]);
        }
}

// ---------------- aggregation ----------------
__global__ void k_aggr(float* __restrict__ out) {
    int n = blockIdx.x;
    int t = threadIdx.x;
    int s = g_off[n], e_end = g_off[n + 1];
    float p = g_P[(size_t)n * 128 + t];
    float acc[8];
#pragma unroll
    for (int h = 0; h < 8; h++) acc[h] = 0.f;
    if (e_end > s) {
        for (int j = s; j < e_end; j++) {
            int e = g_perm[j];
            float m = lrelu(p + g_attrpart[(size_t)e * 128 + t]);
            const float4* xp = (const float4*)(g_ex + e * 8);
            float4 ea = xp[0], eb = xp[1];
            acc[0] += ea.x * m; acc[1] += ea.y * m; acc[2] += ea.z * m; acc[3] += ea.w * m;
            acc[4] += eb.x * m; acc[5] += eb.y * m; acc[6] += eb.z * m; acc[7] += eb.w * m;
        }
        const float4* dp = (const float4*)(g_denom + n * 8);
        float4 da = dp[0], db = dp[1];
        acc[0] /= da.x; acc[1] /= da.y; acc[2] /= da.z; acc[3] /= da.w;
        acc[4] /= db.x; acc[5] /= db.y; acc[6] /= db.z; acc[7] /= db.w;
    }
#pragma unroll
    for (int h = 0; h < 8; h++) out[(size_t)n * 1024 + h * 128 + t] = acc[h];
}

// ---------------- launch (k_node at slot 4 for ncu) ----------------
extern "C" void kernel_launch(void* const* d_in, const int* in_sizes, int n_in,
                              void* d_out, int out_size) {
    const float* node_feats = (const float*)d_in[0];
    const int*   edge_index = (const int*)d_in[1];
    const float* edge_attr  = (const float*)d_in[2];
    const float* edge_type  = (const float*)d_in[3];
    const int*   ntl        = (const int*)d_in[4];
    const float* W_node  = (const float*)d_in[6];
    const float* W_eattr = (const float*)d_in[7];
    const float* W_etype = (const float*)d_in[8];
    const float* W_upd   = (const float*)d_in[9];
    const float* W_attn  = (const float*)d_in[10];
    float* out = (float*)d_out;

    cudaFuncSetAttribute(k_edge, cudaFuncAttributeMaxDynamicSharedMemorySize, EDGE_SMEM_BYTES);
    cudaFuncSetAttribute(k_node, cudaFuncAttributeMaxDynamicSharedMemorySize, NODE_SMEM_BYTES);

    const int TB = 256;
    const int GB_E = (N_EDGES + TB - 1) / TB;

    k_wprep<<<16, TB>>>(W_eattr, W_etype, W_upd, W_attn);                                   // 1
    k_init<<<GB_E, TB>>>(edge_index);                                                       // 2
    k_tscatter<<<(N_NODES + TB - 1) / TB, TB>>>(ntl);                                       // 3
    k_node<<<3 * NBLK3, TB, NODE_SMEM_BYTES>>>(node_feats, W_node, W_upd, W_attn);          // 4 <- profiled
    k_edge<<<NTILES, TB, EDGE_SMEM_BYTES>>>(edge_attr, edge_type);                          // 5
    k_hist<<<GB_E, TB>>>();                                                                 // 6
    k_scanA<<<NSCANB, TB>>>();                                                              // 7
    k_scanB<<<1, TB>>>();                                                                   // 8
    k_scanC<<<NSCANB, TB>>>();                                                              // 9
    k_scatter<<<GB_E, TB>>>();                                                              // 10
    k_aggr<<<N_NODES, 128>>>(out);                                                          // 11
}

// round 10
// speedup vs baseline: 2.9389x; 1.2545x over previous
#include <cuda_runtime.h>
#include <cuda_bf16.h>
#include <math.h>

#define N_NODES 50000
#define N_EDGES 400000
#define SLOPE   0.2f

#define ETILE   64
#define NTILES  (N_EDGES / ETILE)   // 6250, exact
#define NSCANB  196                 // ceil(50000/256)
#define NBLK64  782                 // ceil(50000/64) tiles per type bucket
#define PERM3_CAP (NBLK64 * 64)     // 50048

// ---------------- scratch ----------------
__device__ __align__(16) float g_P[(size_t)N_NODES * 128];
__device__ __align__(16) float g_star[N_NODES * 8];
__device__ __align__(16) float g_ssrc[N_NODES * 8];
__device__ __align__(16) float g_attrpart[(size_t)N_EDGES * 128];
__device__ __align__(16) float g_ex[N_EDGES * 8];
__device__ __align__(16) float g_denom[N_NODES * 8];
__device__ int g_src[N_EDGES], g_tar[N_EDGES];
__device__ int g_deg[N_NODES], g_off[N_NODES + 1], g_cursor[N_NODES], g_perm[N_EDGES];
__device__ int g_bpart[NSCANB], g_bpre[NSCANB];
__device__ int g_perm3[3 * PERM3_CAP];
__device__ int g_tcursor3[3];

// mma-ready packed B fragments: uint4 {bh0, bh1, bl0, bl1} per (n, kstep, fc)
__device__ __align__(16) uint4 gBea[128 * 4 * 4];      // Wea:  [n=128][kk=4][fc=4]
__device__ __align__(16) uint4 gBet[128 * 4 * 4];      // Wet
__device__ __align__(16) uint4 gBup[128 * 8 * 4];      // Wupd rows 128:256
__device__ __align__(16) uint4 gBa [8 * 16 * 4];       // Wattn rows 128:384
__device__ __align__(16) uint4 gBn [3 * 128 * 16 * 4]; // W_node: [t][n=128][kk=16][fc=4]
__device__ __align__(16) uint4 gBuT[128 * 8 * 4];      // Wupd rows 0:128
__device__ __align__(16) uint4 gBs [16 * 8 * 4];       // scores: n<8 star head n, n>=8 ssrc head n-8

__device__ __forceinline__ float lrelu(float x) { return x >= 0.f ? x : SLOPE * x; }

__device__ __forceinline__ void splitpack(float x, float y, unsigned& hi, unsigned& lo) {
    __nv_bfloat16 hx = __float2bfloat16(x);
    __nv_bfloat16 hy = __float2bfloat16(y);
    float lx = x - __bfloat162float(hx);
    float ly = y - __bfloat162float(hy);
    __nv_bfloat162 h2 = __halves2bfloat162(hx, hy);
    __nv_bfloat162 l2 = __halves2bfloat162(__float2bfloat16(lx), __float2bfloat16(ly));
    hi = *reinterpret_cast<unsigned*>(&h2);
    lo = *reinterpret_cast<unsigned*>(&l2);
}

__device__ __forceinline__ uint4 pack4(float w0, float w1, float w2, float w3) {
    unsigned h0, l0, h1, l1;
    splitpack(w0, w1, h0, l0);
    splitpack(w2, w3, h1, l1);
    return make_uint4(h0, h1, l0, l1);
}

__device__ __forceinline__ void mma16816(float* c, unsigned a0, unsigned a1, unsigned a2,
                                         unsigned a3, unsigned b0, unsigned b1) {
    asm volatile(
        "mma.sync.aligned.m16n8k16.row.col.f32.bf16.bf16.f32 "
        "{%0,%1,%2,%3}, {%4,%5,%6,%7}, {%8,%9}, {%0,%1,%2,%3};"
        : "+f"(c[0]), "+f"(c[1]), "+f"(c[2]), "+f"(c[3])
        : "r"(a0), "r"(a1), "r"(a2), "r"(a3), "r"(b0), "r"(b1));
}

// ---------------- weight prep: pack into mma-ready uint4 fragments ----------------
__global__ void k_wprep(const float* __restrict__ Wea, const float* __restrict__ Wet,
                        const float* __restrict__ Wupd, const float* __restrict__ Wattn,
                        const float* __restrict__ Wn) {
    int i = blockIdx.x * blockDim.x + threadIdx.x;
    if (i < 2048) {            // Bea / Bet
        int n = i >> 4, kk = (i >> 2) & 3, fc = i & 3;
        int k0 = 2 * (kk * 8 + fc);
        gBea[i] = pack4(Wea[k0 * 128 + n],       Wea[(k0 + 1) * 128 + n],
                        Wea[(k0 + 8) * 128 + n], Wea[(k0 + 9) * 128 + n]);
        gBet[i] = pack4(Wet[k0 * 128 + n],       Wet[(k0 + 1) * 128 + n],
                        Wet[(k0 + 8) * 128 + n], Wet[(k0 + 9) * 128 + n]);
    }
    if (i < 4096) {            // Bup (rows 128..255) and BuT (rows 0..127)
        int n = i >> 5, kk = (i >> 2) & 7, fc = i & 3;
        int k0 = 2 * (kk * 8 + fc);
        gBup[i] = pack4(Wupd[(128 + k0) * 128 + n], Wupd[(129 + k0) * 128 + n],
                        Wupd[(136 + k0) * 128 + n], Wupd[(137 + k0) * 128 + n]);
        gBuT[i] = pack4(Wupd[k0 * 128 + n],       Wupd[(k0 + 1) * 128 + n],
                        Wupd[(k0 + 8) * 128 + n], Wupd[(k0 + 9) * 128 + n]);
    }
    if (i < 512) {             // Ba (Wattn rows 128..383) and Bs (rows 0..127 / 384..511)
        int h = i >> 6, kk = (i >> 2) & 15, fc = i & 3;
        int k0 = 2 * (kk * 8 + fc);
        gBa[i] = pack4(Wattn[(128 + k0) * 8 + h], Wattn[(129 + k0) * 8 + h],
                       Wattn[(136 + k0) * 8 + h], Wattn[(137 + k0) * 8 + h]);
        int n = i >> 5, kk2 = (i >> 2) & 7, fc2 = i & 3;
        int q0 = 2 * (kk2 * 8 + fc2);
        int ro = (n < 8) ? 0 : 384;
        int hh = (n < 8) ? n : n - 8;
        gBs[i] = pack4(Wattn[(ro + q0) * 8 + hh],     Wattn[(ro + q0 + 1) * 8 + hh],
                       Wattn[(ro + q0 + 8) * 8 + hh], Wattn[(ro + q0 + 9) * 8 + hh]);
    }
    if (i < 24576) {           // Bn: tp = i>>13, n = (i>>6)&127, kk = (i>>2)&15, fc = i&3
        int tp = i >> 13, r = i & 8191;
        int n = r >> 6, kk = (r >> 2) & 15, fc = r & 3;
        int k0 = 2 * (kk * 8 + fc);
        const float* W = Wn + (size_t)tp * 32768;
        gBn[i] = pack4(W[k0 * 128 + n],       W[(k0 + 1) * 128 + n],
                       W[(k0 + 8) * 128 + n], W[(k0 + 9) * 128 + n]);
    }
}

// ---------------- init (indices are INT32) ----------------
__global__ void k_init(const int* __restrict__ eidx) {
    int i = blockIdx.x * blockDim.x + threadIdx.x;
    if (i < N_EDGES) {
        g_src[i] = eidx[i];
        g_tar[i] = eidx[N_EDGES + i];
    }
    if (i < N_NODES * 8) g_denom[i] = 0.f;
    if (i < N_NODES) g_deg[i] = 0;
    if (i < 3 * PERM3_CAP) g_perm3[i] = -1;
    if (i < 3) g_tcursor3[i] = 0;
}

__global__ void k_tscatter(const int* __restrict__ ntl) {
    int i = blockIdx.x * blockDim.x + threadIdx.x;
    if (i < N_NODES) {
        int tp = ntl[i];
        int p = atomicAdd(&g_tcursor3[tp], 1);
        g_perm3[tp * PERM3_CAP + p] = i;
    }
}

__global__ void k_hist() {
    int i = blockIdx.x * blockDim.x + threadIdx.x;
    if (i < N_EDGES) atomicAdd(&g_deg[g_src[i]], 1);
}

// ---------------- parallel scan (3 phases) ----------------
__global__ void k_scanA() {
    __shared__ int sh[8];
    int b = blockIdx.x, t = threadIdx.x, i = b * 256 + t;
    int v = (i < N_NODES) ? g_deg[i] : 0;
#pragma unroll
    for (int d = 16; d; d >>= 1) v += __shfl_down_sync(~0u, v, d);
    if ((t & 31) == 0) sh[t >> 5] = v;
    __syncthreads();
    if (t < 8) {
        int s = sh[t];
#pragma unroll
        for (int d = 4; d; d >>= 1) s += __shfl_down_sync(0xff, s, d);
        if (t == 0) g_bpart[b] = s;
    }
}

__global__ void k_scanB() {
    int t = threadIdx.x, lane = t & 31, wp = t >> 5;
    int v = (t < NSCANB) ? g_bpart[t] : 0;
    int inc = v;
#pragma unroll
    for (int d = 1; d < 32; d <<= 1) {
        int n = __shfl_up_sync(~0u, inc, d);
        if (lane >= d) inc += n;
    }
    __shared__ int wsum[8];
    if (lane == 31) wsum[wp] = inc;
    __syncthreads();
    if (t == 0) {
        int r = 0;
        for (int q = 0; q < 8; q++) { int x = wsum[q]; wsum[q] = r; r += x; }
    }
    __syncthreads();
    if (t < NSCANB) g_bpre[t] = inc - v + wsum[wp];
    if (t == 0) g_off[N_NODES] = N_EDGES;
}

__global__ void k_scanC() {
    int b = blockIdx.x, t = threadIdx.x, lane = t & 31, wp = t >> 5;
    int i = b * 256 + t;
    int v = (i < N_NODES) ? g_deg[i] : 0;
    int inc = v;
#pragma unroll
    for (int d = 1; d < 32; d <<= 1) {
        int n = __shfl_up_sync(~0u, inc, d);
        if (lane >= d) inc += n;
    }
    __shared__ int wsum[8];
    if (lane == 31) wsum[wp] = inc;
    __syncthreads();
    if (t == 0) {
        int r = 0;
        for (int q = 0; q < 8; q++) { int x = wsum[q]; wsum[q] = r; r += x; }
    }
    __syncthreads();
    int off = g_bpre[b] + inc - v + wsum[wp];
    if (i < N_NODES) { g_off[i] = off; g_cursor[i] = off; }
}

__global__ void k_scatter() {
    int i = blockIdx.x * blockDim.x + threadIdx.x;
    if (i < N_EDGES) {
        int p = atomicAdd(&g_cursor[g_src[i]], 1);
        g_perm[p] = i;
    }
}

// ---------------- shared gemm fragment helper (32 rows x 32 cols per warp) ----------------
template <int KSTEPS, int STRIDE>
__device__ __forceinline__ void gemm_frag2(const unsigned* xh, const unsigned* xl,
                                           const uint4* __restrict__ B,
                                           int rb, int nh, int lane, float acc[2][4][4]) {
    int fr = lane >> 2, fc = lane & 3;
#pragma unroll
    for (int kk = 0; kk < KSTEPS; kk++) {
        int o0 = (rb + fr) * STRIDE + kk * 8 + fc;
        int o1 = o0 + 8 * STRIDE;
        int o2 = o0 + 32 * STRIDE;
        int o3 = o0 + 40 * STRIDE;
        unsigned ah0 = xh[o0], ah1 = xh[o1], ah2 = xh[o0 + 4], ah3 = xh[o1 + 4];
        unsigned al0 = xl[o0], al1 = xl[o1], al2 = xl[o0 + 4], al3 = xl[o1 + 4];
        unsigned ch0 = xh[o2], ch1 = xh[o3], ch2 = xh[o2 + 4], ch3 = xh[o3 + 4];
        unsigned cl0 = xl[o2], cl1 = xl[o3], cl2 = xl[o2 + 4], cl3 = xl[o3 + 4];
#pragma unroll
        for (int j = 0; j < 4; j++) {
            int n = nh * 32 + j * 8 + fr;
            uint4 b = B[(n * KSTEPS + kk) * 4 + fc];   // one LDG.128, feeds 6 mmas
            mma16816(acc[0][j], ah0, ah1, ah2, ah3, b.x, b.y);
            mma16816(acc[0][j], ah0, ah1, ah2, ah3, b.z, b.w);
            mma16816(acc[0][j], al0, al1, al2, al3, b.x, b.y);
            mma16816(acc[1][j], ch0, ch1, ch2, ch3, b.x, b.y);
            mma16816(acc[1][j], ch0, ch1, ch2, ch3, b.z, b.w);
            mma16816(acc[1][j], cl0, cl1, cl2, cl3, b.x, b.y);
        }
    }
}

// ---------------- tensor-core node kernel (M=64 tiles per type bucket) ----------------
// smem u32: Xhi[64*132] Xlo[64*132] Ehi[64*68] Elo[64*68]
#define N_XHI 0
#define N_XLO 8448
#define N_EHI 16896
#define N_ELO 21248
#define NODE_SMEM_U32 25600
#define NODE_SMEM_BYTES (NODE_SMEM_U32 * 4)

__global__ void __launch_bounds__(256)
k_node(const float* __restrict__ x) {
    extern __shared__ unsigned su[];
    __shared__ int sNid[64];
    unsigned* Xhi = su + N_XHI;
    unsigned* Xlo = su + N_XLO;
    unsigned* Ehi = su + N_EHI;
    unsigned* Elo = su + N_ELO;

    int t = threadIdx.x, lane = t & 31, w = t >> 5;
    int b = blockIdx.x;
    int tp = b / NBLK64;
    int base = tp * PERM3_CAP + (b - tp * NBLK64) * 64;

    if (g_perm3[base] < 0) return;   // fully empty tile (bucket fill is dense)
    if (t < 64) sNid[t] = g_perm3[base + t];
    __syncthreads();

    // stage X: 64 rows x 256 floats -> split bf16 hi/lo (stride 132 u32)
    {
        int row = t >> 2, seg = t & 3;       // 4 threads per row, 64 floats each
        int nid = sNid[row];
        const float4* src = (const float4*)(x + (size_t)(nid < 0 ? 0 : nid) * 256 + seg * 64);
        unsigned* xh = Xhi + row * 132 + seg * 32;
        unsigned* xl = Xlo + row * 132 + seg * 32;
#pragma unroll
        for (int p = 0; p < 16; p++) {
            float4 v = (nid >= 0) ? src[p] : make_float4(0.f, 0.f, 0.f, 0.f);
            unsigned h0, l0, h1, l1;
            splitpack(v.x, v.y, h0, l0);
            splitpack(v.z, v.w, h1, l1);
            xh[p * 2] = h0; xh[p * 2 + 1] = h1;
            xl[p * 2] = l0; xl[p * 2 + 1] = l1;
        }
    }
    __syncthreads();

    int nh = w & 3, rt = w >> 2;
    int rb = rt * 16;
    int fr = lane >> 2, fc = lane & 3;

    float acc[2][4][4];

    // ---- emb = X @ Wn[tp]  (K=256, 16 ksteps) ----
#pragma unroll
    for (int ti = 0; ti < 2; ti++)
#pragma unroll
        for (int j = 0; j < 4; j++)
#pragma unroll
            for (int c = 0; c < 4; c++) acc[ti][j][c] = 0.f;
    gemm_frag2<16, 132>(Xhi, Xlo, gBn + tp * 8192, rb, nh, lane, acc);
#pragma unroll
    for (int ti = 0; ti < 2; ti++)
#pragma unroll
        for (int j = 0; j < 4; j++) {
            int colu = nh * 16 + j * 4 + fc;
            int r = rb + fr + ti * 32;
            unsigned h, l;
            splitpack(acc[ti][j][0], acc[ti][j][1], h, l);
            Ehi[r * 68 + colu] = h;
            Elo[r * 68 + colu] = l;
            splitpack(acc[ti][j][2], acc[ti][j][3], h, l);
            Ehi[(r + 8) * 68 + colu] = h;
            Elo[(r + 8) * 68 + colu] = l;
        }
    __syncthreads();

    // ---- P = emb @ W_upd[0:128]  (K=128, 8 ksteps) ----
#pragma unroll
    for (int ti = 0; ti < 2; ti++)
#pragma unroll
        for (int j = 0; j < 4; j++)
#pragma unroll
            for (int c = 0; c < 4; c++) acc[ti][j][c] = 0.f;
    gemm_frag2<8, 68>(Ehi, Elo, gBuT, rb, nh, lane, acc);
#pragma unroll
    for (int ti = 0; ti < 2; ti++)
#pragma unroll
        for (int j = 0; j < 4; j++) {
            int n0 = nh * 32 + j * 8 + fc * 2;
            int r = rb + fr + ti * 32;
            int n1 = sNid[r], n2 = sNid[r + 8];
            if (n1 >= 0)
                *(float2*)(g_P + (size_t)n1 * 128 + n0) = make_float2(acc[ti][j][0], acc[ti][j][1]);
            if (n2 >= 0)
                *(float2*)(g_P + (size_t)n2 * 128 + n0) = make_float2(acc[ti][j][2], acc[ti][j][3]);
        }

    // ---- scores: D[64x16] = emb @ Ws (warps 0-3; cols 0..7 star, 8..15 ssrc) ----
    if (w < 4) {
        int srb = w * 16;
        float sa[2][4];
#pragma unroll
        for (int j = 0; j < 2; j++)
#pragma unroll
            for (int c = 0; c < 4; c++) sa[j][c] = 0.f;
#pragma unroll
        for (int kk = 0; kk < 8; kk++) {
            int o0 = (srb + fr) * 68 + kk * 8 + fc;
            int o1 = o0 + 8 * 68;
            unsigned ah0 = Ehi[o0], ah1 = Ehi[o1], ah2 = Ehi[o0 + 4], ah3 = Ehi[o1 + 4];
            unsigned al0 = Elo[o0], al1 = Elo[o1], al2 = Elo[o0 + 4], al3 = Elo[o1 + 4];
#pragma unroll
            for (int j = 0; j < 2; j++) {
                int n = j * 8 + fr;
                uint4 bq = gBs[(n * 8 + kk) * 4 + fc];
                mma16816(sa[j], ah0, ah1, ah2, ah3, bq.x, bq.y);
                mma16816(sa[j], ah0, ah1, ah2, ah3, bq.z, bq.w);
                mma16816(sa[j], al0, al1, al2, al3, bq.x, bq.y);
            }
        }
#pragma unroll
        for (int j = 0; j < 2; j++)
#pragma unroll
            for (int q = 0; q < 4; q++) {
                int row = srb + fr + (q >> 1) * 8;
                int nid = sNid[row];
                int h = fc * 2 + (q & 1);
                if (nid >= 0) {
                    if (j == 0) g_star[nid * 8 + h] = sa[j][q];
                    else        g_ssrc[nid * 8 + h] = sa[j][q];
                }
            }
    }
}

// ---------------- tensor-core edge kernel (packed-B, 32-row warps) ----------------
#define XHI 0
#define XLO 2304
#define AHI 4608
#define ALO 8960
#define THI 13312
#define TLO 17664
#define EDGE_SMEM_U32 22016
#define EDGE_SMEM_BYTES (EDGE_SMEM_U32 * 4)

__global__ void __launch_bounds__(256)
k_edge(const float* __restrict__ eattr, const float* __restrict__ etype) {
    extern __shared__ unsigned su[];
    __shared__ int sSrc[ETILE], sTar[ETILE];

    int t = threadIdx.x, lane = t & 31, w = t >> 5;
    int nh = w & 3, rt = w >> 2;
    int rb = rt * 16;
    int fr = lane >> 2, fc = lane & 3;
    int e0 = blockIdx.x * ETILE;

    {
        int row = t >> 2, cg = (t & 3) * 16;
        const float4* src = (const float4*)(eattr + (size_t)(e0 + row) * 64 + cg);
        unsigned* xh = su + XHI + row * 36 + cg / 2;
        unsigned* xl = su + XLO + row * 36 + cg / 2;
#pragma unroll
        for (int p = 0; p < 4; p++) {
            float4 v = src[p];
            unsigned h0, l0, h1, l1;
            splitpack(v.x, v.y, h0, l0);
            splitpack(v.z, v.w, h1, l1);
            xh[p * 2] = h0; xh[p * 2 + 1] = h1;
            xl[p * 2] = l0; xl[p * 2 + 1] = l1;
        }
    }
    if (t < ETILE) sSrc[t] = g_src[e0 + t];
    else if (t < 2 * ETILE) sTar[t - ETILE] = g_tar[e0 + t - ETILE];
    __syncthreads();

    float acc[2][4][4];

    // ---- phase A ----
#pragma unroll
    for (int ti = 0; ti < 2; ti++)
#pragma unroll
        for (int j = 0; j < 4; j++)
#pragma unroll
            for (int c = 0; c < 4; c++) acc[ti][j][c] = 0.f;
    gemm_frag2<4, 36>(su + XHI, su + XLO, gBea, rb, nh, lane, acc);
#pragma unroll
    for (int ti = 0; ti < 2; ti++)
#pragma unroll
        for (int j = 0; j < 4; j++) {
            int colu = nh * 16 + j * 4 + fc;
            int r = rb + fr + ti * 32;
            unsigned h, l;
            splitpack(lrelu(acc[ti][j][0]), lrelu(acc[ti][j][1]), h, l);
            su[AHI + r * 68 + colu] = h;
            su[ALO + r * 68 + colu] = l;
            splitpack(lrelu(acc[ti][j][2]), lrelu(acc[ti][j][3]), h, l);
            su[AHI + (r + 8) * 68 + colu] = h;
            su[ALO + (r + 8) * 68 + colu] = l;
        }
    __syncthreads();

    {
        int row = t >> 2, cg = (t & 3) * 16;
        const float4* src = (const float4*)(etype + (size_t)(e0 + row) * 64 + cg);
        unsigned* xh = su + XHI + row * 36 + cg / 2;
        unsigned* xl = su + XLO + row * 36 + cg / 2;
#pragma unroll
        for (int p = 0; p < 4; p++) {
            float4 v = src[p];
            unsigned h0, l0, h1, l1;
            splitpack(v.x, v.y, h0, l0);
            splitpack(v.z, v.w, h1, l1);
            xh[p * 2] = h0; xh[p * 2 + 1] = h1;
            xl[p * 2] = l0; xl[p * 2 + 1] = l1;
        }
    }
    __syncthreads();

    // ---- phase T ----
#pragma unroll
    for (int ti = 0; ti < 2; ti++)
#pragma unroll
        for (int j = 0; j < 4; j++)
#pragma unroll
            for (int c = 0; c < 4; c++) acc[ti][j][c] = 0.f;
    gemm_frag2<4, 36>(su + XHI, su + XLO, gBet, rb, nh, lane, acc);
#pragma unroll
    for (int ti = 0; ti < 2; ti++)
#pragma unroll
        for (int j = 0; j < 4; j++) {
            int colu = nh * 16 + j * 4 + fc;
            int r = rb + fr + ti * 32;
            unsigned h, l;
            splitpack(lrelu(acc[ti][j][0]), lrelu(acc[ti][j][1]), h, l);
            su[THI + r * 68 + colu] = h;
            su[TLO + r * 68 + colu] = l;
            splitpack(lrelu(acc[ti][j][2]), lrelu(acc[ti][j][3]), h, l);
            su[THI + (r + 8) * 68 + colu] = h;
            su[TLO + (r + 8) * 68 + colu] = l;
        }
    __syncthreads();

    // ---- scores (warps 0-3) ----
    if (w < 4) {
        int srb = w * 16;
        float sacc[4] = {0.f, 0.f, 0.f, 0.f};
#pragma unroll
        for (int kk = 0; kk < 16; kk++) {
            int base_h = (kk < 8) ? AHI : THI;
            int base_l = (kk < 8) ? ALO : TLO;
            int kx = kk & 7;
            int o0 = (srb + fr) * 68 + kx * 8 + fc;
            int o1 = (srb + fr + 8) * 68 + kx * 8 + fc;
            unsigned ah0 = su[base_h + o0], ah1 = su[base_h + o1];
            unsigned ah2 = su[base_h + o0 + 4], ah3 = su[base_h + o1 + 4];
            unsigned al0 = su[base_l + o0], al1 = su[base_l + o1];
            unsigned al2 = su[base_l + o0 + 4], al3 = su[base_l + o1 + 4];
            uint4 bq = gBa[(fr * 16 + kk) * 4 + fc];
            mma16816(sacc, ah0, ah1, ah2, ah3, bq.x, bq.y);
            mma16816(sacc, ah0, ah1, ah2, ah3, bq.z, bq.w);
            mma16816(sacc, al0, al1, al2, al3, bq.x, bq.y);
        }
        int h0 = fc * 2;
#pragma unroll
        for (int q = 0; q < 4; q++) {
            int row = srb + fr + (q >> 1) * 8;
            int h = h0 + (q & 1);
            int sr = sSrc[row], tg = sTar[row];
            float sc = sacc[q] + g_star[tg * 8 + h] + g_ssrc[sr * 8 + h];
            sc = lrelu(sc);
            float ex = expf(sc);
            g_ex[(e0 + row) * 8 + h] = ex;
            atomicAdd(&g_denom[sr * 8 + h], ex);
        }
    }

    // ---- phase P ----
#pragma unroll
    for (int ti = 0; ti < 2; ti++)
#pragma unroll
        for (int j = 0; j < 4; j++)
#pragma unroll
            for (int c = 0; c < 4; c++) acc[ti][j][c] = 0.f;
    gemm_frag2<8, 68>(su + AHI, su + ALO, gBup, rb, nh, lane, acc);
#pragma unroll
    for (int ti = 0; ti < 2; ti++)
#pragma unroll
        for (int j = 0; j < 4; j++) {
            int n0 = nh * 32 + j * 8 + fc * 2;
            int r = rb + fr + ti * 32;
            *(float2*)(g_attrpart + (size_t)(e0 + r) * 128 + n0) =
                make_float2(acc[ti][j][0], acc[ti][j][1]);
            *(float2*)(g_attrpart + (size_t)(e0 + r + 8) * 128 + n0) =
                make_float2(acc[ti][j][2], acc[ti][j][3]);
        }
}

// ---------------- aggregation ----------------
__global__ void k_aggr(float* __restrict__ out) {
    int n = blockIdx.x;
    int t = threadIdx.x;
    int s = g_off[n], e_end = g_off[n + 1];
    float p = g_P[(size_t)n * 128 + t];
    float acc[8];
#pragma unroll
    for (int h = 0; h < 8; h++) acc[h] = 0.f;
    if (e_end > s) {
        for (int j = s; j < e_end; j++) {
            int e = g_perm[j];
            float m = lrelu(p + g_attrpart[(size_t)e * 128 + t]);
            const float4* xp = (const float4*)(g_ex + e * 8);
            float4 ea = xp[0], eb = xp[1];
            acc[0] += ea.x * m; acc[1] += ea.y * m; acc[2] += ea.z * m; acc[3] += ea.w * m;
            acc[4] += eb.x * m; acc[5] += eb.y * m; acc[6] += eb.z * m; acc[7] += eb.w * m;
        }
        const float4* dp = (const float4*)(g_denom + n * 8);
        float4 da = dp[0], db = dp[1];
        acc[0] /= da.x; acc[1] /= da.y; acc[2] /= da.z; acc[3] /= da.w;
        acc[4] /= db.x; acc[5] /= db.y; acc[6] /= db.z; acc[7] /= db.w;
    }
#pragma unroll
    for (int h = 0; h < 8; h++) out[(size_t)n * 1024 + h * 128 + t] = acc[h];
}

// ---------------- launch (k_node at slot 4 for ncu) ----------------
extern "C" void kernel_launch(void* const* d_in, const int* in_sizes, int n_in,
                              void* d_out, int out_size) {
    const float* node_feats = (const float*)d_in[0];
    const int*   edge_index = (const int*)d_in[1];
    const float* edge_attr  = (const float*)d_in[2];
    const float* edge_type  = (const float*)d_in[3];
    const int*   ntl        = (const int*)d_in[4];
    const float* W_node  = (const float*)d_in[6];
    const float* W_eattr = (const float*)d_in[7];
    const float* W_etype = (const float*)d_in[8];
    const float* W_upd   = (const float*)d_in[9];
    const float* W_attn  = (const float*)d_in[10];
    float* out = (float*)d_out;

    cudaFuncSetAttribute(k_edge, cudaFuncAttributeMaxDynamicSharedMemorySize, EDGE_SMEM_BYTES);
    cudaFuncSetAttribute(k_node, cudaFuncAttributeMaxDynamicSharedMemorySize, NODE_SMEM_BYTES);

    const int TB = 256;
    const int GB_E = (N_EDGES + TB - 1) / TB;

    k_wprep<<<96, TB>>>(W_eattr, W_etype, W_upd, W_attn, W_node);                           // 1
    k_init<<<GB_E, TB>>>(edge_index);                                                       // 2
    k_tscatter<<<(N_NODES + TB - 1) / TB, TB>>>(ntl);                                       // 3
    k_node<<<3 * NBLK64, TB, NODE_SMEM_BYTES>>>(node_feats);                                // 4 <- profiled
    k_edge<<<NTILES, TB, EDGE_SMEM_BYTES>>>(edge_attr, edge_type);                          // 5
    k_hist<<<GB_E, TB>>>();                                                                 // 6
    k_scanA<<<NSCANB, TB>>>();                                                              // 7
    k_scanB<<<1, TB>>>();                                                                   // 8
    k_scanC<<<NSCANB, TB>>>();                                                              // 9
    k_scatter<<<GB_E, TB>>>();                                                              // 10
    k_aggr<<<N_NODES, 128>>>(out);                                                          // 11
}

// round 11
// speedup vs baseline: 3.2610x; 1.1096x over previous
#include <cuda_runtime.h>
#include <cuda_bf16.h>
#include <math.h>

#define N_NODES 50000
#define N_EDGES 400000
#define SLOPE   0.2f

#define ETILE   64
#define NTILES  (N_EDGES / ETILE)   // 6250, exact
#define NSCANB  196                 // ceil(50000/256)
#define NBLK64  782                 // ceil(50000/64) tiles per type bucket
#define PERM3_CAP (NBLK64 * 64)     // 50048

// ---------------- scratch ----------------
__device__ __align__(16) float g_P[(size_t)N_NODES * 128];
__device__ __align__(16) float g_star[N_NODES * 8];
__device__ __align__(16) float g_ssrc[N_NODES * 8];
__device__ __align__(16) float g_attrpart[(size_t)N_EDGES * 128];
__device__ __align__(16) float g_ex[N_EDGES * 8];
__device__ __align__(16) float g_denom[N_NODES * 8];
__device__ int g_src[N_EDGES], g_tar[N_EDGES];
__device__ int g_deg[N_NODES], g_off[N_NODES + 1], g_cursor[N_NODES], g_perm[N_EDGES];
__device__ int g_bpart[NSCANB], g_bpre[NSCANB];
__device__ int g_perm3[3 * PERM3_CAP];
__device__ int g_tcursor3[3];

// mma-ready packed B fragments: uint4 {bh0, bh1, bl0, bl1} per (n, kstep, fc)
__device__ __align__(16) uint4 gBea[128 * 4 * 4];      // Wea:  [n=128][kk=4][fc=4]
__device__ __align__(16) uint4 gBet[128 * 4 * 4];      // Wet
__device__ __align__(16) uint4 gBup[128 * 8 * 4];      // Wupd rows 128:256
__device__ __align__(16) uint4 gBa [8 * 16 * 4];       // Wattn rows 128:384
__device__ __align__(16) uint4 gBn [3 * 128 * 16 * 4]; // W_node: [t][n=128][kk=16][fc=4]
__device__ __align__(16) uint4 gBuT[128 * 8 * 4];      // Wupd rows 0:128
__device__ __align__(16) uint4 gBs [16 * 8 * 4];       // scores: n<8 star, n>=8 ssrc

__device__ __forceinline__ float lrelu(float x) { return x >= 0.f ? x : SLOPE * x; }

__device__ __forceinline__ void splitpack(float x, float y, unsigned& hi, unsigned& lo) {
    __nv_bfloat16 hx = __float2bfloat16(x);
    __nv_bfloat16 hy = __float2bfloat16(y);
    float lx = x - __bfloat162float(hx);
    float ly = y - __bfloat162float(hy);
    __nv_bfloat162 h2 = __halves2bfloat162(hx, hy);
    __nv_bfloat162 l2 = __halves2bfloat162(__float2bfloat16(lx), __float2bfloat16(ly));
    hi = *reinterpret_cast<unsigned*>(&h2);
    lo = *reinterpret_cast<unsigned*>(&l2);
}

__device__ __forceinline__ uint4 pack4(float w0, float w1, float w2, float w3) {
    unsigned h0, l0, h1, l1;
    splitpack(w0, w1, h0, l0);
    splitpack(w2, w3, h1, l1);
    return make_uint4(h0, h1, l0, l1);
}

__device__ __forceinline__ void mma16816(float* c, unsigned a0, unsigned a1, unsigned a2,
                                         unsigned a3, unsigned b0, unsigned b1) {
    asm volatile(
        "mma.sync.aligned.m16n8k16.row.col.f32.bf16.bf16.f32 "
        "{%0,%1,%2,%3}, {%4,%5,%6,%7}, {%8,%9}, {%0,%1,%2,%3};"
        : "+f"(c[0]), "+f"(c[1]), "+f"(c[2]), "+f"(c[3])
        : "r"(a0), "r"(a1), "r"(a2), "r"(a3), "r"(b0), "r"(b1));
}

// ---------------- fused init: indices + zeroing + weight pack ----------------
__global__ void k_init(const int* __restrict__ eidx,
                       const float* __restrict__ Wea, const float* __restrict__ Wet,
                       const float* __restrict__ Wupd, const float* __restrict__ Wattn,
                       const float* __restrict__ Wn) {
    int i = blockIdx.x * blockDim.x + threadIdx.x;
    if (i < N_EDGES) {
        g_src[i] = eidx[i];
        g_tar[i] = eidx[N_EDGES + i];
    }
    if (i < N_NODES * 8) g_denom[i] = 0.f;
    if (i < N_NODES) g_deg[i] = 0;
    if (i < 3 * PERM3_CAP) g_perm3[i] = -1;
    if (i < 3) g_tcursor3[i] = 0;

    // --- weight packing ---
    if (i < 2048) {            // Bea / Bet
        int n = i >> 4, kk = (i >> 2) & 3, fc = i & 3;
        int k0 = 2 * (kk * 8 + fc);
        gBea[i] = pack4(Wea[k0 * 128 + n],       Wea[(k0 + 1) * 128 + n],
                        Wea[(k0 + 8) * 128 + n], Wea[(k0 + 9) * 128 + n]);
        gBet[i] = pack4(Wet[k0 * 128 + n],       Wet[(k0 + 1) * 128 + n],
                        Wet[(k0 + 8) * 128 + n], Wet[(k0 + 9) * 128 + n]);
    }
    if (i < 4096) {            // Bup (rows 128..255) and BuT (rows 0..127)
        int n = i >> 5, kk = (i >> 2) & 7, fc = i & 3;
        int k0 = 2 * (kk * 8 + fc);
        gBup[i] = pack4(Wupd[(128 + k0) * 128 + n], Wupd[(129 + k0) * 128 + n],
                        Wupd[(136 + k0) * 128 + n], Wupd[(137 + k0) * 128 + n]);
        gBuT[i] = pack4(Wupd[k0 * 128 + n],       Wupd[(k0 + 1) * 128 + n],
                        Wupd[(k0 + 8) * 128 + n], Wupd[(k0 + 9) * 128 + n]);
    }
    if (i < 512) {             // Ba (Wattn rows 128..383) and Bs (rows 0..127 / 384..511)
        int h = i >> 6, kk = (i >> 2) & 15, fc = i & 3;
        int k0 = 2 * (kk * 8 + fc);
        gBa[i] = pack4(Wattn[(128 + k0) * 8 + h], Wattn[(129 + k0) * 8 + h],
                       Wattn[(136 + k0) * 8 + h], Wattn[(137 + k0) * 8 + h]);
        int n = i >> 5, kk2 = (i >> 2) & 7, fc2 = i & 3;
        int q0 = 2 * (kk2 * 8 + fc2);
        int ro = (n < 8) ? 0 : 384;
        int hh = (n < 8) ? n : n - 8;
        gBs[i] = pack4(Wattn[(ro + q0) * 8 + hh],     Wattn[(ro + q0 + 1) * 8 + hh],
                       Wattn[(ro + q0 + 8) * 8 + hh], Wattn[(ro + q0 + 9) * 8 + hh]);
    }
    if (i < 24576) {           // Bn
        int tp = i >> 13, r = i & 8191;
        int n = r >> 6, kk = (r >> 2) & 15, fc = r & 3;
        int k0 = 2 * (kk * 8 + fc);
        const float* W = Wn + (size_t)tp * 32768;
        gBn[i] = pack4(W[k0 * 128 + n],       W[(k0 + 1) * 128 + n],
                       W[(k0 + 8) * 128 + n], W[(k0 + 9) * 128 + n]);
    }
}

// fused: edge-degree histogram + node type-bucket scatter
__global__ void k_hist(const int* __restrict__ ntl) {
    int i = blockIdx.x * blockDim.x + threadIdx.x;
    if (i < N_EDGES) atomicAdd(&g_deg[g_src[i]], 1);
    if (i < N_NODES) {
        int tp = ntl[i];
        int p = atomicAdd(&g_tcursor3[tp], 1);
        g_perm3[tp * PERM3_CAP + p] = i;
    }
}

// ---------------- parallel scan (3 phases) ----------------
__global__ void k_scanA() {
    __shared__ int sh[8];
    int b = blockIdx.x, t = threadIdx.x, i = b * 256 + t;
    int v = (i < N_NODES) ? g_deg[i] : 0;
#pragma unroll
    for (int d = 16; d; d >>= 1) v += __shfl_down_sync(~0u, v, d);
    if ((t & 31) == 0) sh[t >> 5] = v;
    __syncthreads();
    if (t < 8) {
        int s = sh[t];
#pragma unroll
        for (int d = 4; d; d >>= 1) s += __shfl_down_sync(0xff, s, d);
        if (t == 0) g_bpart[b] = s;
    }
}

__global__ void k_scanB() {
    int t = threadIdx.x, lane = t & 31, wp = t >> 5;
    int v = (t < NSCANB) ? g_bpart[t] : 0;
    int inc = v;
#pragma unroll
    for (int d = 1; d < 32; d <<= 1) {
        int n = __shfl_up_sync(~0u, inc, d);
        if (lane >= d) inc += n;
    }
    __shared__ int wsum[8];
    if (lane == 31) wsum[wp] = inc;
    __syncthreads();
    if (t == 0) {
        int r = 0;
        for (int q = 0; q < 8; q++) { int x = wsum[q]; wsum[q] = r; r += x; }
    }
    __syncthreads();
    if (t < NSCANB) g_bpre[t] = inc - v + wsum[wp];
    if (t == 0) g_off[N_NODES] = N_EDGES;
}

__global__ void k_scanC() {
    int b = blockIdx.x, t = threadIdx.x, lane = t & 31, wp = t >> 5;
    int i = b * 256 + t;
    int v = (i < N_NODES) ? g_deg[i] : 0;
    int inc = v;
#pragma unroll
    for (int d = 1; d < 32; d <<= 1) {
        int n = __shfl_up_sync(~0u, inc, d);
        if (lane >= d) inc += n;
    }
    __shared__ int wsum[8];
    if (lane == 31) wsum[wp] = inc;
    __syncthreads();
    if (t == 0) {
        int r = 0;
        for (int q = 0; q < 8; q++) { int x = wsum[q]; wsum[q] = r; r += x; }
    }
    __syncthreads();
    int off = g_bpre[b] + inc - v + wsum[wp];
    if (i < N_NODES) { g_off[i] = off; g_cursor[i] = off; }
}

__global__ void k_scatter() {
    int i = blockIdx.x * blockDim.x + threadIdx.x;
    if (i < N_EDGES) {
        int p = atomicAdd(&g_cursor[g_src[i]], 1);
        g_perm[p] = i;
    }
}

// ---------------- shared gemm fragment helper (32 rows x 32 cols per warp) ----------------
template <int KSTEPS, int STRIDE>
__device__ __forceinline__ void gemm_frag2(const unsigned* xh, const unsigned* xl,
                                           const uint4* __restrict__ B,
                                           int rb, int nh, int lane, float acc[2][4][4]) {
    int fr = lane >> 2, fc = lane & 3;
#pragma unroll
    for (int kk = 0; kk < KSTEPS; kk++) {
        int o0 = (rb + fr) * STRIDE + kk * 8 + fc;
        int o1 = o0 + 8 * STRIDE;
        int o2 = o0 + 32 * STRIDE;
        int o3 = o0 + 40 * STRIDE;
        unsigned ah0 = xh[o0], ah1 = xh[o1], ah2 = xh[o0 + 4], ah3 = xh[o1 + 4];
        unsigned al0 = xl[o0], al1 = xl[o1], al2 = xl[o0 + 4], al3 = xl[o1 + 4];
        unsigned ch0 = xh[o2], ch1 = xh[o3], ch2 = xh[o2 + 4], ch3 = xh[o3 + 4];
        unsigned cl0 = xl[o2], cl1 = xl[o3], cl2 = xl[o2 + 4], cl3 = xl[o3 + 4];
#pragma unroll
        for (int j = 0; j < 4; j++) {
            int n = nh * 32 + j * 8 + fr;
            uint4 b = B[(n * KSTEPS + kk) * 4 + fc];   // one LDG.128, feeds 6 mmas
            mma16816(acc[0][j], ah0, ah1, ah2, ah3, b.x, b.y);
            mma16816(acc[0][j], ah0, ah1, ah2, ah3, b.z, b.w);
            mma16816(acc[0][j], al0, al1, al2, al3, b.x, b.y);
            mma16816(acc[1][j], ch0, ch1, ch2, ch3, b.x, b.y);
            mma16816(acc[1][j], ch0, ch1, ch2, ch3, b.z, b.w);
            mma16816(acc[1][j], cl0, cl1, cl2, cl3, b.x, b.y);
        }
    }
}

// ---------------- tensor-core node kernel (M=64 tiles; E aliases X -> 3 CTAs/SM) ----------------
// smem u32: X [64*132]*2 = 16896; E (hi 4352 + lo 4352) ALIASED onto [0, 8704)
#define N_XHI 0
#define N_XLO 8448
#define N_EHI 0
#define N_ELO 4352
#define NODE_SMEM_U32 16896
#define NODE_SMEM_BYTES (NODE_SMEM_U32 * 4)

__global__ void __launch_bounds__(256)
k_node(const float* __restrict__ x) {
    extern __shared__ unsigned su[];
    __shared__ int sNid[64];
    unsigned* Xhi = su + N_XHI;
    unsigned* Xlo = su + N_XLO;
    unsigned* Ehi = su + N_EHI;   // aliases X (dead after emb gemm)
    unsigned* Elo = su + N_ELO;

    int t = threadIdx.x, lane = t & 31, w = t >> 5;
    int b = blockIdx.x;
    int tp = b / NBLK64;
    int base = tp * PERM3_CAP + (b - tp * NBLK64) * 64;

    if (g_perm3[base] < 0) return;
    if (t < 64) sNid[t] = g_perm3[base + t];
    __syncthreads();

    // stage X: 64 rows x 256 floats -> split bf16 hi/lo (stride 132 u32)
    {
        int row = t >> 2, seg = t & 3;
        int nid = sNid[row];
        const float4* src = (const float4*)(x + (size_t)(nid < 0 ? 0 : nid) * 256 + seg * 64);
        unsigned* xh = Xhi + row * 132 + seg * 32;
        unsigned* xl = Xlo + row * 132 + seg * 32;
#pragma unroll
        for (int p = 0; p < 16; p++) {
            float4 v = (nid >= 0) ? src[p] : make_float4(0.f, 0.f, 0.f, 0.f);
            unsigned h0, l0, h1, l1;
            splitpack(v.x, v.y, h0, l0);
            splitpack(v.z, v.w, h1, l1);
            xh[p * 2] = h0; xh[p * 2 + 1] = h1;
            xl[p * 2] = l0; xl[p * 2 + 1] = l1;
        }
    }
    __syncthreads();

    int nh = w & 3, rt = w >> 2;
    int rb = rt * 16;
    int fr = lane >> 2, fc = lane & 3;

    float acc[2][4][4];

    // ---- emb = X @ Wn[tp]  (K=256, 16 ksteps) ----
#pragma unroll
    for (int ti = 0; ti < 2; ti++)
#pragma unroll
        for (int j = 0; j < 4; j++)
#pragma unroll
            for (int c = 0; c < 4; c++) acc[ti][j][c] = 0.f;
    gemm_frag2<16, 132>(Xhi, Xlo, gBn + tp * 8192, rb, nh, lane, acc);
    __syncthreads();   // all warps done reading X before E (aliased) is written
#pragma unroll
    for (int ti = 0; ti < 2; ti++)
#pragma unroll
        for (int j = 0; j < 4; j++) {
            int colu = nh * 16 + j * 4 + fc;
            int r = rb + fr + ti * 32;
            unsigned h, l;
            splitpack(acc[ti][j][0], acc[ti][j][1], h, l);
            Ehi[r * 68 + colu] = h;
            Elo[r * 68 + colu] = l;
            splitpack(acc[ti][j][2], acc[ti][j][3], h, l);
            Ehi[(r + 8) * 68 + colu] = h;
            Elo[(r + 8) * 68 + colu] = l;
        }
    __syncthreads();

    // ---- P = emb @ W_upd[0:128]  (K=128, 8 ksteps) ----
#pragma unroll
    for (int ti = 0; ti < 2; ti++)
#pragma unroll
        for (int j = 0; j < 4; j++)
#pragma unroll
            for (int c = 0; c < 4; c++) acc[ti][j][c] = 0.f;
    gemm_frag2<8, 68>(Ehi, Elo, gBuT, rb, nh, lane, acc);
#pragma unroll
    for (int ti = 0; ti < 2; ti++)
#pragma unroll
        for (int j = 0; j < 4; j++) {
            int n0 = nh * 32 + j * 8 + fc * 2;
            int r = rb + fr + ti * 32;
            int n1 = sNid[r], n2 = sNid[r + 8];
            if (n1 >= 0)
                *(float2*)(g_P + (size_t)n1 * 128 + n0) = make_float2(acc[ti][j][0], acc[ti][j][1]);
            if (n2 >= 0)
                *(float2*)(g_P + (size_t)n2 * 128 + n0) = make_float2(acc[ti][j][2], acc[ti][j][3]);
        }

    // ---- scores: D[64x16] = emb @ Ws (warps 0-3) ----
    if (w < 4) {
        int srb = w * 16;
        float sa[2][4];
#pragma unroll
        for (int j = 0; j < 2; j++)
#pragma unroll
            for (int c = 0; c < 4; c++) sa[j][c] = 0.f;
#pragma unroll
        for (int kk = 0; kk < 8; kk++) {
            int o0 = (srb + fr) * 68 + kk * 8 + fc;
            int o1 = o0 + 8 * 68;
            unsigned ah0 = Ehi[o0], ah1 = Ehi[o1], ah2 = Ehi[o0 + 4], ah3 = Ehi[o1 + 4];
            unsigned al0 = Elo[o0], al1 = Elo[o1], al2 = Elo[o0 + 4], al3 = Elo[o1 + 4];
#pragma unroll
            for (int j = 0; j < 2; j++) {
                int n = j * 8 + fr;
                uint4 bq = gBs[(n * 8 + kk) * 4 + fc];
                mma16816(sa[j], ah0, ah1, ah2, ah3, bq.x, bq.y);
                mma16816(sa[j], ah0, ah1, ah2, ah3, bq.z, bq.w);
                mma16816(sa[j], al0, al1, al2, al3, bq.x, bq.y);
            }
        }
#pragma unroll
        for (int j = 0; j < 2; j++)
#pragma unroll
            for (int q = 0; q < 4; q++) {
                int row = srb + fr + (q >> 1) * 8;
                int nid = sNid[row];
                int h = fc * 2 + (q & 1);
                if (nid >= 0) {
                    if (j == 0) g_star[nid * 8 + h] = sa[j][q];
                    else        g_ssrc[nid * 8 + h] = sa[j][q];
                }
            }
    }
}

// ---------------- tensor-core edge kernel (TLO aliases X -> 3 CTAs/SM) ----------------
#define XHI 0
#define XLO 2304
#define AHI 4608
#define ALO 8960
#define THI 13312
#define TLO 0            // aliases X staging (dead after phase-T gemm)
#define EDGE_SMEM_U32 17664
#define EDGE_SMEM_BYTES (EDGE_SMEM_U32 * 4)

__global__ void __launch_bounds__(256)
k_edge(const float* __restrict__ eattr, const float* __restrict__ etype) {
    extern __shared__ unsigned su[];
    __shared__ int sSrc[ETILE], sTar[ETILE];

    int t = threadIdx.x, lane = t & 31, w = t >> 5;
    int nh = w & 3, rt = w >> 2;
    int rb = rt * 16;
    int fr = lane >> 2, fc = lane & 3;
    int e0 = blockIdx.x * ETILE;

    {
        int row = t >> 2, cg = (t & 3) * 16;
        const float4* src = (const float4*)(eattr + (size_t)(e0 + row) * 64 + cg);
        unsigned* xh = su + XHI + row * 36 + cg / 2;
        unsigned* xl = su + XLO + row * 36 + cg / 2;
#pragma unroll
        for (int p = 0; p < 4; p++) {
            float4 v = src[p];
            unsigned h0, l0, h1, l1;
            splitpack(v.x, v.y, h0, l0);
            splitpack(v.z, v.w, h1, l1);
            xh[p * 2] = h0; xh[p * 2 + 1] = h1;
            xl[p * 2] = l0; xl[p * 2 + 1] = l1;
        }
    }
    if (t < ETILE) sSrc[t] = g_src[e0 + t];
    else if (t < 2 * ETILE) sTar[t - ETILE] = g_tar[e0 + t - ETILE];
    __syncthreads();

    float acc[2][4][4];

    // ---- phase A ----
#pragma unroll
    for (int ti = 0; ti < 2; ti++)
#pragma unroll
        for (int j = 0; j < 4; j++)
#pragma unroll
            for (int c = 0; c < 4; c++) acc[ti][j][c] = 0.f;
    gemm_frag2<4, 36>(su + XHI, su + XLO, gBea, rb, nh, lane, acc);
#pragma unroll
    for (int ti = 0; ti < 2; ti++)
#pragma unroll
        for (int j = 0; j < 4; j++) {
            int colu = nh * 16 + j * 4 + fc;
            int r = rb + fr + ti * 32;
            unsigned h, l;
            splitpack(lrelu(acc[ti][j][0]), lrelu(acc[ti][j][1]), h, l);
            su[AHI + r * 68 + colu] = h;
            su[ALO + r * 68 + colu] = l;
            splitpack(lrelu(acc[ti][j][2]), lrelu(acc[ti][j][3]), h, l);
            su[AHI + (r + 8) * 68 + colu] = h;
            su[ALO + (r + 8) * 68 + colu] = l;
        }
    __syncthreads();

    // stage Xt into X region
    {
        int row = t >> 2, cg = (t & 3) * 16;
        const float4* src = (const float4*)(etype + (size_t)(e0 + row) * 64 + cg);
        unsigned* xh = su + XHI + row * 36 + cg / 2;
        unsigned* xl = su + XLO + row * 36 + cg / 2;
#pragma unroll
        for (int p = 0; p < 4; p++) {
            float4 v = src[p];
            unsigned h0, l0, h1, l1;
            splitpack(v.x, v.y, h0, l0);
            splitpack(v.z, v.w, h1, l1);
            xh[p * 2] = h0; xh[p * 2 + 1] = h1;
            xl[p * 2] = l0; xl[p * 2 + 1] = l1;
        }
    }
    __syncthreads();

    // ---- phase T (TLO epilogue aliases X: sync after gemm reads) ----
#pragma unroll
    for (int ti = 0; ti < 2; ti++)
#pragma unroll
        for (int j = 0; j < 4; j++)
#pragma unroll
            for (int c = 0; c < 4; c++) acc[ti][j][c] = 0.f;
    gemm_frag2<4, 36>(su + XHI, su + XLO, gBet, rb, nh, lane, acc);
    __syncthreads();   // all warps done reading Xt before TLO (aliased) is written
#pragma unroll
    for (int ti = 0; ti < 2; ti++)
#pragma unroll
        for (int j = 0; j < 4; j++) {
            int colu = nh * 16 + j * 4 + fc;
            int r = rb + fr + ti * 32;
            unsigned h, l;
            splitpack(lrelu(acc[ti][j][0]), lrelu(acc[ti][j][1]), h, l);
            su[THI + r * 68 + colu] = h;
            su[TLO + r * 68 + colu] = l;
            splitpack(lrelu(acc[ti][j][2]), lrelu(acc[ti][j][3]), h, l);
            su[THI + (r + 8) * 68 + colu] = h;
            su[TLO + (r + 8) * 68 + colu] = l;
        }
    __syncthreads();

    // ---- scores (warps 0-3) ----
    if (w < 4) {
        int srb = w * 16;
        float sacc[4] = {0.f, 0.f, 0.f, 0.f};
#pragma unroll
        for (int kk = 0; kk < 16; kk++) {
            int base_h = (kk < 8) ? AHI : THI;
            int base_l = (kk < 8) ? ALO : TLO;
            int kx = kk & 7;
            int o0 = (srb + fr) * 68 + kx * 8 + fc;
            int o1 = (srb + fr + 8) * 68 + kx * 8 + fc;
            unsigned ah0 = su[base_h + o0], ah1 = su[base_h + o1];
            unsigned ah2 = su[base_h + o0 + 4], ah3 = su[base_h + o1 + 4];
            unsigned al0 = su[base_l + o0], al1 = su[base_l + o1];
            unsigned al2 = su[base_l + o0 + 4], al3 = su[base_l + o1 + 4];
            uint4 bq = gBa[(fr * 16 + kk) * 4 + fc];
            mma16816(sacc, ah0, ah1, ah2, ah3, bq.x, bq.y);
            mma16816(sacc, ah0, ah1, ah2, ah3, bq.z, bq.w);
            mma16816(sacc, al0, al1, al2, al3, bq.x, bq.y);
        }
        int h0 = fc * 2;
#pragma unroll
        for (int q = 0; q < 4; q++) {
            int row = srb + fr + (q >> 1) * 8;
            int h = h0 + (q & 1);
            int sr = sSrc[row], tg = sTar[row];
            float sc = sacc[q] + g_star[tg * 8 + h] + g_ssrc[sr * 8 + h];
            sc = lrelu(sc);
            float ex = expf(sc);
            g_ex[(e0 + row) * 8 + h] = ex;
            atomicAdd(&g_denom[sr * 8 + h], ex);
        }
    }

    // ---- phase P ----
#pragma unroll
    for (int ti = 0; ti < 2; ti++)
#pragma unroll
        for (int j = 0; j < 4; j++)
#pragma unroll
            for (int c = 0; c < 4; c++) acc[ti][j][c] = 0.f;
    gemm_frag2<8, 68>(su + AHI, su + ALO, gBup, rb, nh, lane, acc);
#pragma unroll
    for (int ti = 0; ti < 2; ti++)
#pragma unroll
        for (int j = 0; j < 4; j++) {
            int n0 = nh * 32 + j * 8 + fc * 2;
            int r = rb + fr + ti * 32;
            *(float2*)(g_attrpart + (size_t)(e0 + r) * 128 + n0) =
                make_float2(acc[ti][j][0], acc[ti][j][1]);
            *(float2*)(g_attrpart + (size_t)(e0 + r + 8) * 128 + n0) =
                make_float2(acc[ti][j][2], acc[ti][j][3]);
        }
}

// ---------------- aggregation ----------------
__global__ void k_aggr(float* __restrict__ out) {
    int n = blockIdx.x;
    int t = threadIdx.x;
    int s = g_off[n], e_end = g_off[n + 1];
    float p = g_P[(size_t)n * 128 + t];
    float acc[8];
#pragma unroll
    for (int h = 0; h < 8; h++) acc[h] = 0.f;
    if (e_end > s) {
        for (int j = s; j < e_end; j++) {
            int e = g_perm[j];
            float m = lrelu(p + g_attrpart[(size_t)e * 128 + t]);
            const float4* xp = (const float4*)(g_ex + e * 8);
            float4 ea = xp[0], eb = xp[1];
            acc[0] += ea.x * m; acc[1] += ea.y * m; acc[2] += ea.z * m; acc[3] += ea.w * m;
            acc[4] += eb.x * m; acc[5] += eb.y * m; acc[6] += eb.z * m; acc[7] += eb.w * m;
        }
        const float4* dp = (const float4*)(g_denom + n * 8);
        float4 da = dp[0], db = dp[1];
        acc[0] /= da.x; acc[1] /= da.y; acc[2] /= da.z; acc[3] /= da.w;
        acc[4] /= db.x; acc[5] /= db.y; acc[6] /= db.z; acc[7] /= db.w;
    }
#pragma unroll
    for (int h = 0; h < 8; h++) out[(size_t)n * 1024 + h * 128 + t] = acc[h];
}

// ---------------- launch (k_edge at slot 4 for ncu) ----------------
extern "C" void kernel_launch(void* const* d_in, const int* in_sizes, int n_in,
                              void* d_out, int out_size) {
    const float* node_feats = (const float*)d_in[0];
    const int*   edge_index = (const int*)d_in[1];
    const float* edge_attr  = (const float*)d_in[2];
    const float* edge_type  = (const float*)d_in[3];
    const int*   ntl        = (const int*)d_in[4];
    const float* W_node  = (const float*)d_in[6];
    const float* W_eattr = (const float*)d_in[7];
    const float* W_etype = (const float*)d_in[8];
    const float* W_upd   = (const float*)d_in[9];
    const float* W_attn  = (const float*)d_in[10];
    float* out = (float*)d_out;

    cudaFuncSetAttribute(k_edge, cudaFuncAttributeMaxDynamicSharedMemorySize, EDGE_SMEM_BYTES);
    cudaFuncSetAttribute(k_node, cudaFuncAttributeMaxDynamicSharedMemorySize, NODE_SMEM_BYTES);

    const int TB = 256;
    const int GB_E = (N_EDGES + TB - 1) / TB;

    k_init<<<GB_E, TB>>>(edge_index, W_eattr, W_etype, W_upd, W_attn, W_node);   // 1
    k_hist<<<GB_E, TB>>>(ntl);                                                   // 2
    k_node<<<3 * NBLK64, TB, NODE_SMEM_BYTES>>>(node_feats);                     // 3
    k_edge<<<NTILES, TB, EDGE_SMEM_BYTES>>>(edge_attr, edge_type);               // 4 <- profiled
    k_scanA<<<NSCANB, TB>>>();                                                   // 5
    k_scanB<<<1, TB>>>();                                                        // 6
    k_scanC<<<NSCANB, TB>>>();                                                   // 7
    k_scatter<<<GB_E, TB>>>();                                                   // 8
    k_aggr<<<N_NODES, 128>>>(out);                                               // 9
}

// round 12
// speedup vs baseline: 3.2938x; 1.0101x over previous
#include <cuda_runtime.h>
#include <cuda_bf16.h>
#include <cuda_fp16.h>
#include <math.h>

#define N_NODES 50000
#define N_EDGES 400000
#define SLOPE   0.2f

#define ETILE   64
#define NTILES  (N_EDGES / ETILE)   // 6250, exact
#define NSCANB  196                 // ceil(50000/256)
#define NBLK64  782                 // ceil(50000/64) tiles per type bucket
#define PERM3_CAP (NBLK64 * 64)     // 50048

// ---------------- scratch ----------------
__device__ __align__(16) float g_P[(size_t)N_NODES * 128];
__device__ __align__(16) float g_star[N_NODES * 8];
__device__ __align__(16) float g_ssrc[N_NODES * 8];
__device__ __align__(16) __half g_attrpart_h[(size_t)N_EDGES * 128];
__device__ __align__(16) float g_ex[N_EDGES * 8];
__device__ __align__(16) float g_denom[N_NODES * 8];
__device__ int g_src[N_EDGES], g_tar[N_EDGES];
__device__ int g_deg[N_NODES], g_off[N_NODES + 1], g_cursor[N_NODES], g_perm[N_EDGES];
__device__ int g_bpart[NSCANB], g_bpre[NSCANB];
__device__ int g_perm3[3 * PERM3_CAP];
__device__ int g_tcursor3[3];

// mma-ready packed B fragments: uint4 {bh0, bh1, bl0, bl1} per (n, kstep, fc)
__device__ __align__(16) uint4 gBea[128 * 4 * 4];
__device__ __align__(16) uint4 gBet[128 * 4 * 4];
__device__ __align__(16) uint4 gBup[128 * 8 * 4];
__device__ __align__(16) uint4 gBa [8 * 16 * 4];
__device__ __align__(16) uint4 gBn [3 * 128 * 16 * 4];
__device__ __align__(16) uint4 gBuT[128 * 8 * 4];
__device__ __align__(16) uint4 gBs [16 * 8 * 4];

__device__ __forceinline__ float lrelu(float x) { return x >= 0.f ? x : SLOPE * x; }

__device__ __forceinline__ void splitpack(float x, float y, unsigned& hi, unsigned& lo) {
    __nv_bfloat16 hx = __float2bfloat16(x);
    __nv_bfloat16 hy = __float2bfloat16(y);
    float lx = x - __bfloat162float(hx);
    float ly = y - __bfloat162float(hy);
    __nv_bfloat162 h2 = __halves2bfloat162(hx, hy);
    __nv_bfloat162 l2 = __halves2bfloat162(__float2bfloat16(lx), __float2bfloat16(ly));
    hi = *reinterpret_cast<unsigned*>(&h2);
    lo = *reinterpret_cast<unsigned*>(&l2);
}

__device__ __forceinline__ uint4 pack4(float w0, float w1, float w2, float w3) {
    unsigned h0, l0, h1, l1;
    splitpack(w0, w1, h0, l0);
    splitpack(w2, w3, h1, l1);
    return make_uint4(h0, h1, l0, l1);
}

__device__ __forceinline__ void mma16816(float* c, unsigned a0, unsigned a1, unsigned a2,
                                         unsigned a3, unsigned b0, unsigned b1) {
    asm volatile(
        "mma.sync.aligned.m16n8k16.row.col.f32.bf16.bf16.f32 "
        "{%0,%1,%2,%3}, {%4,%5,%6,%7}, {%8,%9}, {%0,%1,%2,%3};"
        : "+f"(c[0]), "+f"(c[1]), "+f"(c[2]), "+f"(c[3])
        : "r"(a0), "r"(a1), "r"(a2), "r"(a3), "r"(b0), "r"(b1));
}

__device__ __forceinline__ void ldsm4(unsigned& r0, unsigned& r1, unsigned& r2, unsigned& r3,
                                      unsigned addr) {
    asm volatile("ldmatrix.sync.aligned.m8n8.x4.shared.b16 {%0,%1,%2,%3}, [%4];"
                 : "=r"(r0), "=r"(r1), "=r"(r2), "=r"(r3) : "r"(addr));
}

// ---------------- fused init ----------------
__global__ void k_init(const int* __restrict__ eidx,
                       const float* __restrict__ Wea, const float* __restrict__ Wet,
                       const float* __restrict__ Wupd, const float* __restrict__ Wattn,
                       const float* __restrict__ Wn) {
    int i = blockIdx.x * blockDim.x + threadIdx.x;
    if (i < N_EDGES) {
        g_src[i] = eidx[i];
        g_tar[i] = eidx[N_EDGES + i];
    }
    if (i < N_NODES * 8) g_denom[i] = 0.f;
    if (i < N_NODES) g_deg[i] = 0;
    if (i < 3 * PERM3_CAP) g_perm3[i] = -1;
    if (i < 3) g_tcursor3[i] = 0;

    if (i < 2048) {
        int n = i >> 4, kk = (i >> 2) & 3, fc = i & 3;
        int k0 = 2 * (kk * 8 + fc);
        gBea[i] = pack4(Wea[k0 * 128 + n],       Wea[(k0 + 1) * 128 + n],
                        Wea[(k0 + 8) * 128 + n], Wea[(k0 + 9) * 128 + n]);
        gBet[i] = pack4(Wet[k0 * 128 + n],       Wet[(k0 + 1) * 128 + n],
                        Wet[(k0 + 8) * 128 + n], Wet[(k0 + 9) * 128 + n]);
    }
    if (i < 4096) {
        int n = i >> 5, kk = (i >> 2) & 7, fc = i & 3;
        int k0 = 2 * (kk * 8 + fc);
        gBup[i] = pack4(Wupd[(128 + k0) * 128 + n], Wupd[(129 + k0) * 128 + n],
                        Wupd[(136 + k0) * 128 + n], Wupd[(137 + k0) * 128 + n]);
        gBuT[i] = pack4(Wupd[k0 * 128 + n],       Wupd[(k0 + 1) * 128 + n],
                        Wupd[(k0 + 8) * 128 + n], Wupd[(k0 + 9) * 128 + n]);
    }
    if (i < 512) {
        int h = i >> 6, kk = (i >> 2) & 15, fc = i & 3;
        int k0 = 2 * (kk * 8 + fc);
        gBa[i] = pack4(Wattn[(128 + k0) * 8 + h], Wattn[(129 + k0) * 8 + h],
                       Wattn[(136 + k0) * 8 + h], Wattn[(137 + k0) * 8 + h]);
        int n = i >> 5, kk2 = (i >> 2) & 7, fc2 = i & 3;
        int q0 = 2 * (kk2 * 8 + fc2);
        int ro = (n < 8) ? 0 : 384;
        int hh = (n < 8) ? n : n - 8;
        gBs[i] = pack4(Wattn[(ro + q0) * 8 + hh],     Wattn[(ro + q0 + 1) * 8 + hh],
                       Wattn[(ro + q0 + 8) * 8 + hh], Wattn[(ro + q0 + 9) * 8 + hh]);
    }
    if (i < 24576) {
        int tp = i >> 13, r = i & 8191;
        int n = r >> 6, kk = (r >> 2) & 15, fc = r & 3;
        int k0 = 2 * (kk * 8 + fc);
        const float* W = Wn + (size_t)tp * 32768;
        gBn[i] = pack4(W[k0 * 128 + n],       W[(k0 + 1) * 128 + n],
                       W[(k0 + 8) * 128 + n], W[(k0 + 9) * 128 + n]);
    }
}

__global__ void k_hist(const int* __restrict__ ntl) {
    int i = blockIdx.x * blockDim.x + threadIdx.x;
    if (i < N_EDGES) atomicAdd(&g_deg[g_src[i]], 1);
    if (i < N_NODES) {
        int tp = ntl[i];
        int p = atomicAdd(&g_tcursor3[tp], 1);
        g_perm3[tp * PERM3_CAP + p] = i;
    }
}

// ---------------- parallel scan ----------------
__global__ void k_scanA() {
    __shared__ int sh[8];
    int b = blockIdx.x, t = threadIdx.x, i = b * 256 + t;
    int v = (i < N_NODES) ? g_deg[i] : 0;
#pragma unroll
    for (int d = 16; d; d >>= 1) v += __shfl_down_sync(~0u, v, d);
    if ((t & 31) == 0) sh[t >> 5] = v;
    __syncthreads();
    if (t < 8) {
        int s = sh[t];
#pragma unroll
        for (int d = 4; d; d >>= 1) s += __shfl_down_sync(0xff, s, d);
        if (t == 0) g_bpart[b] = s;
    }
}

__global__ void k_scanB() {
    int t = threadIdx.x, lane = t & 31, wp = t >> 5;
    int v = (t < NSCANB) ? g_bpart[t] : 0;
    int inc = v;
#pragma unroll
    for (int d = 1; d < 32; d <<= 1) {
        int n = __shfl_up_sync(~0u, inc, d);
        if (lane >= d) inc += n;
    }
    __shared__ int wsum[8];
    if (lane == 31) wsum[wp] = inc;
    __syncthreads();
    if (t == 0) {
        int r = 0;
        for (int q = 0; q < 8; q++) { int x = wsum[q]; wsum[q] = r; r += x; }
    }
    __syncthreads();
    if (t < NSCANB) g_bpre[t] = inc - v + wsum[wp];
    if (t == 0) g_off[N_NODES] = N_EDGES;
}

__global__ void k_scanC() {
    int b = blockIdx.x, t = threadIdx.x, lane = t & 31, wp = t >> 5;
    int i = b * 256 + t;
    int v = (i < N_NODES) ? g_deg[i] : 0;
    int inc = v;
#pragma unroll
    for (int d = 1; d < 32; d <<= 1) {
        int n = __shfl_up_sync(~0u, inc, d);
        if (lane >= d) inc += n;
    }
    __shared__ int wsum[8];
    if (lane == 31) wsum[wp] = inc;
    __syncthreads();
    if (t == 0) {
        int r = 0;
        for (int q = 0; q < 8; q++) { int x = wsum[q]; wsum[q] = r; r += x; }
    }
    __syncthreads();
    int off = g_bpre[b] + inc - v + wsum[wp];
    if (i < N_NODES) { g_off[i] = off; g_cursor[i] = off; }
}

__global__ void k_scatter() {
    int i = blockIdx.x * blockDim.x + threadIdx.x;
    if (i < N_EDGES) {
        int p = atomicAdd(&g_cursor[g_src[i]], 1);
        g_perm[p] = i;
    }
}

// ---------------- gemm fragment helper (ldmatrix A loads) ----------------
template <int KSTEPS, int STRIDE>
__device__ __forceinline__ void gemm_frag2(const unsigned* xh, const unsigned* xl,
                                           const uint4* __restrict__ B,
                                           int rb, int nh, int lane, float acc[2][4][4]) {
    int fr = lane >> 2, fc = lane & 3;
    int lrow = lane & 15, lhalf = lane >> 4;
    unsigned bh = (unsigned)__cvta_generic_to_shared(xh) + ((rb + lrow) * STRIDE + lhalf * 4) * 4;
    unsigned bl = (unsigned)__cvta_generic_to_shared(xl) + ((rb + lrow) * STRIDE + lhalf * 4) * 4;
    unsigned ch = bh + 32 * STRIDE * 4;
    unsigned cl = bl + 32 * STRIDE * 4;
#pragma unroll
    for (int kk = 0; kk < KSTEPS; kk++) {
        unsigned ah0, ah1, ah2, ah3, al0, al1, al2, al3;
        unsigned ch0, ch1, ch2, ch3, cl0, cl1, cl2, cl3;
        ldsm4(ah0, ah1, ah2, ah3, bh + kk * 32);
        ldsm4(al0, al1, al2, al3, bl + kk * 32);
        ldsm4(ch0, ch1, ch2, ch3, ch + kk * 32);
        ldsm4(cl0, cl1, cl2, cl3, cl + kk * 32);
#pragma unroll
        for (int j = 0; j < 4; j++) {
            int n = nh * 32 + j * 8 + fr;
            uint4 b = B[(n * KSTEPS + kk) * 4 + fc];
            mma16816(acc[0][j], ah0, ah1, ah2, ah3, b.x, b.y);
            mma16816(acc[0][j], ah0, ah1, ah2, ah3, b.z, b.w);
            mma16816(acc[0][j], al0, al1, al2, al3, b.x, b.y);
            mma16816(acc[1][j], ch0, ch1, ch2, ch3, b.x, b.y);
            mma16816(acc[1][j], ch0, ch1, ch2, ch3, b.z, b.w);
            mma16816(acc[1][j], cl0, cl1, cl2, cl3, b.x, b.y);
        }
    }
}

// ---------------- tensor-core node kernel (E aliases X -> 3 CTAs/SM) ----------------
#define N_XHI 0
#define N_XLO 8448
#define N_EHI 0
#define N_ELO 4352
#define NODE_SMEM_U32 16896
#define NODE_SMEM_BYTES (NODE_SMEM_U32 * 4)

__global__ void __launch_bounds__(256)
k_node(const float* __restrict__ x) {
    extern __shared__ unsigned su[];
    __shared__ int sNid[64];
    unsigned* Xhi = su + N_XHI;
    unsigned* Xlo = su + N_XLO;
    unsigned* Ehi = su + N_EHI;
    unsigned* Elo = su + N_ELO;

    int t = threadIdx.x, lane = t & 31, w = t >> 5;
    int b = blockIdx.x;
    int tp = b / NBLK64;
    int base = tp * PERM3_CAP + (b - tp * NBLK64) * 64;

    if (g_perm3[base] < 0) return;
    if (t < 64) sNid[t] = g_perm3[base + t];
    __syncthreads();

    {
        int row = t >> 2, seg = t & 3;
        int nid = sNid[row];
        const float4* src = (const float4*)(x + (size_t)(nid < 0 ? 0 : nid) * 256 + seg * 64);
        unsigned* xh = Xhi + row * 132 + seg * 32;
        unsigned* xl = Xlo + row * 132 + seg * 32;
#pragma unroll
        for (int p = 0; p < 16; p++) {
            float4 v = (nid >= 0) ? src[p] : make_float4(0.f, 0.f, 0.f, 0.f);
            unsigned h0, l0, h1, l1;
            splitpack(v.x, v.y, h0, l0);
            splitpack(v.z, v.w, h1, l1);
            xh[p * 2] = h0; xh[p * 2 + 1] = h1;
            xl[p * 2] = l0; xl[p * 2 + 1] = l1;
        }
    }
    __syncthreads();

    int nh = w & 3, rt = w >> 2;
    int rb = rt * 16;
    int fr = lane >> 2, fc = lane & 3;

    float acc[2][4][4];

#pragma unroll
    for (int ti = 0; ti < 2; ti++)
#pragma unroll
        for (int j = 0; j < 4; j++)
#pragma unroll
            for (int c = 0; c < 4; c++) acc[ti][j][c] = 0.f;
    gemm_frag2<16, 132>(Xhi, Xlo, gBn + tp * 8192, rb, nh, lane, acc);
    __syncthreads();
#pragma unroll
    for (int ti = 0; ti < 2; ti++)
#pragma unroll
        for (int j = 0; j < 4; j++) {
            int colu = nh * 16 + j * 4 + fc;
            int r = rb + fr + ti * 32;
            unsigned h, l;
            splitpack(acc[ti][j][0], acc[ti][j][1], h, l);
            Ehi[r * 68 + colu] = h;
            Elo[r * 68 + colu] = l;
            splitpack(acc[ti][j][2], acc[ti][j][3], h, l);
            Ehi[(r + 8) * 68 + colu] = h;
            Elo[(r + 8) * 68 + colu] = l;
        }
    __syncthreads();

#pragma unroll
    for (int ti = 0; ti < 2; ti++)
#pragma unroll
        for (int j = 0; j < 4; j++)
#pragma unroll
            for (int c = 0; c < 4; c++) acc[ti][j][c] = 0.f;
    gemm_frag2<8, 68>(Ehi, Elo, gBuT, rb, nh, lane, acc);
#pragma unroll
    for (int ti = 0; ti < 2; ti++)
#pragma unroll
        for (int j = 0; j < 4; j++) {
            int n0 = nh * 32 + j * 8 + fc * 2;
            int r = rb + fr + ti * 32;
            int n1 = sNid[r], n2 = sNid[r + 8];
            if (n1 >= 0)
                *(float2*)(g_P + (size_t)n1 * 128 + n0) = make_float2(acc[ti][j][0], acc[ti][j][1]);
            if (n2 >= 0)
                *(float2*)(g_P + (size_t)n2 * 128 + n0) = make_float2(acc[ti][j][2], acc[ti][j][3]);
        }

    if (w < 4) {
        int srb = w * 16;
        float sa[2][4];
#pragma unroll
        for (int j = 0; j < 2; j++)
#pragma unroll
            for (int c = 0; c < 4; c++) sa[j][c] = 0.f;
#pragma unroll
        for (int kk = 0; kk < 8; kk++) {
            int o0 = (srb + fr) * 68 + kk * 8 + fc;
            int o1 = o0 + 8 * 68;
            unsigned ah0 = Ehi[o0], ah1 = Ehi[o1], ah2 = Ehi[o0 + 4], ah3 = Ehi[o1 + 4];
            unsigned al0 = Elo[o0], al1 = Elo[o1], al2 = Elo[o0 + 4], al3 = Elo[o1 + 4];
#pragma unroll
            for (int j = 0; j < 2; j++) {
                int n = j * 8 + fr;
                uint4 bq = gBs[(n * 8 + kk) * 4 + fc];
                mma16816(sa[j], ah0, ah1, ah2, ah3, bq.x, bq.y);
                mma16816(sa[j], ah0, ah1, ah2, ah3, bq.z, bq.w);
                mma16816(sa[j], al0, al1, al2, al3, bq.x, bq.y);
            }
        }
#pragma unroll
        for (int j = 0; j < 2; j++)
#pragma unroll
            for (int q = 0; q < 4; q++) {
                int row = srb + fr + (q >> 1) * 8;
                int nid = sNid[row];
                int h = fc * 2 + (q & 1);
                if (nid >= 0) {
                    if (j == 0) g_star[nid * 8 + h] = sa[j][q];
                    else        g_ssrc[nid * 8 + h] = sa[j][q];
                }
            }
    }
}

// ---------------- tensor-core edge kernel (TLO aliases X -> 3 CTAs/SM) ----------------
#define XHI 0
#define XLO 2304
#define AHI 4608
#define ALO 8960
#define THI 13312
#define TLO 0
#define EDGE_SMEM_U32 17664
#define EDGE_SMEM_BYTES (EDGE_SMEM_U32 * 4)

__global__ void __launch_bounds__(256)
k_edge(const float* __restrict__ eattr, const float* __restrict__ etype) {
    extern __shared__ unsigned su[];
    __shared__ int sSrc[ETILE], sTar[ETILE];

    int t = threadIdx.x, lane = t & 31, w = t >> 5;
    int nh = w & 3, rt = w >> 2;
    int rb = rt * 16;
    int fr = lane >> 2, fc = lane & 3;
    int e0 = blockIdx.x * ETILE;

    {
        int row = t >> 2, cg = (t & 3) * 16;
        const float4* src = (const float4*)(eattr + (size_t)(e0 + row) * 64 + cg);
        unsigned* xh = su + XHI + row * 36 + cg / 2;
        unsigned* xl = su + XLO + row * 36 + cg / 2;
#pragma unroll
        for (int p = 0; p < 4; p++) {
            float4 v = src[p];
            unsigned h0, l0, h1, l1;
            splitpack(v.x, v.y, h0, l0);
            splitpack(v.z, v.w, h1, l1);
            xh[p * 2] = h0; xh[p * 2 + 1] = h1;
            xl[p * 2] = l0; xl[p * 2 + 1] = l1;
        }
    }
    if (t < ETILE) sSrc[t] = g_src[e0 + t];
    else if (t < 2 * ETILE) sTar[t - ETILE] = g_tar[e0 + t - ETILE];
    __syncthreads();

    float acc[2][4][4];

    // ---- phase A ----
#pragma unroll
    for (int ti = 0; ti < 2; ti++)
#pragma unroll
        for (int j = 0; j < 4; j++)
#pragma unroll
            for (int c = 0; c < 4; c++) acc[ti][j][c] = 0.f;
    gemm_frag2<4, 36>(su + XHI, su + XLO, gBea, rb, nh, lane, acc);
#pragma unroll
    for (int ti = 0; ti < 2; ti++)
#pragma unroll
        for (int j = 0; j < 4; j++) {
            int colu = nh * 16 + j * 4 + fc;
            int r = rb + fr + ti * 32;
            unsigned h, l;
            splitpack(lrelu(acc[ti][j][0]), lrelu(acc[ti][j][1]), h, l);
            su[AHI + r * 68 + colu] = h;
            su[ALO + r * 68 + colu] = l;
            splitpack(lrelu(acc[ti][j][2]), lrelu(acc[ti][j][3]), h, l);
            su[AHI + (r + 8) * 68 + colu] = h;
            su[ALO + (r + 8) * 68 + colu] = l;
        }
    __syncthreads();

    {
        int row = t >> 2, cg = (t & 3) * 16;
        const float4* src = (const float4*)(etype + (size_t)(e0 + row) * 64 + cg);
        unsigned* xh = su + XHI + row * 36 + cg / 2;
        unsigned* xl = su + XLO + row * 36 + cg / 2;
#pragma unroll
        for (int p = 0; p < 4; p++) {
            float4 v = src[p];
            unsigned h0, l0, h1, l1;
            splitpack(v.x, v.y, h0, l0);
            splitpack(v.z, v.w, h1, l1);
            xh[p * 2] = h0; xh[p * 2 + 1] = h1;
            xl[p * 2] = l0; xl[p * 2 + 1] = l1;
        }
    }
    __syncthreads();

    // ---- phase T (TLO aliases X: sync after gemm reads) ----
#pragma unroll
    for (int ti = 0; ti < 2; ti++)
#pragma unroll
        for (int j = 0; j < 4; j++)
#pragma unroll
            for (int c = 0; c < 4; c++) acc[ti][j][c] = 0.f;
    gemm_frag2<4, 36>(su + XHI, su + XLO, gBet, rb, nh, lane, acc);
    __syncthreads();
#pragma unroll
    for (int ti = 0; ti < 2; ti++)
#pragma unroll
        for (int j = 0; j < 4; j++) {
            int colu = nh * 16 + j * 4 + fc;
            int r = rb + fr + ti * 32;
            unsigned h, l;
            splitpack(lrelu(acc[ti][j][0]), lrelu(acc[ti][j][1]), h, l);
            su[THI + r * 68 + colu] = h;
            su[TLO + r * 68 + colu] = l;
            splitpack(lrelu(acc[ti][j][2]), lrelu(acc[ti][j][3]), h, l);
            su[THI + (r + 8) * 68 + colu] = h;
            su[TLO + (r + 8) * 68 + colu] = l;
        }
    __syncthreads();

    // ---- scores (warps 0-3) ----
    if (w < 4) {
        int srb = w * 16;
        float sacc[4] = {0.f, 0.f, 0.f, 0.f};
#pragma unroll
        for (int kk = 0; kk < 16; kk++) {
            int base_h = (kk < 8) ? AHI : THI;
            int base_l = (kk < 8) ? ALO : TLO;
            int kx = kk & 7;
            int o0 = (srb + fr) * 68 + kx * 8 + fc;
            int o1 = (srb + fr + 8) * 68 + kx * 8 + fc;
            unsigned ah0 = su[base_h + o0], ah1 = su[base_h + o1];
            unsigned ah2 = su[base_h + o0 + 4], ah3 = su[base_h + o1 + 4];
            unsigned al0 = su[base_l + o0], al1 = su[base_l + o1];
            unsigned al2 = su[base_l + o0 + 4], al3 = su[base_l + o1 + 4];
            uint4 bq = gBa[(fr * 16 + kk) * 4 + fc];
            mma16816(sacc, ah0, ah1, ah2, ah3, bq.x, bq.y);
            mma16816(sacc, ah0, ah1, ah2, ah3, bq.z, bq.w);
            mma16816(sacc, al0, al1, al2, al3, bq.x, bq.y);
        }
        int h0 = fc * 2;
#pragma unroll
        for (int q = 0; q < 4; q++) {
            int row = srb + fr + (q >> 1) * 8;
            int h = h0 + (q & 1);
            int sr = sSrc[row], tg = sTar[row];
            float sc = sacc[q] + g_star[tg * 8 + h] + g_ssrc[sr * 8 + h];
            sc = lrelu(sc);
            float ex = expf(sc);
            g_ex[(e0 + row) * 8 + h] = ex;
            atomicAdd(&g_denom[sr * 8 + h], ex);
        }
    }

    // ---- phase P (fp16 attrpart output) ----
#pragma unroll
    for (int ti = 0; ti < 2; ti++)
#pragma unroll
        for (int j = 0; j < 4; j++)
#pragma unroll
            for (int c = 0; c < 4; c++) acc[ti][j][c] = 0.f;
    gemm_frag2<8, 68>(su + AHI, su + ALO, gBup, rb, nh, lane, acc);
#pragma unroll
    for (int ti = 0; ti < 2; ti++)
#pragma unroll
        for (int j = 0; j < 4; j++) {
            int n0 = nh * 32 + j * 8 + fc * 2;
            int r = rb + fr + ti * 32;
            *(__half2*)(g_attrpart_h + (size_t)(e0 + r) * 128 + n0) =
                __floats2half2_rn(acc[ti][j][0], acc[ti][j][1]);
            *(__half2*)(g_attrpart_h + (size_t)(e0 + r + 8) * 128 + n0) =
                __floats2half2_rn(acc[ti][j][2], acc[ti][j][3]);
        }
}

// ---------------- aggregation (fp16 attrpart, perm prefetch) ----------------
__global__ void k_aggr(float* __restrict__ out) {
    int n = blockIdx.x;
    int t = threadIdx.x;
    int s = g_off[n], e_end = g_off[n + 1];
    float p = g_P[(size_t)n * 128 + t];
    float acc[8];
#pragma unroll
    for (int h = 0; h < 8; h++) acc[h] = 0.f;
    if (e_end > s) {
        int e = g_perm[s];
        for (int j = s; j < e_end; j++) {
            int e_next = (j + 1 < e_end) ? g_perm[j + 1] : 0;
            float m = lrelu(p + __half2float(g_attrpart_h[(size_t)e * 128 + t]));
            const float4* xp = (const float4*)(g_ex + e * 8);
            float4 ea = xp[0], eb = xp[1];
            acc[0] += ea.x * m; acc[1] += ea.y * m; acc[2] += ea.z * m; acc[3] += ea.w * m;
            acc[4] += eb.x * m; acc[5] += eb.y * m; acc[6] += eb.z * m; acc[7] += eb.w * m;
            e = e_next;
        }
        const float4* dp = (const float4*)(g_denom + n * 8);
        float4 da = dp[0], db = dp[1];
        acc[0] /= da.x; acc[1] /= da.y; acc[2] /= da.z; acc[3] /= da.w;
        acc[4] /= db.x; acc[5] /= db.y; acc[6] /= db.z; acc[7] /= db.w;
    }
#pragma unroll
    for (int h = 0; h < 8; h++) out[(size_t)n * 1024 + h * 128 + t] = acc[h];
}

// ---------------- launch (k_edge at slot 4 for ncu) ----------------
extern "C" void kernel_launch(void* const* d_in, const int* in_sizes, int n_in,
                              void* d_out, int out_size) {
    const float* node_feats = (const float*)d_in[0];
    const int*   edge_index = (const int*)d_in[1];
    const float* edge_attr  = (const float*)d_in[2];
    const float* edge_type  = (const float*)d_in[3];
    const int*   ntl        = (const int*)d_in[4];
    const float* W_node  = (const float*)d_in[6];
    const float* W_eattr = (const float*)d_in[7];
    const float* W_etype = (const float*)d_in[8];
    const float* W_upd   = (const float*)d_in[9];
    const float* W_attn  = (const float*)d_in[10];
    float* out = (float*)d_out;

    cudaFuncSetAttribute(k_edge, cudaFuncAttributeMaxDynamicSharedMemorySize, EDGE_SMEM_BYTES);
    cudaFuncSetAttribute(k_node, cudaFuncAttributeMaxDynamicSharedMemorySize, NODE_SMEM_BYTES);

    const int TB = 256;
    const int GB_E = (N_EDGES + TB - 1) / TB;

    k_init<<<GB_E, TB>>>(edge_index, W_eattr, W_etype, W_upd, W_attn, W_node);   // 1
    k_hist<<<GB_E, TB>>>(ntl);                                                   // 2
    k_node<<<3 * NBLK64, TB, NODE_SMEM_BYTES>>>(node_feats);                     // 3
    k_edge<<<NTILES, TB, EDGE_SMEM_BYTES>>>(edge_attr, edge_type);               // 4 <- profiled
    k_scanA<<<NSCANB, TB>>>();                                                   // 5
    k_scanB<<<1, TB>>>();                                                        // 6
    k_scanC<<<NSCANB, TB>>>();                                                   // 7
    k_scatter<<<GB_E, TB>>>();                                                   // 8
    k_aggr<<<N_NODES, 128>>>(out);                                               // 9
}

// round 13
// speedup vs baseline: 3.4630x; 1.0514x over previous
#include <cuda_runtime.h>
#include <cuda_bf16.h>
#include <cuda_fp16.h>
#include <math.h>

#define N_NODES 50000
#define N_EDGES 400000
#define SLOPE   0.2f

#define ETILE   64
#define NTILES  (N_EDGES / ETILE)   // 6250, exact
#define NSCANB  196                 // ceil(50000/256)
#define NBLK64  782                 // ceil(50000/64) tiles per type bucket
#define PERM3_CAP (NBLK64 * 64)     // 50048

// ---------------- scratch ----------------
__device__ __align__(16) float g_P[(size_t)N_NODES * 128];
__device__ __align__(16) float g_star[N_NODES * 8];
__device__ __align__(16) float g_ssrc[N_NODES * 8];
__device__ __align__(16) __half g_attrpart_h[(size_t)N_EDGES * 128];  // CSR-ordered
__device__ __align__(16) float g_ex[N_EDGES * 8];                     // CSR-ordered
__device__ __align__(16) float g_denom[N_NODES * 8];
__device__ int g_src[N_EDGES], g_tar[N_EDGES];
__device__ int g_deg[N_NODES], g_off[N_NODES + 1], g_cursor[N_NODES];
__device__ int g_bpart[NSCANB], g_bpre[NSCANB];
__device__ int g_perm3[3 * PERM3_CAP];
__device__ int g_tcursor3[3];

// mma-ready packed B fragments: uint4 {bh0, bh1, bl0, bl1} per (n, kstep, fc)
__device__ __align__(16) uint4 gBea[128 * 4 * 4];
__device__ __align__(16) uint4 gBet[128 * 4 * 4];
__device__ __align__(16) uint4 gBup[128 * 8 * 4];
__device__ __align__(16) uint4 gBa [8 * 16 * 4];
__device__ __align__(16) uint4 gBn [3 * 128 * 16 * 4];
__device__ __align__(16) uint4 gBuT[128 * 8 * 4];
__device__ __align__(16) uint4 gBs [16 * 8 * 4];

__device__ __forceinline__ float lrelu(float x) { return x >= 0.f ? x : SLOPE * x; }

__device__ __forceinline__ void splitpack(float x, float y, unsigned& hi, unsigned& lo) {
    __nv_bfloat16 hx = __float2bfloat16(x);
    __nv_bfloat16 hy = __float2bfloat16(y);
    float lx = x - __bfloat162float(hx);
    float ly = y - __bfloat162float(hy);
    __nv_bfloat162 h2 = __halves2bfloat162(hx, hy);
    __nv_bfloat162 l2 = __halves2bfloat162(__float2bfloat16(lx), __float2bfloat16(ly));
    hi = *reinterpret_cast<unsigned*>(&h2);
    lo = *reinterpret_cast<unsigned*>(&l2);
}

__device__ __forceinline__ uint4 pack4(float w0, float w1, float w2, float w3) {
    unsigned h0, l0, h1, l1;
    splitpack(w0, w1, h0, l0);
    splitpack(w2, w3, h1, l1);
    return make_uint4(h0, h1, l0, l1);
}

__device__ __forceinline__ void mma16816(float* c, unsigned a0, unsigned a1, unsigned a2,
                                         unsigned a3, unsigned b0, unsigned b1) {
    asm volatile(
        "mma.sync.aligned.m16n8k16.row.col.f32.bf16.bf16.f32 "
        "{%0,%1,%2,%3}, {%4,%5,%6,%7}, {%8,%9}, {%0,%1,%2,%3};"
        : "+f"(c[0]), "+f"(c[1]), "+f"(c[2]), "+f"(c[3])
        : "r"(a0), "r"(a1), "r"(a2), "r"(a3), "r"(b0), "r"(b1));
}

__device__ __forceinline__ void ldsm4(unsigned& r0, unsigned& r1, unsigned& r2, unsigned& r3,
                                      unsigned addr) {
    asm volatile("ldmatrix.sync.aligned.m8n8.x4.shared.b16 {%0,%1,%2,%3}, [%4];"
                 : "=r"(r0), "=r"(r1), "=r"(r2), "=r"(r3) : "r"(addr));
}

// ---------------- fused init ----------------
__global__ void k_init(const int* __restrict__ eidx,
                       const float* __restrict__ Wea, const float* __restrict__ Wet,
                       const float* __restrict__ Wupd, const float* __restrict__ Wattn,
                       const float* __restrict__ Wn) {
    int i = blockIdx.x * blockDim.x + threadIdx.x;
    if (i < N_EDGES) {
        g_src[i] = eidx[i];
        g_tar[i] = eidx[N_EDGES + i];
    }
    if (i < N_NODES * 8) g_denom[i] = 0.f;
    if (i < N_NODES) g_deg[i] = 0;
    if (i < 3 * PERM3_CAP) g_perm3[i] = -1;
    if (i < 3) g_tcursor3[i] = 0;

    if (i < 2048) {
        int n = i >> 4, kk = (i >> 2) & 3, fc = i & 3;
        int k0 = 2 * (kk * 8 + fc);
        gBea[i] = pack4(Wea[k0 * 128 + n],       Wea[(k0 + 1) * 128 + n],
                        Wea[(k0 + 8) * 128 + n], Wea[(k0 + 9) * 128 + n]);
        gBet[i] = pack4(Wet[k0 * 128 + n],       Wet[(k0 + 1) * 128 + n],
                        Wet[(k0 + 8) * 128 + n], Wet[(k0 + 9) * 128 + n]);
    }
    if (i < 4096) {
        int n = i >> 5, kk = (i >> 2) & 7, fc = i & 3;
        int k0 = 2 * (kk * 8 + fc);
        gBup[i] = pack4(Wupd[(128 + k0) * 128 + n], Wupd[(129 + k0) * 128 + n],
                        Wupd[(136 + k0) * 128 + n], Wupd[(137 + k0) * 128 + n]);
        gBuT[i] = pack4(Wupd[k0 * 128 + n],       Wupd[(k0 + 1) * 128 + n],
                        Wupd[(k0 + 8) * 128 + n], Wupd[(k0 + 9) * 128 + n]);
    }
    if (i < 512) {
        int h = i >> 6, kk = (i >> 2) & 15, fc = i & 3;
        int k0 = 2 * (kk * 8 + fc);
        gBa[i] = pack4(Wattn[(128 + k0) * 8 + h], Wattn[(129 + k0) * 8 + h],
                       Wattn[(136 + k0) * 8 + h], Wattn[(137 + k0) * 8 + h]);
        int n = i >> 5, kk2 = (i >> 2) & 7, fc2 = i & 3;
        int q0 = 2 * (kk2 * 8 + fc2);
        int ro = (n < 8) ? 0 : 384;
        int hh = (n < 8) ? n : n - 8;
        gBs[i] = pack4(Wattn[(ro + q0) * 8 + hh],     Wattn[(ro + q0 + 1) * 8 + hh],
                       Wattn[(ro + q0 + 8) * 8 + hh], Wattn[(ro + q0 + 9) * 8 + hh]);
    }
    if (i < 24576) {
        int tp = i >> 13, r = i & 8191;
        int n = r >> 6, kk = (r >> 2) & 15, fc = r & 3;
        int k0 = 2 * (kk * 8 + fc);
        const float* W = Wn + (size_t)tp * 32768;
        gBn[i] = pack4(W[k0 * 128 + n],       W[(k0 + 1) * 128 + n],
                       W[(k0 + 8) * 128 + n], W[(k0 + 9) * 128 + n]);
    }
}

__global__ void k_hist(const int* __restrict__ ntl) {
    int i = blockIdx.x * blockDim.x + threadIdx.x;
    if (i < N_EDGES) atomicAdd(&g_deg[g_src[i]], 1);
    if (i < N_NODES) {
        int tp = ntl[i];
        int p = atomicAdd(&g_tcursor3[tp], 1);
        g_perm3[tp * PERM3_CAP + p] = i;
    }
}

// ---------------- parallel scan ----------------
__global__ void k_scanA() {
    __shared__ int sh[8];
    int b = blockIdx.x, t = threadIdx.x, i = b * 256 + t;
    int v = (i < N_NODES) ? g_deg[i] : 0;
#pragma unroll
    for (int d = 16; d; d >>= 1) v += __shfl_down_sync(~0u, v, d);
    if ((t & 31) == 0) sh[t >> 5] = v;
    __syncthreads();
    if (t < 8) {
        int s = sh[t];
#pragma unroll
        for (int d = 4; d; d >>= 1) s += __shfl_down_sync(0xff, s, d);
        if (t == 0) g_bpart[b] = s;
    }
}

__global__ void k_scanB() {
    int t = threadIdx.x, lane = t & 31, wp = t >> 5;
    int v = (t < NSCANB) ? g_bpart[t] : 0;
    int inc = v;
#pragma unroll
    for (int d = 1; d < 32; d <<= 1) {
        int n = __shfl_up_sync(~0u, inc, d);
        if (lane >= d) inc += n;
    }
    __shared__ int wsum[8];
    if (lane == 31) wsum[wp] = inc;
    __syncthreads();
    if (t == 0) {
        int r = 0;
        for (int q = 0; q < 8; q++) { int x = wsum[q]; wsum[q] = r; r += x; }
    }
    __syncthreads();
    if (t < NSCANB) g_bpre[t] = inc - v + wsum[wp];
    if (t == 0) g_off[N_NODES] = N_EDGES;
}

__global__ void k_scanC() {
    int b = blockIdx.x, t = threadIdx.x, lane = t & 31, wp = t >> 5;
    int i = b * 256 + t;
    int v = (i < N_NODES) ? g_deg[i] : 0;
    int inc = v;
#pragma unroll
    for (int d = 1; d < 32; d <<= 1) {
        int n = __shfl_up_sync(~0u, inc, d);
        if (lane >= d) inc += n;
    }
    __shared__ int wsum[8];
    if (lane == 31) wsum[wp] = inc;
    __syncthreads();
    if (t == 0) {
        int r = 0;
        for (int q = 0; q < 8; q++) { int x = wsum[q]; wsum[q] = r; r += x; }
    }
    __syncthreads();
    int off = g_bpre[b] + inc - v + wsum[wp];
    if (i < N_NODES) { g_off[i] = off; g_cursor[i] = off; }
}

// ---------------- gemm fragment helper (ldmatrix A loads) ----------------
template <int KSTEPS, int STRIDE>
__device__ __forceinline__ void gemm_frag2(const unsigned* xh, const unsigned* xl,
                                           const uint4* __restrict__ B,
                                           int rb, int nh, int lane, float acc[2][4][4]) {
    int fr = lane >> 2, fc = lane & 3;
    int lrow = lane & 15, lhalf = lane >> 4;
    unsigned bh = (unsigned)__cvta_generic_to_shared(xh) + ((rb + lrow) * STRIDE + lhalf * 4) * 4;
    unsigned bl = (unsigned)__cvta_generic_to_shared(xl) + ((rb + lrow) * STRIDE + lhalf * 4) * 4;
    unsigned ch = bh + 32 * STRIDE * 4;
    unsigned cl = bl + 32 * STRIDE * 4;
#pragma unroll
    for (int kk = 0; kk < KSTEPS; kk++) {
        unsigned ah0, ah1, ah2, ah3, al0, al1, al2, al3;
        unsigned ch0, ch1, ch2, ch3, cl0, cl1, cl2, cl3;
        ldsm4(ah0, ah1, ah2, ah3, bh + kk * 32);
        ldsm4(al0, al1, al2, al3, bl + kk * 32);
        ldsm4(ch0, ch1, ch2, ch3, ch + kk * 32);
        ldsm4(cl0, cl1, cl2, cl3, cl + kk * 32);
#pragma unroll
        for (int j = 0; j < 4; j++) {
            int n = nh * 32 + j * 8 + fr;
            uint4 b = B[(n * KSTEPS + kk) * 4 + fc];
            mma16816(acc[0][j], ah0, ah1, ah2, ah3, b.x, b.y);
            mma16816(acc[0][j], ah0, ah1, ah2, ah3, b.z, b.w);
            mma16816(acc[0][j], al0, al1, al2, al3, b.x, b.y);
            mma16816(acc[1][j], ch0, ch1, ch2, ch3, b.x, b.y);
            mma16816(acc[1][j], ch0, ch1, ch2, ch3, b.z, b.w);
            mma16816(acc[1][j], cl0, cl1, cl2, cl3, b.x, b.y);
        }
    }
}

// ---------------- tensor-core node kernel ----------------
#define N_XHI 0
#define N_XLO 8448
#define N_EHI 0
#define N_ELO 4352
#define NODE_SMEM_U32 16896
#define NODE_SMEM_BYTES (NODE_SMEM_U32 * 4)

__global__ void __launch_bounds__(256)
k_node(const float* __restrict__ x) {
    extern __shared__ unsigned su[];
    __shared__ int sNid[64];
    unsigned* Xhi = su + N_XHI;
    unsigned* Xlo = su + N_XLO;
    unsigned* Ehi = su + N_EHI;
    unsigned* Elo = su + N_ELO;

    int t = threadIdx.x, lane = t & 31, w = t >> 5;
    int b = blockIdx.x;
    int tp = b / NBLK64;
    int base = tp * PERM3_CAP + (b - tp * NBLK64) * 64;

    if (g_perm3[base] < 0) return;
    if (t < 64) sNid[t] = g_perm3[base + t];
    __syncthreads();

    {
        int row = t >> 2, seg = t & 3;
        int nid = sNid[row];
        const float4* src = (const float4*)(x + (size_t)(nid < 0 ? 0 : nid) * 256 + seg * 64);
        unsigned* xh = Xhi + row * 132 + seg * 32;
        unsigned* xl = Xlo + row * 132 + seg * 32;
#pragma unroll
        for (int p = 0; p < 16; p++) {
            float4 v = (nid >= 0) ? src[p] : make_float4(0.f, 0.f, 0.f, 0.f);
            unsigned h0, l0, h1, l1;
            splitpack(v.x, v.y, h0, l0);
            splitpack(v.z, v.w, h1, l1);
            xh[p * 2] = h0; xh[p * 2 + 1] = h1;
            xl[p * 2] = l0; xl[p * 2 + 1] = l1;
        }
    }
    __syncthreads();

    int nh = w & 3, rt = w >> 2;
    int rb = rt * 16;
    int fr = lane >> 2, fc = lane & 3;

    float acc[2][4][4];

#pragma unroll
    for (int ti = 0; ti < 2; ti++)
#pragma unroll
        for (int j = 0; j < 4; j++)
#pragma unroll
            for (int c = 0; c < 4; c++) acc[ti][j][c] = 0.f;
    gemm_frag2<16, 132>(Xhi, Xlo, gBn + tp * 8192, rb, nh, lane, acc);
    __syncthreads();
#pragma unroll
    for (int ti = 0; ti < 2; ti++)
#pragma unroll
        for (int j = 0; j < 4; j++) {
            int colu = nh * 16 + j * 4 + fc;
            int r = rb + fr + ti * 32;
            unsigned h, l;
            splitpack(acc[ti][j][0], acc[ti][j][1], h, l);
            Ehi[r * 68 + colu] = h;
            Elo[r * 68 + colu] = l;
            splitpack(acc[ti][j][2], acc[ti][j][3], h, l);
            Ehi[(r + 8) * 68 + colu] = h;
            Elo[(r + 8) * 68 + colu] = l;
        }
    __syncthreads();

#pragma unroll
    for (int ti = 0; ti < 2; ti++)
#pragma unroll
        for (int j = 0; j < 4; j++)
#pragma unroll
            for (int c = 0; c < 4; c++) acc[ti][j][c] = 0.f;
    gemm_frag2<8, 68>(Ehi, Elo, gBuT, rb, nh, lane, acc);
#pragma unroll
    for (int ti = 0; ti < 2; ti++)
#pragma unroll
        for (int j = 0; j < 4; j++) {
            int n0 = nh * 32 + j * 8 + fc * 2;
            int r = rb + fr + ti * 32;
            int n1 = sNid[r], n2 = sNid[r + 8];
            if (n1 >= 0)
                *(float2*)(g_P + (size_t)n1 * 128 + n0) = make_float2(acc[ti][j][0], acc[ti][j][1]);
            if (n2 >= 0)
                *(float2*)(g_P + (size_t)n2 * 128 + n0) = make_float2(acc[ti][j][2], acc[ti][j][3]);
        }

    if (w < 4) {
        int srb = w * 16;
        float sa[2][4];
#pragma unroll
        for (int j = 0; j < 2; j++)
#pragma unroll
            for (int c = 0; c < 4; c++) sa[j][c] = 0.f;
#pragma unroll
        for (int kk = 0; kk < 8; kk++) {
            int o0 = (srb + fr) * 68 + kk * 8 + fc;
            int o1 = o0 + 8 * 68;
            unsigned ah0 = Ehi[o0], ah1 = Ehi[o1], ah2 = Ehi[o0 + 4], ah3 = Ehi[o1 + 4];
            unsigned al0 = Elo[o0], al1 = Elo[o1], al2 = Elo[o0 + 4], al3 = Elo[o1 + 4];
#pragma unroll
            for (int j = 0; j < 2; j++) {
                int n = j * 8 + fr;
                uint4 bq = gBs[(n * 8 + kk) * 4 + fc];
                mma16816(sa[j], ah0, ah1, ah2, ah3, bq.x, bq.y);
                mma16816(sa[j], ah0, ah1, ah2, ah3, bq.z, bq.w);
                mma16816(sa[j], al0, al1, al2, al3, bq.x, bq.y);
            }
        }
#pragma unroll
        for (int j = 0; j < 2; j++)
#pragma unroll
            for (int q = 0; q < 4; q++) {
                int row = srb + fr + (q >> 1) * 8;
                int nid = sNid[row];
                int h = fc * 2 + (q & 1);
                if (nid >= 0) {
                    if (j == 0) g_star[nid * 8 + h] = sa[j][q];
                    else        g_ssrc[nid * 8 + h] = sa[j][q];
                }
            }
    }
}

// ---------------- tensor-core edge kernel (CSR-position output) ----------------
#define XHI 0
#define XLO 2304
#define AHI 4608
#define ALO 8960
#define THI 13312
#define TLO 0
#define EDGE_SMEM_U32 17664
#define EDGE_SMEM_BYTES (EDGE_SMEM_U32 * 4)

__global__ void __launch_bounds__(256)
k_edge(const float* __restrict__ eattr, const float* __restrict__ etype) {
    extern __shared__ unsigned su[];
    __shared__ int sSrc[ETILE], sTar[ETILE], sPos[ETILE];

    int t = threadIdx.x, lane = t & 31, w = t >> 5;
    int nh = w & 3, rt = w >> 2;
    int rb = rt * 16;
    int fr = lane >> 2, fc = lane & 3;
    int e0 = blockIdx.x * ETILE;

    {
        int row = t >> 2, cg = (t & 3) * 16;
        const float4* src = (const float4*)(eattr + (size_t)(e0 + row) * 64 + cg);
        unsigned* xh = su + XHI + row * 36 + cg / 2;
        unsigned* xl = su + XLO + row * 36 + cg / 2;
#pragma unroll
        for (int p = 0; p < 4; p++) {
            float4 v = src[p];
            unsigned h0, l0, h1, l1;
            splitpack(v.x, v.y, h0, l0);
            splitpack(v.z, v.w, h1, l1);
            xh[p * 2] = h0; xh[p * 2 + 1] = h1;
            xl[p * 2] = l0; xl[p * 2 + 1] = l1;
        }
    }
    if (t < ETILE) {
        int s = g_src[e0 + t];
        sSrc[t] = s;
        sPos[t] = atomicAdd(&g_cursor[s], 1);   // claim CSR slot for this edge
    } else if (t < 2 * ETILE) {
        sTar[t - ETILE] = g_tar[e0 + t - ETILE];
    }
    __syncthreads();

    float acc[2][4][4];

    // ---- phase A ----
#pragma unroll
    for (int ti = 0; ti < 2; ti++)
#pragma unroll
        for (int j = 0; j < 4; j++)
#pragma unroll
            for (int c = 0; c < 4; c++) acc[ti][j][c] = 0.f;
    gemm_frag2<4, 36>(su + XHI, su + XLO, gBea, rb, nh, lane, acc);
#pragma unroll
    for (int ti = 0; ti < 2; ti++)
#pragma unroll
        for (int j = 0; j < 4; j++) {
            int colu = nh * 16 + j * 4 + fc;
            int r = rb + fr + ti * 32;
            unsigned h, l;
            splitpack(lrelu(acc[ti][j][0]), lrelu(acc[ti][j][1]), h, l);
            su[AHI + r * 68 + colu] = h;
            su[ALO + r * 68 + colu] = l;
            splitpack(lrelu(acc[ti][j][2]), lrelu(acc[ti][j][3]), h, l);
            su[AHI + (r + 8) * 68 + colu] = h;
            su[ALO + (r + 8) * 68 + colu] = l;
        }
    __syncthreads();

    {
        int row = t >> 2, cg = (t & 3) * 16;
        const float4* src = (const float4*)(etype + (size_t)(e0 + row) * 64 + cg);
        unsigned* xh = su + XHI + row * 36 + cg / 2;
        unsigned* xl = su + XLO + row * 36 + cg / 2;
#pragma unroll
        for (int p = 0; p < 4; p++) {
            float4 v = src[p];
            unsigned h0, l0, h1, l1;
            splitpack(v.x, v.y, h0, l0);
            splitpack(v.z, v.w, h1, l1);
            xh[p * 2] = h0; xh[p * 2 + 1] = h1;
            xl[p * 2] = l0; xl[p * 2 + 1] = l1;
        }
    }
    __syncthreads();

    // ---- phase T (TLO aliases X: sync after gemm reads) ----
#pragma unroll
    for (int ti = 0; ti < 2; ti++)
#pragma unroll
        for (int j = 0; j < 4; j++)
#pragma unroll
            for (int c = 0; c < 4; c++) acc[ti][j][c] = 0.f;
    gemm_frag2<4, 36>(su + XHI, su + XLO, gBet, rb, nh, lane, acc);
    __syncthreads();
#pragma unroll
    for (int ti = 0; ti < 2; ti++)
#pragma unroll
        for (int j = 0; j < 4; j++) {
            int colu = nh * 16 + j * 4 + fc;
            int r = rb + fr + ti * 32;
            unsigned h, l;
            splitpack(lrelu(acc[ti][j][0]), lrelu(acc[ti][j][1]), h, l);
            su[THI + r * 68 + colu] = h;
            su[TLO + r * 68 + colu] = l;
            splitpack(lrelu(acc[ti][j][2]), lrelu(acc[ti][j][3]), h, l);
            su[THI + (r + 8) * 68 + colu] = h;
            su[TLO + (r + 8) * 68 + colu] = l;
        }
    __syncthreads();

    // ---- scores (warps 0-3), write ex at CSR position ----
    if (w < 4) {
        int srb = w * 16;
        float sacc[4] = {0.f, 0.f, 0.f, 0.f};
#pragma unroll
        for (int kk = 0; kk < 16; kk++) {
            int base_h = (kk < 8) ? AHI : THI;
            int base_l = (kk < 8) ? ALO : TLO;
            int kx = kk & 7;
            int o0 = (srb + fr) * 68 + kx * 8 + fc;
            int o1 = (srb + fr + 8) * 68 + kx * 8 + fc;
            unsigned ah0 = su[base_h + o0], ah1 = su[base_h + o1];
            unsigned ah2 = su[base_h + o0 + 4], ah3 = su[base_h + o1 + 4];
            unsigned al0 = su[base_l + o0], al1 = su[base_l + o1];
            unsigned al2 = su[base_l + o0 + 4], al3 = su[base_l + o1 + 4];
            uint4 bq = gBa[(fr * 16 + kk) * 4 + fc];
            mma16816(sacc, ah0, ah1, ah2, ah3, bq.x, bq.y);
            mma16816(sacc, ah0, ah1, ah2, ah3, bq.z, bq.w);
            mma16816(sacc, al0, al1, al2, al3, bq.x, bq.y);
        }
        int h0 = fc * 2;
#pragma unroll
        for (int q = 0; q < 4; q++) {
            int row = srb + fr + (q >> 1) * 8;
            int h = h0 + (q & 1);
            int sr = sSrc[row], tg = sTar[row];
            float sc = sacc[q] + g_star[tg * 8 + h] + g_ssrc[sr * 8 + h];
            sc = lrelu(sc);
            float ex = expf(sc);
            g_ex[(size_t)sPos[row] * 8 + h] = ex;
            atomicAdd(&g_denom[sr * 8 + h], ex);
        }
    }

    // ---- phase P (fp16 attrpart at CSR position) ----
#pragma unroll
    for (int ti = 0; ti < 2; ti++)
#pragma unroll
        for (int j = 0; j < 4; j++)
#pragma unroll
            for (int c = 0; c < 4; c++) acc[ti][j][c] = 0.f;
    gemm_frag2<8, 68>(su + AHI, su + ALO, gBup, rb, nh, lane, acc);
#pragma unroll
    for (int ti = 0; ti < 2; ti++)
#pragma unroll
        for (int j = 0; j < 4; j++) {
            int n0 = nh * 32 + j * 8 + fc * 2;
            int r = rb + fr + ti * 32;
            *(__half2*)(g_attrpart_h + (size_t)sPos[r] * 128 + n0) =
                __floats2half2_rn(acc[ti][j][0], acc[ti][j][1]);
            *(__half2*)(g_attrpart_h + (size_t)sPos[r + 8] * 128 + n0) =
                __floats2half2_rn(acc[ti][j][2], acc[ti][j][3]);
        }
}

// ---------------- aggregation (fully sequential streams) ----------------
__global__ void k_aggr(float* __restrict__ out) {
    int n = blockIdx.x;
    int t = threadIdx.x;
    int s = g_off[n], e_end = g_off[n + 1];
    float p = g_P[(size_t)n * 128 + t];
    float acc[8];
#pragma unroll
    for (int h = 0; h < 8; h++) acc[h] = 0.f;
    if (e_end > s) {
        for (int j = s; j < e_end; j++) {
            float m = lrelu(p + __half2float(g_attrpart_h[(size_t)j * 128 + t]));
            const float4* xp = (const float4*)(g_ex + (size_t)j * 8);
            float4 ea = xp[0], eb = xp[1];
            acc[0] += ea.x * m; acc[1] += ea.y * m; acc[2] += ea.z * m; acc[3] += ea.w * m;
            acc[4] += eb.x * m; acc[5] += eb.y * m; acc[6] += eb.z * m; acc[7] += eb.w * m;
        }
        const float4* dp = (const float4*)(g_denom + n * 8);
        float4 da = dp[0], db = dp[1];
        acc[0] /= da.x; acc[1] /= da.y; acc[2] /= da.z; acc[3] /= da.w;
        acc[4] /= db.x; acc[5] /= db.y; acc[6] /= db.z; acc[7] /= db.w;
    }
#pragma unroll
    for (int h = 0; h < 8; h++) out[(size_t)n * 1024 + h * 128 + t] = acc[h];
}

// ---------------- launch ----------------
extern "C" void kernel_launch(void* const* d_in, const int* in_sizes, int n_in,
                              void* d_out, int out_size) {
    const float* node_feats = (const float*)d_in[0];
    const int*   edge_index = (const int*)d_in[1];
    const float* edge_attr  = (const float*)d_in[2];
    const float* edge_type  = (const float*)d_in[3];
    const int*   ntl        = (const int*)d_in[4];
    const float* W_node  = (const float*)d_in[6];
    const float* W_eattr = (const float*)d_in[7];
    const float* W_etype = (const float*)d_in[8];
    const float* W_upd   = (const float*)d_in[9];
    const float* W_attn  = (const float*)d_in[10];
    float* out = (float*)d_out;

    cudaFuncSetAttribute(k_edge, cudaFuncAttributeMaxDynamicSharedMemorySize, EDGE_SMEM_BYTES);
    cudaFuncSetAttribute(k_node, cudaFuncAttributeMaxDynamicSharedMemorySize, NODE_SMEM_BYTES);

    const int TB = 256;
    const int GB_E = (N_EDGES + TB - 1) / TB;

    k_init<<<GB_E, TB>>>(edge_index, W_eattr, W_etype, W_upd, W_attn, W_node);   // 1
    k_hist<<<GB_E, TB>>>(ntl);                                                   // 2
    k_scanA<<<NSCANB, TB>>>();                                                   // 3
    k_scanB<<<1, TB>>>();                                                        // 4
    k_scanC<<<NSCANB, TB>>>();                                                   // 5
    k_node<<<3 * NBLK64, TB, NODE_SMEM_BYTES>>>(node_feats);                     // 6
    k_edge<<<NTILES, TB, EDGE_SMEM_BYTES>>>(edge_attr, edge_type);               // 7
    k_aggr<<<N_NODES, 128>>>(out);                                               // 8
}

// round 14
// speedup vs baseline: 3.7472x; 1.0821x over previous
#include <cuda_runtime.h>
#include <cuda_bf16.h>
#include <cuda_fp16.h>
#include <math.h>

#define N_NODES 50000
#define N_EDGES 400000
#define SLOPE   0.2f

#define ETILE   64
#define NTILES  (N_EDGES / ETILE)   // 6250, exact
#define NSCANB  196                 // ceil(50000/256)
#define NBLK64  782                 // ceil(50000/64) tiles per type bucket
#define PERM3_CAP (NBLK64 * 64)     // 50048

// ---------------- scratch ----------------
__device__ __align__(16) float g_P[(size_t)N_NODES * 128];
__device__ __align__(16) float g_star[N_NODES * 8];
__device__ __align__(16) float g_ssrc[N_NODES * 8];
__device__ __align__(16) __half g_attrpart_h[(size_t)N_EDGES * 128];  // CSR-ordered
__device__ __align__(16) float g_ex[N_EDGES * 8];                     // CSR-ordered
__device__ __align__(16) float g_denom[N_NODES * 8];
__device__ int g_src[N_EDGES], g_tar[N_EDGES];
__device__ int g_deg[N_NODES], g_off[N_NODES + 1], g_cursor[N_NODES];
__device__ int g_bpart[NSCANB], g_bpre[NSCANB];
__device__ int g_perm3[3 * PERM3_CAP];
__device__ int g_tcursor3[3];

// mma-ready packed B fragments, CONTIGUOUS per (warp-group, kstep):
// layout [g=(nh*4+j)][kk][fr][fc] -> one j-iteration = 512B contiguous
__device__ __align__(16) uint4 gBea[16 * 4 * 32];
__device__ __align__(16) uint4 gBet[16 * 4 * 32];
__device__ __align__(16) uint4 gBup[16 * 8 * 32];
__device__ __align__(16) uint4 gBa [16 * 32];          // [kk][fr][fc]
__device__ __align__(16) uint4 gBn [3 * 16 * 16 * 32];
__device__ __align__(16) uint4 gBuT[16 * 8 * 32];
__device__ __align__(16) uint4 gBs [2 * 8 * 32];       // [j][kk][fr][fc]

__device__ __forceinline__ float lrelu(float x) { return x >= 0.f ? x : SLOPE * x; }

__device__ __forceinline__ void splitpack(float x, float y, unsigned& hi, unsigned& lo) {
    __nv_bfloat16 hx = __float2bfloat16(x);
    __nv_bfloat16 hy = __float2bfloat16(y);
    float lx = x - __bfloat162float(hx);
    float ly = y - __bfloat162float(hy);
    __nv_bfloat162 h2 = __halves2bfloat162(hx, hy);
    __nv_bfloat162 l2 = __halves2bfloat162(__float2bfloat16(lx), __float2bfloat16(ly));
    hi = *reinterpret_cast<unsigned*>(&h2);
    lo = *reinterpret_cast<unsigned*>(&l2);
}

__device__ __forceinline__ uint4 pack4(float w0, float w1, float w2, float w3) {
    unsigned h0, l0, h1, l1;
    splitpack(w0, w1, h0, l0);
    splitpack(w2, w3, h1, l1);
    return make_uint4(h0, h1, l0, l1);
}

__device__ __forceinline__ void mma16816(float* c, unsigned a0, unsigned a1, unsigned a2,
                                         unsigned a3, unsigned b0, unsigned b1) {
    asm volatile(
        "mma.sync.aligned.m16n8k16.row.col.f32.bf16.bf16.f32 "
        "{%0,%1,%2,%3}, {%4,%5,%6,%7}, {%8,%9}, {%0,%1,%2,%3};"
        : "+f"(c[0]), "+f"(c[1]), "+f"(c[2]), "+f"(c[3])
        : "r"(a0), "r"(a1), "r"(a2), "r"(a3), "r"(b0), "r"(b1));
}

__device__ __forceinline__ void ldsm4(unsigned& r0, unsigned& r1, unsigned& r2, unsigned& r3,
                                      unsigned addr) {
    asm volatile("ldmatrix.sync.aligned.m8n8.x4.shared.b16 {%0,%1,%2,%3}, [%4];"
                 : "=r"(r0), "=r"(r1), "=r"(r2), "=r"(r3) : "r"(addr));
}

// ---------------- fused init (packing in new contiguous layout) ----------------
__global__ void k_init(const int* __restrict__ eidx,
                       const float* __restrict__ Wea, const float* __restrict__ Wet,
                       const float* __restrict__ Wupd, const float* __restrict__ Wattn,
                       const float* __restrict__ Wn) {
    int i = blockIdx.x * blockDim.x + threadIdx.x;
    if (i < N_EDGES) {
        g_src[i] = eidx[i];
        g_tar[i] = eidx[N_EDGES + i];
    }
    if (i < N_NODES * 8) g_denom[i] = 0.f;
    if (i < N_NODES) g_deg[i] = 0;
    if (i < 3 * PERM3_CAP) g_perm3[i] = -1;
    if (i < 3) g_tcursor3[i] = 0;

    if (i < 2048) {            // Bea/Bet: KSTEPS=4; i = ((g*4+kk)*8+fr)*4+fc
        int fc = i & 3, fr = (i >> 2) & 7, kk = (i >> 5) & 3, g = i >> 7;
        int n = (g >> 2) * 32 + (g & 3) * 8 + fr;
        int k0 = 2 * (kk * 8 + fc);
        gBea[i] = pack4(Wea[k0 * 128 + n],       Wea[(k0 + 1) * 128 + n],
                        Wea[(k0 + 8) * 128 + n], Wea[(k0 + 9) * 128 + n]);
        gBet[i] = pack4(Wet[k0 * 128 + n],       Wet[(k0 + 1) * 128 + n],
                        Wet[(k0 + 8) * 128 + n], Wet[(k0 + 9) * 128 + n]);
    }
    if (i < 4096) {            // Bup/BuT: KSTEPS=8
        int fc = i & 3, fr = (i >> 2) & 7, kk = (i >> 5) & 7, g = i >> 8;
        int n = (g >> 2) * 32 + (g & 3) * 8 + fr;
        int k0 = 2 * (kk * 8 + fc);
        gBup[i] = pack4(Wupd[(128 + k0) * 128 + n], Wupd[(129 + k0) * 128 + n],
                        Wupd[(136 + k0) * 128 + n], Wupd[(137 + k0) * 128 + n]);
        gBuT[i] = pack4(Wupd[k0 * 128 + n],       Wupd[(k0 + 1) * 128 + n],
                        Wupd[(k0 + 8) * 128 + n], Wupd[(k0 + 9) * 128 + n]);
    }
    if (i < 512) {             // Ba: [kk][fr][fc], kk 0..15, h = fr
        int fc = i & 3, fr = (i >> 2) & 7, kk = i >> 5;
        int k0 = 2 * (kk * 8 + fc);
        int h = fr;
        gBa[i] = pack4(Wattn[(128 + k0) * 8 + h], Wattn[(129 + k0) * 8 + h],
                       Wattn[(136 + k0) * 8 + h], Wattn[(137 + k0) * 8 + h]);
        // Bs: [j][kk2][fr][fc], n = j*8+fr  (n<8 -> star rows 0..127, else ssrc rows 384..511)
        int j = i >> 8, kk2 = (i >> 5) & 7;
        int n = j * 8 + fr;
        int q0 = 2 * (kk2 * 8 + fc);
        int ro = (n < 8) ? 0 : 384;
        int hh = (n < 8) ? n : n - 8;
        gBs[i] = pack4(Wattn[(ro + q0) * 8 + hh],     Wattn[(ro + q0 + 1) * 8 + hh],
                       Wattn[(ro + q0 + 8) * 8 + hh], Wattn[(ro + q0 + 9) * 8 + hh]);
    }
    if (i < 24576) {           // Bn: KSTEPS=16 per type
        int tp = i >> 13, r = i & 8191;
        int fc = r & 3, fr = (r >> 2) & 7, kk = (r >> 5) & 15, g = r >> 9;
        int n = (g >> 2) * 32 + (g & 3) * 8 + fr;
        int k0 = 2 * (kk * 8 + fc);
        const float* W = Wn + (size_t)tp * 32768;
        gBn[i] = pack4(W[k0 * 128 + n],       W[(k0 + 1) * 128 + n],
                       W[(k0 + 8) * 128 + n], W[(k0 + 9) * 128 + n]);
    }
}

__global__ void k_hist(const int* __restrict__ ntl) {
    int i = blockIdx.x * blockDim.x + threadIdx.x;
    if (i < N_EDGES) atomicAdd(&g_deg[g_src[i]], 1);
    if (i < N_NODES) {
        int tp = ntl[i];
        int p = atomicAdd(&g_tcursor3[tp], 1);
        g_perm3[tp * PERM3_CAP + p] = i;
    }
}

// ---------------- parallel scan ----------------
__global__ void k_scanA() {
    __shared__ int sh[8];
    int b = blockIdx.x, t = threadIdx.x, i = b * 256 + t;
    int v = (i < N_NODES) ? g_deg[i] : 0;
#pragma unroll
    for (int d = 16; d; d >>= 1) v += __shfl_down_sync(~0u, v, d);
    if ((t & 31) == 0) sh[t >> 5] = v;
    __syncthreads();
    if (t < 8) {
        int s = sh[t];
#pragma unroll
        for (int d = 4; d; d >>= 1) s += __shfl_down_sync(0xff, s, d);
        if (t == 0) g_bpart[b] = s;
    }
}

__global__ void k_scanB() {
    int t = threadIdx.x, lane = t & 31, wp = t >> 5;
    int v = (t < NSCANB) ? g_bpart[t] : 0;
    int inc = v;
#pragma unroll
    for (int d = 1; d < 32; d <<= 1) {
        int n = __shfl_up_sync(~0u, inc, d);
        if (lane >= d) inc += n;
    }
    __shared__ int wsum[8];
    if (lane == 31) wsum[wp] = inc;
    __syncthreads();
    if (t == 0) {
        int r = 0;
        for (int q = 0; q < 8; q++) { int x = wsum[q]; wsum[q] = r; r += x; }
    }
    __syncthreads();
    if (t < NSCANB) g_bpre[t] = inc - v + wsum[wp];
    if (t == 0) g_off[N_NODES] = N_EDGES;
}

__global__ void k_scanC() {
    int b = blockIdx.x, t = threadIdx.x, lane = t & 31, wp = t >> 5;
    int i = b * 256 + t;
    int v = (i < N_NODES) ? g_deg[i] : 0;
    int inc = v;
#pragma unroll
    for (int d = 1; d < 32; d <<= 1) {
        int n = __shfl_up_sync(~0u, inc, d);
        if (lane >= d) inc += n;
    }
    __shared__ int wsum[8];
    if (lane == 31) wsum[wp] = inc;
    __syncthreads();
    if (t == 0) {
        int r = 0;
        for (int q = 0; q < 8; q++) { int x = wsum[q]; wsum[q] = r; r += x; }
    }
    __syncthreads();
    int off = g_bpre[b] + inc - v + wsum[wp];
    if (i < N_NODES) { g_off[i] = off; g_cursor[i] = off; }
}

// ---------------- gemm fragment helper (ldmatrix A, contiguous B) ----------------
template <int KSTEPS, int STRIDE>
__device__ __forceinline__ void gemm_frag2(const unsigned* xh, const unsigned* xl,
                                           const uint4* __restrict__ B,
                                           int rb, int nh, int lane, float acc[2][4][4]) {
    int lrow = lane & 15, lhalf = lane >> 4;
    unsigned bh = (unsigned)__cvta_generic_to_shared(xh) + ((rb + lrow) * STRIDE + lhalf * 4) * 4;
    unsigned bl = (unsigned)__cvta_generic_to_shared(xl) + ((rb + lrow) * STRIDE + lhalf * 4) * 4;
    unsigned ch = bh + 32 * STRIDE * 4;
    unsigned cl = bl + 32 * STRIDE * 4;
    const uint4* Bw = B + (nh * 4) * KSTEPS * 32 + lane;   // lane = fr*4+fc
#pragma unroll
    for (int kk = 0; kk < KSTEPS; kk++) {
        unsigned ah0, ah1, ah2, ah3, al0, al1, al2, al3;
        unsigned ch0, ch1, ch2, ch3, cl0, cl1, cl2, cl3;
        ldsm4(ah0, ah1, ah2, ah3, bh + kk * 32);
        ldsm4(al0, al1, al2, al3, bl + kk * 32);
        ldsm4(ch0, ch1, ch2, ch3, ch + kk * 32);
        ldsm4(cl0, cl1, cl2, cl3, cl + kk * 32);
#pragma unroll
        for (int j = 0; j < 4; j++) {
            uint4 b = Bw[(j * KSTEPS + kk) * 32];   // one 512B-contiguous warp load
            mma16816(acc[0][j], ah0, ah1, ah2, ah3, b.x, b.y);
            mma16816(acc[0][j], ah0, ah1, ah2, ah3, b.z, b.w);
            mma16816(acc[0][j], al0, al1, al2, al3, b.x, b.y);
            mma16816(acc[1][j], ch0, ch1, ch2, ch3, b.x, b.y);
            mma16816(acc[1][j], ch0, ch1, ch2, ch3, b.z, b.w);
            mma16816(acc[1][j], cl0, cl1, cl2, cl3, b.x, b.y);
        }
    }
}

// ---------------- tensor-core node kernel ----------------
#define N_XHI 0
#define N_XLO 8448
#define N_EHI 0
#define N_ELO 4352
#define NODE_SMEM_U32 16896
#define NODE_SMEM_BYTES (NODE_SMEM_U32 * 4)

__global__ void __launch_bounds__(256)
k_node(const float* __restrict__ x) {
    extern __shared__ unsigned su[];
    __shared__ int sNid[64];
    unsigned* Xhi = su + N_XHI;
    unsigned* Xlo = su + N_XLO;
    unsigned* Ehi = su + N_EHI;
    unsigned* Elo = su + N_ELO;

    int t = threadIdx.x, lane = t & 31, w = t >> 5;
    int b = blockIdx.x;
    int tp = b / NBLK64;
    int base = tp * PERM3_CAP + (b - tp * NBLK64) * 64;

    if (g_perm3[base] < 0) return;
    if (t < 64) sNid[t] = g_perm3[base + t];
    __syncthreads();

    {
        int row = t >> 2, seg = t & 3;
        int nid = sNid[row];
        const float4* src = (const float4*)(x + (size_t)(nid < 0 ? 0 : nid) * 256 + seg * 64);
        unsigned* xh = Xhi + row * 132 + seg * 32;
        unsigned* xl = Xlo + row * 132 + seg * 32;
#pragma unroll
        for (int p = 0; p < 16; p++) {
            float4 v = (nid >= 0) ? src[p] : make_float4(0.f, 0.f, 0.f, 0.f);
            unsigned h0, l0, h1, l1;
            splitpack(v.x, v.y, h0, l0);
            splitpack(v.z, v.w, h1, l1);
            xh[p * 2] = h0; xh[p * 2 + 1] = h1;
            xl[p * 2] = l0; xl[p * 2 + 1] = l1;
        }
    }
    __syncthreads();

    int nh = w & 3, rt = w >> 2;
    int rb = rt * 16;
    int fr = lane >> 2, fc = lane & 3;

    float acc[2][4][4];

#pragma unroll
    for (int ti = 0; ti < 2; ti++)
#pragma unroll
        for (int j = 0; j < 4; j++)
#pragma unroll
            for (int c = 0; c < 4; c++) acc[ti][j][c] = 0.f;
    gemm_frag2<16, 132>(Xhi, Xlo, gBn + tp * 8192, rb, nh, lane, acc);
    __syncthreads();
#pragma unroll
    for (int ti = 0; ti < 2; ti++)
#pragma unroll
        for (int j = 0; j < 4; j++) {
            int colu = nh * 16 + j * 4 + fc;
            int r = rb + fr + ti * 32;
            unsigned h, l;
            splitpack(acc[ti][j][0], acc[ti][j][1], h, l);
            Ehi[r * 68 + colu] = h;
            Elo[r * 68 + colu] = l;
            splitpack(acc[ti][j][2], acc[ti][j][3], h, l);
            Ehi[(r + 8) * 68 + colu] = h;
            Elo[(r + 8) * 68 + colu] = l;
        }
    __syncthreads();

#pragma unroll
    for (int ti = 0; ti < 2; ti++)
#pragma unroll
        for (int j = 0; j < 4; j++)
#pragma unroll
            for (int c = 0; c < 4; c++) acc[ti][j][c] = 0.f;
    gemm_frag2<8, 68>(Ehi, Elo, gBuT, rb, nh, lane, acc);
#pragma unroll
    for (int ti = 0; ti < 2; ti++)
#pragma unroll
        for (int j = 0; j < 4; j++) {
            int n0 = nh * 32 + j * 8 + fc * 2;
            int r = rb + fr + ti * 32;
            int n1 = sNid[r], n2 = sNid[r + 8];
            if (n1 >= 0)
                *(float2*)(g_P + (size_t)n1 * 128 + n0) = make_float2(acc[ti][j][0], acc[ti][j][1]);
            if (n2 >= 0)
                *(float2*)(g_P + (size_t)n2 * 128 + n0) = make_float2(acc[ti][j][2], acc[ti][j][3]);
        }

    if (w < 4) {
        int srb = w * 16;
        float sa[2][4];
#pragma unroll
        for (int j = 0; j < 2; j++)
#pragma unroll
            for (int c = 0; c < 4; c++) sa[j][c] = 0.f;
#pragma unroll
        for (int kk = 0; kk < 8; kk++) {
            int o0 = (srb + fr) * 68 + kk * 8 + fc;
            int o1 = o0 + 8 * 68;
            unsigned ah0 = Ehi[o0], ah1 = Ehi[o1], ah2 = Ehi[o0 + 4], ah3 = Ehi[o1 + 4];
            unsigned al0 = Elo[o0], al1 = Elo[o1], al2 = Elo[o0 + 4], al3 = Elo[o1 + 4];
#pragma unroll
            for (int j = 0; j < 2; j++) {
                uint4 bq = gBs[(j * 8 + kk) * 32 + lane];
                mma16816(sa[j], ah0, ah1, ah2, ah3, bq.x, bq.y);
                mma16816(sa[j], ah0, ah1, ah2, ah3, bq.z, bq.w);
                mma16816(sa[j], al0, al1, al2, al3, bq.x, bq.y);
            }
        }
#pragma unroll
        for (int j = 0; j < 2; j++)
#pragma unroll
            for (int q = 0; q < 4; q++) {
                int row = srb + fr + (q >> 1) * 8;
                int nid = sNid[row];
                int h = fc * 2 + (q & 1);
                if (nid >= 0) {
                    if (j == 0) g_star[nid * 8 + h] = sa[j][q];
                    else        g_ssrc[nid * 8 + h] = sa[j][q];
                }
            }
    }
}

// ---------------- tensor-core edge kernel (CSR-position output) ----------------
#define XHI 0
#define XLO 2304
#define AHI 4608
#define ALO 8960
#define THI 13312
#define TLO 0
#define EDGE_SMEM_U32 17664
#define EDGE_SMEM_BYTES (EDGE_SMEM_U32 * 4)

__global__ void __launch_bounds__(256)
k_edge(const float* __restrict__ eattr, const float* __restrict__ etype) {
    extern __shared__ unsigned su[];
    __shared__ int sSrc[ETILE], sTar[ETILE], sPos[ETILE];

    int t = threadIdx.x, lane = t & 31, w = t >> 5;
    int nh = w & 3, rt = w >> 2;
    int rb = rt * 16;
    int fr = lane >> 2, fc = lane & 3;
    int e0 = blockIdx.x * ETILE;

    {
        int row = t >> 2, cg = (t & 3) * 16;
        const float4* src = (const float4*)(eattr + (size_t)(e0 + row) * 64 + cg);
        unsigned* xh = su + XHI + row * 36 + cg / 2;
        unsigned* xl = su + XLO + row * 36 + cg / 2;
#pragma unroll
        for (int p = 0; p < 4; p++) {
            float4 v = src[p];
            unsigned h0, l0, h1, l1;
            splitpack(v.x, v.y, h0, l0);
            splitpack(v.z, v.w, h1, l1);
            xh[p * 2] = h0; xh[p * 2 + 1] = h1;
            xl[p * 2] = l0; xl[p * 2 + 1] = l1;
        }
    }
    if (t < ETILE) {
        int s = g_src[e0 + t];
        sSrc[t] = s;
        sPos[t] = atomicAdd(&g_cursor[s], 1);
    } else if (t < 2 * ETILE) {
        sTar[t - ETILE] = g_tar[e0 + t - ETILE];
    }
    __syncthreads();

    float acc[2][4][4];

    // ---- phase A ----
#pragma unroll
    for (int ti = 0; ti < 2; ti++)
#pragma unroll
        for (int j = 0; j < 4; j++)
#pragma unroll
            for (int c = 0; c < 4; c++) acc[ti][j][c] = 0.f;
    gemm_frag2<4, 36>(su + XHI, su + XLO, gBea, rb, nh, lane, acc);
#pragma unroll
    for (int ti = 0; ti < 2; ti++)
#pragma unroll
        for (int j = 0; j < 4; j++) {
            int colu = nh * 16 + j * 4 + fc;
            int r = rb + fr + ti * 32;
            unsigned h, l;
            splitpack(lrelu(acc[ti][j][0]), lrelu(acc[ti][j][1]), h, l);
            su[AHI + r * 68 + colu] = h;
            su[ALO + r * 68 + colu] = l;
            splitpack(lrelu(acc[ti][j][2]), lrelu(acc[ti][j][3]), h, l);
            su[AHI + (r + 8) * 68 + colu] = h;
            su[ALO + (r + 8) * 68 + colu] = l;
        }
    __syncthreads();

    {
        int row = t >> 2, cg = (t & 3) * 16;
        const float4* src = (const float4*)(etype + (size_t)(e0 + row) * 64 + cg);
        unsigned* xh = su + XHI + row * 36 + cg / 2;
        unsigned* xl = su + XLO + row * 36 + cg / 2;
#pragma unroll
        for (int p = 0; p < 4; p++) {
            float4 v = src[p];
            unsigned h0, l0, h1, l1;
            splitpack(v.x, v.y, h0, l0);
            splitpack(v.z, v.w, h1, l1);
            xh[p * 2] = h0; xh[p * 2 + 1] = h1;
            xl[p * 2] = l0; xl[p * 2 + 1] = l1;
        }
    }
    __syncthreads();

    // ---- phase T (TLO aliases X: sync after gemm reads) ----
#pragma unroll
    for (int ti = 0; ti < 2; ti++)
#pragma unroll
        for (int j = 0; j < 4; j++)
#pragma unroll
            for (int c = 0; c < 4; c++) acc[ti][j][c] = 0.f;
    gemm_frag2<4, 36>(su + XHI, su + XLO, gBet, rb, nh, lane, acc);
    __syncthreads();
#pragma unroll
    for (int ti = 0; ti < 2; ti++)
#pragma unroll
        for (int j = 0; j < 4; j++) {
            int colu = nh * 16 + j * 4 + fc;
            int r = rb + fr + ti * 32;
            unsigned h, l;
            splitpack(lrelu(acc[ti][j][0]), lrelu(acc[ti][j][1]), h, l);
            su[THI + r * 68 + colu] = h;
            su[TLO + r * 68 + colu] = l;
            splitpack(lrelu(acc[ti][j][2]), lrelu(acc[ti][j][3]), h, l);
            su[THI + (r + 8) * 68 + colu] = h;
            su[TLO + (r + 8) * 68 + colu] = l;
        }
    __syncthreads();

    // ---- scores (warps 0-3), ex at CSR position ----
    if (w < 4) {
        int srb = w * 16;
        float sacc[4] = {0.f, 0.f, 0.f, 0.f};
#pragma unroll
        for (int kk = 0; kk < 16; kk++) {
            int base_h = (kk < 8) ? AHI : THI;
            int base_l = (kk < 8) ? ALO : TLO;
            int kx = kk & 7;
            int o0 = (srb + fr) * 68 + kx * 8 + fc;
            int o1 = (srb + fr + 8) * 68 + kx * 8 + fc;
            unsigned ah0 = su[base_h + o0], ah1 = su[base_h + o1];
            unsigned ah2 = su[base_h + o0 + 4], ah3 = su[base_h + o1 + 4];
            unsigned al0 = su[base_l + o0], al1 = su[base_l + o1];
            unsigned al2 = su[base_l + o0 + 4], al3 = su[base_l + o1 + 4];
            uint4 bq = gBa[kk * 32 + lane];
            mma16816(sacc, ah0, ah1, ah2, ah3, bq.x, bq.y);
            mma16816(sacc, ah0, ah1, ah2, ah3, bq.z, bq.w);
            mma16816(sacc, al0, al1, al2, al3, bq.x, bq.y);
        }
        int h0 = fc * 2;
#pragma unroll
        for (int q = 0; q < 4; q++) {
            int row = srb + fr + (q >> 1) * 8;
            int h = h0 + (q & 1);
            int sr = sSrc[row], tg = sTar[row];
            float sc = sacc[q] + g_star[tg * 8 + h] + g_ssrc[sr * 8 + h];
            sc = lrelu(sc);
            float ex = expf(sc);
            g_ex[(size_t)sPos[row] * 8 + h] = ex;
            atomicAdd(&g_denom[sr * 8 + h], ex);
        }
    }

    // ---- phase P (fp16 attrpart at CSR position) ----
#pragma unroll
    for (int ti = 0; ti < 2; ti++)
#pragma unroll
        for (int j = 0; j < 4; j++)
#pragma unroll
            for (int c = 0; c < 4; c++) acc[ti][j][c] = 0.f;
    gemm_frag2<8, 68>(su + AHI, su + ALO, gBup, rb, nh, lane, acc);
#pragma unroll
    for (int ti = 0; ti < 2; ti++)
#pragma unroll
        for (int j = 0; j < 4; j++) {
            int n0 = nh * 32 + j * 8 + fc * 2;
            int r = rb + fr + ti * 32;
            *(__half2*)(g_attrpart_h + (size_t)sPos[r] * 128 + n0) =
                __floats2half2_rn(acc[ti][j][0], acc[ti][j][1]);
            *(__half2*)(g_attrpart_h + (size_t)sPos[r + 8] * 128 + n0) =
                __floats2half2_rn(acc[ti][j][2], acc[ti][j][3]);
        }
}

// ---------------- aggregation (sequential streams) ----------------
__global__ void k_aggr(float* __restrict__ out) {
    int n = blockIdx.x;
    int t = threadIdx.x;
    int s = g_off[n], e_end = g_off[n + 1];
    float p = g_P[(size_t)n * 128 + t];
    float acc[8];
#pragma unroll
    for (int h = 0; h < 8; h++) acc[h] = 0.f;
    if (e_end > s) {
        for (int j = s; j < e_end; j++) {
            float m = lrelu(p + __half2float(g_attrpart_h[(size_t)j * 128 + t]));
            const float4* xp = (const float4*)(g_ex + (size_t)j * 8);
            float4 ea = xp[0], eb = xp[1];
            acc[0] += ea.x * m; acc[1] += ea.y * m; acc[2] += ea.z * m; acc[3] += ea.w * m;
            acc[4] += eb.x * m; acc[5] += eb.y * m; acc[6] += eb.z * m; acc[7] += eb.w * m;
        }
        const float4* dp = (const float4*)(g_denom + n * 8);
        float4 da = dp[0], db = dp[1];
        acc[0] /= da.x; acc[1] /= da.y; acc[2] /= da.z; acc[3] /= da.w;
        acc[4] /= db.x; acc[5] /= db.y; acc[6] /= db.z; acc[7] /= db.w;
    }
#pragma unroll
    for (int h = 0; h < 8; h++) out[(size_t)n * 1024 + h * 128 + t] = acc[h];
}

// ---------------- launch (k_node at slot 4 for ncu) ----------------
extern "C" void kernel_launch(void* const* d_in, const int* in_sizes, int n_in,
                              void* d_out, int out_size) {
    const float* node_feats = (const float*)d_in[0];
    const int*   edge_index = (const int*)d_in[1];
    const float* edge_attr  = (const float*)d_in[2];
    const float* edge_type  = (const float*)d_in[3];
    const int*   ntl        = (const int*)d_in[4];
    const float* W_node  = (const float*)d_in[6];
    const float* W_eattr = (const float*)d_in[7];
    const float* W_etype = (const float*)d_in[8];
    const float* W_upd   = (const float*)d_in[9];
    const float* W_attn  = (const float*)d_in[10];
    float* out = (float*)d_out;

    cudaFuncSetAttribute(k_edge, cudaFuncAttributeMaxDynamicSharedMemorySize, EDGE_SMEM_BYTES);
    cudaFuncSetAttribute(k_node, cudaFuncAttributeMaxDynamicSharedMemorySize, NODE_SMEM_BYTES);

    const int TB = 256;
    const int GB_E = (N_EDGES + TB - 1) / TB;

    k_init<<<GB_E, TB>>>(edge_index, W_eattr, W_etype, W_upd, W_attn, W_node);   // 1
    k_hist<<<GB_E, TB>>>(ntl);                                                   // 2
    k_scanA<<<NSCANB, TB>>>();                                                   // 3
    k_node<<<3 * NBLK64, TB, NODE_SMEM_BYTES>>>(node_feats);                     // 4 <- profiled
    k_scanB<<<1, TB>>>();                                                        // 5
    k_scanC<<<NSCANB, TB>>>();                                                   // 6
    k_edge<<<NTILES, TB, EDGE_SMEM_BYTES>>>(edge_attr, edge_type);               // 7
    k_aggr<<<N_NODES, 128>>>(out);                                               // 8
}

// round 15
// speedup vs baseline: 4.1195x; 1.0994x over previous
#include <cuda_runtime.h>
#include <cuda_bf16.h>
#include <cuda_fp16.h>
#include <math.h>

#define N_NODES 50000
#define N_EDGES 400000
#define SLOPE   0.2f

#define ETILE   64
#define NTILES  (N_EDGES / ETILE)   // 6250, exact
#define NSCANB  196                 // ceil(50000/256)
#define NBLK64  782                 // ceil(50000/64) tiles per type bucket
#define PERM3_CAP (NBLK64 * 64)     // 50048

// ---------------- scratch ----------------
__device__ __align__(16) float g_P[(size_t)N_NODES * 128];
__device__ __align__(16) float g_star[N_NODES * 8];
__device__ __align__(16) float g_ssrc[N_NODES * 8];
__device__ __align__(16) __half g_attrpart_h[(size_t)N_EDGES * 128];  // CSR-ordered
__device__ __align__(16) float g_ex[N_EDGES * 8];                     // CSR-ordered
__device__ __align__(16) float g_denom[N_NODES * 8];
__device__ int g_src[N_EDGES], g_tar[N_EDGES];
__device__ int g_deg[N_NODES], g_off[N_NODES + 1], g_cursor[N_NODES];
__device__ int g_bpart[NSCANB], g_bpre[NSCANB];
__device__ int g_perm3[3 * PERM3_CAP];
__device__ int g_tcursor3[3];

// mma-ready packed B fragments, CONTIGUOUS per (warp-group, kstep)
__device__ __align__(16) uint4 gBea[16 * 4 * 32];
__device__ __align__(16) uint4 gBet[16 * 4 * 32];
__device__ __align__(16) uint4 gBup[16 * 8 * 32];
__device__ __align__(16) uint4 gBa [16 * 32];
__device__ __align__(16) uint4 gBn [3 * 16 * 16 * 32];
__device__ __align__(16) uint4 gBuT[16 * 8 * 32];
__device__ __align__(16) uint4 gBs [2 * 8 * 32];

__device__ __forceinline__ float lrelu(float x) { return x >= 0.f ? x : SLOPE * x; }

__device__ __forceinline__ void splitpack(float x, float y, unsigned& hi, unsigned& lo) {
    __nv_bfloat16 hx = __float2bfloat16(x);
    __nv_bfloat16 hy = __float2bfloat16(y);
    float lx = x - __bfloat162float(hx);
    float ly = y - __bfloat162float(hy);
    __nv_bfloat162 h2 = __halves2bfloat162(hx, hy);
    __nv_bfloat162 l2 = __halves2bfloat162(__float2bfloat16(lx), __float2bfloat16(ly));
    hi = *reinterpret_cast<unsigned*>(&h2);
    lo = *reinterpret_cast<unsigned*>(&l2);
}

__device__ __forceinline__ uint4 pack4(float w0, float w1, float w2, float w3) {
    unsigned h0, l0, h1, l1;
    splitpack(w0, w1, h0, l0);
    splitpack(w2, w3, h1, l1);
    return make_uint4(h0, h1, l0, l1);
}

__device__ __forceinline__ void mma16816(float* c, unsigned a0, unsigned a1, unsigned a2,
                                         unsigned a3, unsigned b0, unsigned b1) {
    asm volatile(
        "mma.sync.aligned.m16n8k16.row.col.f32.bf16.bf16.f32 "
        "{%0,%1,%2,%3}, {%4,%5,%6,%7}, {%8,%9}, {%0,%1,%2,%3};"
        : "+f"(c[0]), "+f"(c[1]), "+f"(c[2]), "+f"(c[3])
        : "r"(a0), "r"(a1), "r"(a2), "r"(a3), "r"(b0), "r"(b1));
}

__device__ __forceinline__ void ldsm4(unsigned& r0, unsigned& r1, unsigned& r2, unsigned& r3,
                                      unsigned addr) {
    asm volatile("ldmatrix.sync.aligned.m8n8.x4.shared.b16 {%0,%1,%2,%3}, [%4];"
                 : "=r"(r0), "=r"(r1), "=r"(r2), "=r"(r3) : "r"(addr));
}

// ---------------- fused init ----------------
__global__ void k_init(const int* __restrict__ eidx,
                       const float* __restrict__ Wea, const float* __restrict__ Wet,
                       const float* __restrict__ Wupd, const float* __restrict__ Wattn,
                       const float* __restrict__ Wn) {
    int i = blockIdx.x * blockDim.x + threadIdx.x;
    if (i < N_EDGES) {
        g_src[i] = eidx[i];
        g_tar[i] = eidx[N_EDGES + i];
    }
    if (i < N_NODES * 8) g_denom[i] = 0.f;
    if (i < N_NODES) g_deg[i] = 0;
    if (i < 3 * PERM3_CAP) g_perm3[i] = -1;
    if (i < 3) g_tcursor3[i] = 0;

    if (i < 2048) {
        int fc = i & 3, fr = (i >> 2) & 7, kk = (i >> 5) & 3, g = i >> 7;
        int n = (g >> 2) * 32 + (g & 3) * 8 + fr;
        int k0 = 2 * (kk * 8 + fc);
        gBea[i] = pack4(Wea[k0 * 128 + n],       Wea[(k0 + 1) * 128 + n],
                        Wea[(k0 + 8) * 128 + n], Wea[(k0 + 9) * 128 + n]);
        gBet[i] = pack4(Wet[k0 * 128 + n],       Wet[(k0 + 1) * 128 + n],
                        Wet[(k0 + 8) * 128 + n], Wet[(k0 + 9) * 128 + n]);
    }
    if (i < 4096) {
        int fc = i & 3, fr = (i >> 2) & 7, kk = (i >> 5) & 7, g = i >> 8;
        int n = (g >> 2) * 32 + (g & 3) * 8 + fr;
        int k0 = 2 * (kk * 8 + fc);
        gBup[i] = pack4(Wupd[(128 + k0) * 128 + n], Wupd[(129 + k0) * 128 + n],
                        Wupd[(136 + k0) * 128 + n], Wupd[(137 + k0) * 128 + n]);
        gBuT[i] = pack4(Wupd[k0 * 128 + n],       Wupd[(k0 + 1) * 128 + n],
                        Wupd[(k0 + 8) * 128 + n], Wupd[(k0 + 9) * 128 + n]);
    }
    if (i < 512) {
        int fc = i & 3, fr = (i >> 2) & 7, kk = i >> 5;
        int k0 = 2 * (kk * 8 + fc);
        int h = fr;
        gBa[i] = pack4(Wattn[(128 + k0) * 8 + h], Wattn[(129 + k0) * 8 + h],
                       Wattn[(136 + k0) * 8 + h], Wattn[(137 + k0) * 8 + h]);
        int j = i >> 8, kk2 = (i >> 5) & 7;
        int n = j * 8 + fr;
        int q0 = 2 * (kk2 * 8 + fc);
        int ro = (n < 8) ? 0 : 384;
        int hh = (n < 8) ? n : n - 8;
        gBs[i] = pack4(Wattn[(ro + q0) * 8 + hh],     Wattn[(ro + q0 + 1) * 8 + hh],
                       Wattn[(ro + q0 + 8) * 8 + hh], Wattn[(ro + q0 + 9) * 8 + hh]);
    }
    if (i < 24576) {
        int tp = i >> 13, r = i & 8191;
        int fc = r & 3, fr = (r >> 2) & 7, kk = (r >> 5) & 15, g = r >> 9;
        int n = (g >> 2) * 32 + (g & 3) * 8 + fr;
        int k0 = 2 * (kk * 8 + fc);
        const float* W = Wn + (size_t)tp * 32768;
        gBn[i] = pack4(W[k0 * 128 + n],       W[(k0 + 1) * 128 + n],
                       W[(k0 + 8) * 128 + n], W[(k0 + 9) * 128 + n]);
    }
}

__global__ void k_hist(const int* __restrict__ ntl) {
    int i = blockIdx.x * blockDim.x + threadIdx.x;
    if (i < N_EDGES) atomicAdd(&g_deg[g_src[i]], 1);
    if (i < N_NODES) {
        int tp = ntl[i];
        int p = atomicAdd(&g_tcursor3[tp], 1);
        g_perm3[tp * PERM3_CAP + p] = i;
    }
}

// ---------------- parallel scan ----------------
__global__ void k_scanA() {
    __shared__ int sh[8];
    int b = blockIdx.x, t = threadIdx.x, i = b * 256 + t;
    int v = (i < N_NODES) ? g_deg[i] : 0;
#pragma unroll
    for (int d = 16; d; d >>= 1) v += __shfl_down_sync(~0u, v, d);
    if ((t & 31) == 0) sh[t >> 5] = v;
    __syncthreads();
    if (t < 8) {
        int s = sh[t];
#pragma unroll
        for (int d = 4; d; d >>= 1) s += __shfl_down_sync(0xff, s, d);
        if (t == 0) g_bpart[b] = s;
    }
}

__global__ void k_scanB() {
    int t = threadIdx.x, lane = t & 31, wp = t >> 5;
    int v = (t < NSCANB) ? g_bpart[t] : 0;
    int inc = v;
#pragma unroll
    for (int d = 1; d < 32; d <<= 1) {
        int n = __shfl_up_sync(~0u, inc, d);
        if (lane >= d) inc += n;
    }
    __shared__ int wsum[8];
    if (lane == 31) wsum[wp] = inc;
    __syncthreads();
    if (t == 0) {
        int r = 0;
        for (int q = 0; q < 8; q++) { int x = wsum[q]; wsum[q] = r; r += x; }
    }
    __syncthreads();
    if (t < NSCANB) g_bpre[t] = inc - v + wsum[wp];
    if (t == 0) g_off[N_NODES] = N_EDGES;
}

__global__ void k_scanC() {
    int b = blockIdx.x, t = threadIdx.x, lane = t & 31, wp = t >> 5;
    int i = b * 256 + t;
    int v = (i < N_NODES) ? g_deg[i] : 0;
    int inc = v;
#pragma unroll
    for (int d = 1; d < 32; d <<= 1) {
        int n = __shfl_up_sync(~0u, inc, d);
        if (lane >= d) inc += n;
    }
    __shared__ int wsum[8];
    if (lane == 31) wsum[wp] = inc;
    __syncthreads();
    if (t == 0) {
        int r = 0;
        for (int q = 0; q < 8; q++) { int x = wsum[q]; wsum[q] = r; r += x; }
    }
    __syncthreads();
    int off = g_bpre[b] + inc - v + wsum[wp];
    if (i < N_NODES) { g_off[i] = off; g_cursor[i] = off; }
}

// ---------------- gemm fragment helper (ldmatrix A, contiguous B) ----------------
template <int KSTEPS, int STRIDE>
__device__ __forceinline__ void gemm_frag2(const unsigned* xh, const unsigned* xl,
                                           const uint4* __restrict__ B,
                                           int rb, int nh, int lane, float acc[2][4][4]) {
    int lrow = lane & 15, lhalf = lane >> 4;
    unsigned bh = (unsigned)__cvta_generic_to_shared(xh) + ((rb + lrow) * STRIDE + lhalf * 4) * 4;
    unsigned bl = (unsigned)__cvta_generic_to_shared(xl) + ((rb + lrow) * STRIDE + lhalf * 4) * 4;
    unsigned ch = bh + 32 * STRIDE * 4;
    unsigned cl = bl + 32 * STRIDE * 4;
    const uint4* Bw = B + (nh * 4) * KSTEPS * 32 + lane;
#pragma unroll
    for (int kk = 0; kk < KSTEPS; kk++) {
        unsigned ah0, ah1, ah2, ah3, al0, al1, al2, al3;
        unsigned ch0, ch1, ch2, ch3, cl0, cl1, cl2, cl3;
        ldsm4(ah0, ah1, ah2, ah3, bh + kk * 32);
        ldsm4(al0, al1, al2, al3, bl + kk * 32);
        ldsm4(ch0, ch1, ch2, ch3, ch + kk * 32);
        ldsm4(cl0, cl1, cl2, cl3, cl + kk * 32);
#pragma unroll
        for (int j = 0; j < 4; j++) {
            uint4 b = Bw[(j * KSTEPS + kk) * 32];
            mma16816(acc[0][j], ah0, ah1, ah2, ah3, b.x, b.y);
            mma16816(acc[0][j], ah0, ah1, ah2, ah3, b.z, b.w);
            mma16816(acc[0][j], al0, al1, al2, al3, b.x, b.y);
            mma16816(acc[1][j], ch0, ch1, ch2, ch3, b.x, b.y);
            mma16816(acc[1][j], ch0, ch1, ch2, ch3, b.z, b.w);
            mma16816(acc[1][j], cl0, cl1, cl2, cl3, b.x, b.y);
        }
    }
}

// ---------------- tensor-core node kernel ----------------
#define N_XHI 0
#define N_XLO 8448
#define N_EHI 0
#define N_ELO 4352
#define NODE_SMEM_U32 16896
#define NODE_SMEM_BYTES (NODE_SMEM_U32 * 4)

__global__ void __launch_bounds__(256)
k_node(const float* __restrict__ x) {
    extern __shared__ unsigned su[];
    __shared__ int sNid[64];
    unsigned* Xhi = su + N_XHI;
    unsigned* Xlo = su + N_XLO;
    unsigned* Ehi = su + N_EHI;
    unsigned* Elo = su + N_ELO;

    int t = threadIdx.x, lane = t & 31, w = t >> 5;
    int b = blockIdx.x;
    int tp = b / NBLK64;
    int base = tp * PERM3_CAP + (b - tp * NBLK64) * 64;

    if (g_perm3[base] < 0) return;
    if (t < 64) sNid[t] = g_perm3[base + t];
    __syncthreads();

    {
        int row = t >> 2, seg = t & 3;
        int nid = sNid[row];
        const float4* src = (const float4*)(x + (size_t)(nid < 0 ? 0 : nid) * 256 + seg * 64);
        unsigned* xh = Xhi + row * 132 + seg * 32;
        unsigned* xl = Xlo + row * 132 + seg * 32;
#pragma unroll
        for (int p = 0; p < 16; p++) {
            float4 v = (nid >= 0) ? src[p] : make_float4(0.f, 0.f, 0.f, 0.f);
            unsigned h0, l0, h1, l1;
            splitpack(v.x, v.y, h0, l0);
            splitpack(v.z, v.w, h1, l1);
            xh[p * 2] = h0; xh[p * 2 + 1] = h1;
            xl[p * 2] = l0; xl[p * 2 + 1] = l1;
        }
    }
    __syncthreads();

    int nh = w & 3, rt = w >> 2;
    int rb = rt * 16;
    int fr = lane >> 2, fc = lane & 3;

    float acc[2][4][4];

#pragma unroll
    for (int ti = 0; ti < 2; ti++)
#pragma unroll
        for (int j = 0; j < 4; j++)
#pragma unroll
            for (int c = 0; c < 4; c++) acc[ti][j][c] = 0.f;
    gemm_frag2<16, 132>(Xhi, Xlo, gBn + tp * 8192, rb, nh, lane, acc);
    __syncthreads();
#pragma unroll
    for (int ti = 0; ti < 2; ti++)
#pragma unroll
        for (int j = 0; j < 4; j++) {
            int colu = nh * 16 + j * 4 + fc;
            int r = rb + fr + ti * 32;
            unsigned h, l;
            splitpack(acc[ti][j][0], acc[ti][j][1], h, l);
            Ehi[r * 68 + colu] = h;
            Elo[r * 68 + colu] = l;
            splitpack(acc[ti][j][2], acc[ti][j][3], h, l);
            Ehi[(r + 8) * 68 + colu] = h;
            Elo[(r + 8) * 68 + colu] = l;
        }
    __syncthreads();

#pragma unroll
    for (int ti = 0; ti < 2; ti++)
#pragma unroll
        for (int j = 0; j < 4; j++)
#pragma unroll
            for (int c = 0; c < 4; c++) acc[ti][j][c] = 0.f;
    gemm_frag2<8, 68>(Ehi, Elo, gBuT, rb, nh, lane, acc);
#pragma unroll
    for (int ti = 0; ti < 2; ti++)
#pragma unroll
        for (int j = 0; j < 4; j++) {
            int n0 = nh * 32 + j * 8 + fc * 2;
            int r = rb + fr + ti * 32;
            int n1 = sNid[r], n2 = sNid[r + 8];
            if (n1 >= 0)
                *(float2*)(g_P + (size_t)n1 * 128 + n0) = make_float2(acc[ti][j][0], acc[ti][j][1]);
            if (n2 >= 0)
                *(float2*)(g_P + (size_t)n2 * 128 + n0) = make_float2(acc[ti][j][2], acc[ti][j][3]);
        }

    if (w < 4) {
        int srb = w * 16;
        float sa[2][4];
#pragma unroll
        for (int j = 0; j < 2; j++)
#pragma unroll
            for (int c = 0; c < 4; c++) sa[j][c] = 0.f;
#pragma unroll
        for (int kk = 0; kk < 8; kk++) {
            int o0 = (srb + fr) * 68 + kk * 8 + fc;
            int o1 = o0 + 8 * 68;
            unsigned ah0 = Ehi[o0], ah1 = Ehi[o1], ah2 = Ehi[o0 + 4], ah3 = Ehi[o1 + 4];
            unsigned al0 = Elo[o0], al1 = Elo[o1], al2 = Elo[o0 + 4], al3 = Elo[o1 + 4];
#pragma unroll
            for (int j = 0; j < 2; j++) {
                uint4 bq = gBs[(j * 8 + kk) * 32 + lane];
                mma16816(sa[j], ah0, ah1, ah2, ah3, bq.x, bq.y);
                mma16816(sa[j], ah0, ah1, ah2, ah3, bq.z, bq.w);
                mma16816(sa[j], al0, al1, al2, al3, bq.x, bq.y);
            }
        }
#pragma unroll
        for (int j = 0; j < 2; j++)
#pragma unroll
            for (int q = 0; q < 4; q++) {
                int row = srb + fr + (q >> 1) * 8;
                int nid = sNid[row];
                int h = fc * 2 + (q & 1);
                if (nid >= 0) {
                    if (j == 0) g_star[nid * 8 + h] = sa[j][q];
                    else        g_ssrc[nid * 8 + h] = sa[j][q];
                }
            }
    }
}

// ---------------- tensor-core edge kernel (CSR-position output) ----------------
#define XHI 0
#define XLO 2304
#define AHI 4608
#define ALO 8960
#define THI 13312
#define TLO 0
#define EDGE_SMEM_U32 17664
#define EDGE_SMEM_BYTES (EDGE_SMEM_U32 * 4)

__global__ void __launch_bounds__(256)
k_edge(const float* __restrict__ eattr, const float* __restrict__ etype) {
    extern __shared__ unsigned su[];
    __shared__ int sSrc[ETILE], sTar[ETILE], sPos[ETILE];

    int t = threadIdx.x, lane = t & 31, w = t >> 5;
    int nh = w & 3, rt = w >> 2;
    int rb = rt * 16;
    int fr = lane >> 2, fc = lane & 3;
    int e0 = blockIdx.x * ETILE;

    {
        int row = t >> 2, cg = (t & 3) * 16;
        const float4* src = (const float4*)(eattr + (size_t)(e0 + row) * 64 + cg);
        unsigned* xh = su + XHI + row * 36 + cg / 2;
        unsigned* xl = su + XLO + row * 36 + cg / 2;
#pragma unroll
        for (int p = 0; p < 4; p++) {
            float4 v = src[p];
            unsigned h0, l0, h1, l1;
            splitpack(v.x, v.y, h0, l0);
            splitpack(v.z, v.w, h1, l1);
            xh[p * 2] = h0; xh[p * 2 + 1] = h1;
            xl[p * 2] = l0; xl[p * 2 + 1] = l1;
        }
    }
    if (t < ETILE) {
        int s = g_src[e0 + t];
        sSrc[t] = s;
        sPos[t] = atomicAdd(&g_cursor[s], 1);
    } else if (t < 2 * ETILE) {
        sTar[t - ETILE] = g_tar[e0 + t - ETILE];
    }
    __syncthreads();

    float acc[2][4][4];

    // ---- phase A ----
#pragma unroll
    for (int ti = 0; ti < 2; ti++)
#pragma unroll
        for (int j = 0; j < 4; j++)
#pragma unroll
            for (int c = 0; c < 4; c++) acc[ti][j][c] = 0.f;
    gemm_frag2<4, 36>(su + XHI, su + XLO, gBea, rb, nh, lane, acc);
#pragma unroll
    for (int ti = 0; ti < 2; ti++)
#pragma unroll
        for (int j = 0; j < 4; j++) {
            int colu = nh * 16 + j * 4 + fc;
            int r = rb + fr + ti * 32;
            unsigned h, l;
            splitpack(lrelu(acc[ti][j][0]), lrelu(acc[ti][j][1]), h, l);
            su[AHI + r * 68 + colu] = h;
            su[ALO + r * 68 + colu] = l;
            splitpack(lrelu(acc[ti][j][2]), lrelu(acc[ti][j][3]), h, l);
            su[AHI + (r + 8) * 68 + colu] = h;
            su[ALO + (r + 8) * 68 + colu] = l;
        }
    __syncthreads();

    {
        int row = t >> 2, cg = (t & 3) * 16;
        const float4* src = (const float4*)(etype + (size_t)(e0 + row) * 64 + cg);
        unsigned* xh = su + XHI + row * 36 + cg / 2;
        unsigned* xl = su + XLO + row * 36 + cg / 2;
#pragma unroll
        for (int p = 0; p < 4; p++) {
            float4 v = src[p];
            unsigned h0, l0, h1, l1;
            splitpack(v.x, v.y, h0, l0);
            splitpack(v.z, v.w, h1, l1);
            xh[p * 2] = h0; xh[p * 2 + 1] = h1;
            xl[p * 2] = l0; xl[p * 2 + 1] = l1;
        }
    }
    __syncthreads();

    // ---- phase T (TLO aliases X: sync after gemm reads) ----
#pragma unroll
    for (int ti = 0; ti < 2; ti++)
#pragma unroll
        for (int j = 0; j < 4; j++)
#pragma unroll
            for (int c = 0; c < 4; c++) acc[ti][j][c] = 0.f;
    gemm_frag2<4, 36>(su + XHI, su + XLO, gBet, rb, nh, lane, acc);
    __syncthreads();
#pragma unroll
    for (int ti = 0; ti < 2; ti++)
#pragma unroll
        for (int j = 0; j < 4; j++) {
            int colu = nh * 16 + j * 4 + fc;
            int r = rb + fr + ti * 32;
            unsigned h, l;
            splitpack(lrelu(acc[ti][j][0]), lrelu(acc[ti][j][1]), h, l);
            su[THI + r * 68 + colu] = h;
            su[TLO + r * 68 + colu] = l;
            splitpack(lrelu(acc[ti][j][2]), lrelu(acc[ti][j][3]), h, l);
            su[THI + (r + 8) * 68 + colu] = h;
            su[TLO + (r + 8) * 68 + colu] = l;
        }
    __syncthreads();

    // ---- scores (warps 0-3), ex at CSR position ----
    if (w < 4) {
        int srb = w * 16;
        float sacc[4] = {0.f, 0.f, 0.f, 0.f};
#pragma unroll
        for (int kk = 0; kk < 16; kk++) {
            int base_h = (kk < 8) ? AHI : THI;
            int base_l = (kk < 8) ? ALO : TLO;
            int kx = kk & 7;
            int o0 = (srb + fr) * 68 + kx * 8 + fc;
            int o1 = (srb + fr + 8) * 68 + kx * 8 + fc;
            unsigned ah0 = su[base_h + o0], ah1 = su[base_h + o1];
            unsigned ah2 = su[base_h + o0 + 4], ah3 = su[base_h + o1 + 4];
            unsigned al0 = su[base_l + o0], al1 = su[base_l + o1];
            unsigned al2 = su[base_l + o0 + 4], al3 = su[base_l + o1 + 4];
            uint4 bq = gBa[kk * 32 + lane];
            mma16816(sacc, ah0, ah1, ah2, ah3, bq.x, bq.y);
            mma16816(sacc, ah0, ah1, ah2, ah3, bq.z, bq.w);
            mma16816(sacc, al0, al1, al2, al3, bq.x, bq.y);
        }
        int h0 = fc * 2;
#pragma unroll
        for (int q = 0; q < 4; q++) {
            int row = srb + fr + (q >> 1) * 8;
            int h = h0 + (q & 1);
            int sr = sSrc[row], tg = sTar[row];
            float sc = sacc[q] + g_star[tg * 8 + h] + g_ssrc[sr * 8 + h];
            sc = lrelu(sc);
            float ex = expf(sc);
            g_ex[(size_t)sPos[row] * 8 + h] = ex;
            atomicAdd(&g_denom[sr * 8 + h], ex);
        }
    }

    // ---- phase P (fp16 attrpart at CSR position) ----
#pragma unroll
    for (int ti = 0; ti < 2; ti++)
#pragma unroll
        for (int j = 0; j < 4; j++)
#pragma unroll
            for (int c = 0; c < 4; c++) acc[ti][j][c] = 0.f;
    gemm_frag2<8, 68>(su + AHI, su + ALO, gBup, rb, nh, lane, acc);
#pragma unroll
    for (int ti = 0; ti < 2; ti++)
#pragma unroll
        for (int j = 0; j < 4; j++) {
            int n0 = nh * 32 + j * 8 + fc * 2;
            int r = rb + fr + ti * 32;
            *(__half2*)(g_attrpart_h + (size_t)sPos[r] * 128 + n0) =
                __floats2half2_rn(acc[ti][j][0], acc[ti][j][1]);
            *(__half2*)(g_attrpart_h + (size_t)sPos[r + 8] * 128 + n0) =
                __floats2half2_rn(acc[ti][j][2], acc[ti][j][3]);
        }
}

// ---------------- aggregation: 4 nodes/block, 2 cols/thread (half2) ----------------
__global__ void __launch_bounds__(256)
k_aggr(float* __restrict__ out) {
    int t = threadIdx.x;
    int n = blockIdx.x * 4 + (t >> 6);         // 4 nodes per block
    int c = (t & 63) * 2;                      // column pair
    int s = g_off[n], e_end = g_off[n + 1];
    float2 p = *(const float2*)(g_P + (size_t)n * 128 + c);
    float2 acc[8];
#pragma unroll
    for (int h = 0; h < 8; h++) acc[h] = make_float2(0.f, 0.f);
    if (e_end > s) {
        for (int j = s; j < e_end; j++) {
            float2 ap = __half22float2(*(const __half2*)(g_attrpart_h + (size_t)j * 128 + c));
            float mx = lrelu(p.x + ap.x);
            float my = lrelu(p.y + ap.y);
            const float4* xp = (const float4*)(g_ex + (size_t)j * 8);
            float4 ea = xp[0], eb = xp[1];
            acc[0].x += ea.x * mx; acc[0].y += ea.x * my;
            acc[1].x += ea.y * mx; acc[1].y += ea.y * my;
            acc[2].x += ea.z * mx; acc[2].y += ea.z * my;
            acc[3].x += ea.w * mx; acc[3].y += ea.w * my;
            acc[4].x += eb.x * mx; acc[4].y += eb.x * my;
            acc[5].x += eb.y * mx; acc[5].y += eb.y * my;
            acc[6].x += eb.z * mx; acc[6].y += eb.z * my;
            acc[7].x += eb.w * mx; acc[7].y += eb.w * my;
        }
        const float4* dp = (const float4*)(g_denom + n * 8);
        float4 da = dp[0], db = dp[1];
        acc[0].x /= da.x; acc[0].y /= da.x;
        acc[1].x /= da.y; acc[1].y /= da.y;
        acc[2].x /= da.z; acc[2].y /= da.z;
        acc[3].x /= da.w; acc[3].y /= da.w;
        acc[4].x /= db.x; acc[4].y /= db.x;
        acc[5].x /= db.y; acc[5].y /= db.y;
        acc[6].x /= db.z; acc[6].y /= db.z;
        acc[7].x /= db.w; acc[7].y /= db.w;
    }
#pragma unroll
    for (int h = 0; h < 8; h++)
        *(float2*)(out + (size_t)n * 1024 + h * 128 + c) = acc[h];
}

// ---------------- launch ----------------
extern "C" void kernel_launch(void* const* d_in, const int* in_sizes, int n_in,
                              void* d_out, int out_size) {
    const float* node_feats = (const float*)d_in[0];
    const int*   edge_index = (const int*)d_in[1];
    const float* edge_attr  = (const float*)d_in[2];
    const float* edge_type  = (const float*)d_in[3];
    const int*   ntl        = (const int*)d_in[4];
    const float* W_node  = (const float*)d_in[6];
    const float* W_eattr = (const float*)d_in[7];
    const float* W_etype = (const float*)d_in[8];
    const float* W_upd   = (const float*)d_in[9];
    const float* W_attn  = (const float*)d_in[10];
    float* out = (float*)d_out;

    cudaFuncSetAttribute(k_edge, cudaFuncAttributeMaxDynamicSharedMemorySize, EDGE_SMEM_BYTES);
    cudaFuncSetAttribute(k_node, cudaFuncAttributeMaxDynamicSharedMemorySize, NODE_SMEM_BYTES);

    const int TB = 256;
    const int GB_E = (N_EDGES + TB - 1) / TB;

    k_init<<<GB_E, TB>>>(edge_index, W_eattr, W_etype, W_upd, W_attn, W_node);   // 1
    k_hist<<<GB_E, TB>>>(ntl);                                                   // 2
    k_scanA<<<NSCANB, TB>>>();                                                   // 3
    k_node<<<3 * NBLK64, TB, NODE_SMEM_BYTES>>>(node_feats);                     // 4 <- profiled
    k_scanB<<<1, TB>>>();                                                        // 5
    k_scanC<<<NSCANB, TB>>>();                                                   // 6
    k_edge<<<NTILES, TB, EDGE_SMEM_BYTES>>>(edge_attr, edge_type);               // 7
    k_aggr<<<N_NODES / 4, TB>>>(out);                                            // 8
}